// round 1
// baseline (speedup 1.0000x reference)
#include <cuda_runtime.h>
#include <cstdint>

// Problem constants
#define B_   64
#define S_   512
#define D_   768
#define H_   12
#define DH_  64
#define P_   256
#define N3_  2304

#define ATTN_SZ   (B_*P_*D_)        // 12582912
#define NM_OFF    (ATTN_SZ)         // new_mask at 12582912
#define RQ_OFF    (ATTN_SZ + B_*P_) // residual_query at 12599296

// Scratch: K,V in head-major layout [b,h,s,d]
__device__ float g_k[B_*H_*S_*DH_];
__device__ float g_v[B_*H_*S_*DH_];

// ---------------- packed f32x2 helpers ----------------
__device__ __forceinline__ unsigned long long splat2(float x) {
    unsigned long long r; unsigned u = __float_as_uint(x);
    asm("mov.b64 %0, {%1, %1};" : "=l"(r) : "r"(u));
    return r;
}
__device__ __forceinline__ unsigned long long pack2(float a, float b) {
    unsigned long long r; unsigned ua = __float_as_uint(a), ub = __float_as_uint(b);
    asm("mov.b64 %0, {%1, %2};" : "=l"(r) : "r"(ua), "r"(ub));
    return r;
}
__device__ __forceinline__ void fma2(unsigned long long &d, unsigned long long a, unsigned long long b) {
    asm("fma.rn.f32x2 %0, %1, %2, %0;" : "+l"(d) : "l"(a), "l"(b));
}
__device__ __forceinline__ void fma2o(unsigned long long &d, unsigned long long a, unsigned long long b, unsigned long long c) {
    asm("fma.rn.f32x2 %0, %1, %2, %3;" : "=l"(d) : "l"(a), "l"(b), "l"(c));
}
__device__ __forceinline__ void add2(unsigned long long &d, unsigned long long a) {
    asm("add.rn.f32x2 %0, %0, %1;" : "+l"(d) : "l"(a));
}
__device__ __forceinline__ float2 unpack2(unsigned long long v) {
    unsigned lo, hi;
    asm("mov.b64 {%0, %1}, %2;" : "=r"(lo), "=r"(hi) : "l"(v));
    return make_float2(__uint_as_float(lo), __uint_as_float(hi));
}

// ---------------- Kernel 1: QKV GEMM + bias + mask + fused q-pool ----------------
// C[m, n] = hidden[m, :] @ W[:, n] + bias[n], masked by mask[m].
// n < 768  -> pooled q written to residual_query region of d_out
// 768..1535 -> g_k head-major;  1536..2303 -> g_v head-major.
#define BM 128
#define BN 128
#define BK 16

__global__ __launch_bounds__(256)
void qkv_gemm(const float* __restrict__ A, const float* __restrict__ W,
              const float* __restrict__ Wb, const int* __restrict__ maskp,
              float* __restrict__ resid)
{
    __shared__ float As[BK][BM + 4];
    __shared__ float Bs[BK][BN];

    const int tid = threadIdx.x;
    const int n0 = blockIdx.x * BN;   // 0..17 tiles
    const int m0 = blockIdx.y * BM;   // 0..255 tiles
    const int tx = tid & 15, ty = tid >> 4;
    const int ry = ty * 8, cx = tx * 8;

    unsigned long long c2[8][4];
    #pragma unroll
    for (int i = 0; i < 8; i++)
        #pragma unroll
        for (int j = 0; j < 4; j++) c2[i][j] = 0ull;

    for (int k0 = 0; k0 < D_; k0 += BK) {
        #pragma unroll
        for (int t = 0; t < 2; t++) {
            int idx = tid * 2 + t;
            int row = idx >> 2;
            int kc4 = (idx & 3) * 4;
            float4 v = *(const float4*)&A[(m0 + row) * D_ + k0 + kc4];
            As[kc4 + 0][row] = v.x; As[kc4 + 1][row] = v.y;
            As[kc4 + 2][row] = v.z; As[kc4 + 3][row] = v.w;
        }
        #pragma unroll
        for (int t = 0; t < 2; t++) {
            int idx = tid * 2 + t;
            int row = idx >> 5;
            int c4  = (idx & 31) * 4;
            *(float4*)&Bs[row][c4] = *(const float4*)&W[(k0 + row) * N3_ + n0 + c4];
        }
        __syncthreads();

        #pragma unroll
        for (int kk = 0; kk < BK; kk++) {
            float a[8];
            *(float4*)&a[0] = *(const float4*)&As[kk][ry];
            *(float4*)&a[4] = *(const float4*)&As[kk][ry + 4];
            ulonglong2 bA = *(const ulonglong2*)&Bs[kk][cx];
            ulonglong2 bB = *(const ulonglong2*)&Bs[kk][cx + 4];
            unsigned long long b2[4] = { bA.x, bA.y, bB.x, bB.y };
            #pragma unroll
            for (int i = 0; i < 8; i++) {
                unsigned long long a2 = splat2(a[i]);
                #pragma unroll
                for (int j = 0; j < 4; j++) fma2(c2[i][j], a2, b2[j]);
            }
        }
        __syncthreads();
    }

    // Epilogue
    float c[8][8];
    #pragma unroll
    for (int i = 0; i < 8; i++)
        #pragma unroll
        for (int j2 = 0; j2 < 4; j2++) {
            float2 t = unpack2(c2[i][j2]);
            c[i][2*j2] = t.x; c[i][2*j2+1] = t.y;
        }
    float bv[8];
    #pragma unroll
    for (int j = 0; j < 8; j++) bv[j] = Wb[n0 + cx + j];
    float mk[8];
    #pragma unroll
    for (int i = 0; i < 8; i++) mk[i] = (float)maskp[m0 + ry + i];
    #pragma unroll
    for (int i = 0; i < 8; i++)
        #pragma unroll
        for (int j = 0; j < 8; j++) c[i][j] = (c[i][j] + bv[j]) * mk[i];

    const int region = n0 / D_;      // block-uniform: 0=q, 1=k, 2=v
    const int b = m0 >> 9;           // tile stays within one batch (512 % 128 == 0)

    if (region == 0) {
        #pragma unroll
        for (int i = 0; i < 8; i += 2) {
            int s = (m0 + ry + i) & (S_ - 1);
            int p = s >> 1;
            int msum = (int)mk[i] + (int)mk[i + 1];
            float inv = 1.0f / (float)(msum > 0 ? msum : 1);
            float pv[8];
            #pragma unroll
            for (int j = 0; j < 8; j++) pv[j] = (c[i][j] + c[i + 1][j]) * inv;
            float* dst = resid + (b * P_ + p) * D_ + (n0 + cx);
            *(float4*)dst       = make_float4(pv[0], pv[1], pv[2], pv[3]);
            *(float4*)(dst + 4) = make_float4(pv[4], pv[5], pv[6], pv[7]);
        }
    } else {
        float* g = (region == 1) ? g_k : g_v;
        int nb = n0 + cx - region * D_;
        int h = nb >> 6, d = nb & 63;
        #pragma unroll
        for (int i = 0; i < 8; i++) {
            int s = (m0 + ry + i) & (S_ - 1);
            float* dst = g + ((b * H_ + h) * S_ + s) * DH_ + d;
            *(float4*)dst       = make_float4(c[i][0], c[i][1], c[i][2], c[i][3]);
            *(float4*)(dst + 4) = make_float4(c[i][4], c[i][5], c[i][6], c[i][7]);
        }
    }
}

// ---------------- Kernel 2: new_mask ----------------
__global__ void nm_kernel(const int* __restrict__ mask, float* __restrict__ out_nm)
{
    int i = blockIdx.x * blockDim.x + threadIdx.x;   // 0..16383
    int b = i >> 8, p = i & 255;
    int m = mask[b * S_ + 2 * p] | mask[b * S_ + 2 * p + 1];
    out_nm[i] = (float)m;
}

// ---------------- Kernel 3: attention ----------------
// One block per (b,h); one thread per pooled row p (256 threads).
#define SC 64

__global__ __launch_bounds__(256)
void attn_kernel(const int* __restrict__ mask, const float* __restrict__ resid,
                 float* __restrict__ out)
{
    __shared__ float Ks[SC * DH_];
    __shared__ float Vs[SC * DH_];
    __shared__ float sb[SC];

    const int bh = blockIdx.x;
    const int b = bh / H_, h = bh - b * H_;
    const int p = threadIdx.x;

    const float slope = (h < 8) ? exp2f(-(float)(h + 1)) : exp2f(-0.5f - (float)(h - 8));
    const float pf = (float)p;

    // q row (residual_query == q_pooled identically)
    const float* qrow = resid + (b * P_ + p) * D_ + h * DH_;
    unsigned long long q2[32];
    #pragma unroll
    for (int d4 = 0; d4 < 16; d4++) {
        float4 v = *(const float4*)(qrow + d4 * 4);
        q2[d4 * 2]     = pack2(v.x, v.y);
        q2[d4 * 2 + 1] = pack2(v.z, v.w);
    }
    const int nm = mask[b * S_ + 2 * p] | mask[b * S_ + 2 * p + 1];

    unsigned long long acc2[32];
    #pragma unroll
    for (int j = 0; j < 32; j++) acc2[j] = 0ull;
    float mrun = -1e30f, lsum = 0.0f;

    const float* kg = g_k + bh * (S_ * DH_);
    const float* vg = g_v + bh * (S_ * DH_);

    for (int s0 = 0; s0 < S_; s0 += SC) {
        const float4* ksrc = (const float4*)(kg + s0 * DH_);
        const float4* vsrc = (const float4*)(vg + s0 * DH_);
        #pragma unroll
        for (int t = 0; t < 4; t++) {
            ((float4*)Ks)[t * 256 + threadIdx.x] = ksrc[t * 256 + threadIdx.x];
            ((float4*)Vs)[t * 256 + threadIdx.x] = vsrc[t * 256 + threadIdx.x];
        }
        if (threadIdx.x < SC)
            sb[threadIdx.x] = mask[b * S_ + s0 + threadIdx.x] ? 0.0f : -10000.0f;
        __syncthreads();

        if (nm) {
            for (int ss = 0; ss < SC; ss++) {
                const ulonglong2* kr = (const ulonglong2*)(Ks + ss * DH_);
                unsigned long long p0 = 0ull, p1 = 0ull, p2 = 0ull, p3 = 0ull;
                #pragma unroll
                for (int j = 0; j < 8; j++) {
                    ulonglong2 ta = kr[j];
                    ulonglong2 tb = kr[8 + j];
                    fma2(p0, q2[2 * j],      ta.x);
                    fma2(p1, q2[2 * j + 1],  ta.y);
                    fma2(p2, q2[16 + 2 * j], tb.x);
                    fma2(p3, q2[17 + 2 * j], tb.y);
                }
                add2(p0, p1); add2(p2, p3); add2(p0, p2);
                float2 dt = unpack2(p0);
                float sc = (dt.x + dt.y) * 0.125f + sb[ss]
                         - slope * fabsf((float)(s0 + ss) - pf);

                const ulonglong2* vr = (const ulonglong2*)(Vs + ss * DH_);
                if (sc <= mrun) {
                    float pr = __expf(sc - mrun);
                    lsum += pr;
                    unsigned long long pr2 = splat2(pr);
                    #pragma unroll
                    for (int j = 0; j < 16; j++) {
                        ulonglong2 t = vr[j];
                        fma2(acc2[2 * j],     pr2, t.x);
                        fma2(acc2[2 * j + 1], pr2, t.y);
                    }
                } else {
                    float corr = __expf(mrun - sc);
                    mrun = sc;
                    lsum = lsum * corr + 1.0f;
                    unsigned long long c2s = splat2(corr);
                    #pragma unroll
                    for (int j = 0; j < 16; j++) {
                        ulonglong2 t = vr[j];
                        fma2o(acc2[2 * j],     acc2[2 * j],     c2s, t.x);
                        fma2o(acc2[2 * j + 1], acc2[2 * j + 1], c2s, t.y);
                    }
                }
            }
        }
        __syncthreads();
    }

    float* dst = out + (b * P_ + p) * D_ + h * DH_;
    if (nm) {
        float invl = 1.0f / lsum;
        #pragma unroll
        for (int g = 0; g < 16; g++) {
            float2 u = unpack2(acc2[2 * g]);
            float2 w = unpack2(acc2[2 * g + 1]);
            *(float4*)(dst + 4 * g) = make_float4(u.x * invl, u.y * invl,
                                                  w.x * invl, w.y * invl);
        }
    } else {
        float4 z = make_float4(0.f, 0.f, 0.f, 0.f);
        #pragma unroll
        for (int g = 0; g < 16; g++) *(float4*)(dst + 4 * g) = z;
    }
}

// ---------------- launch ----------------
extern "C" void kernel_launch(void* const* d_in, const int* in_sizes, int n_in,
                              void* d_out, int out_size)
{
    const float* hidden = (const float*)d_in[0];
    const int*   mask   = (const int*)d_in[1];
    const float* W      = (const float*)d_in[2];
    const float* Wb     = (const float*)d_in[3];
    float* out = (float*)d_out;

    float* resid = out + RQ_OFF;
    float* nmout = out + NM_OFF;

    qkv_gemm<<<dim3(N3_ / BN, (B_ * S_) / BM), 256>>>(hidden, W, Wb, mask, resid);
    nm_kernel<<<(B_ * P_) / 256, 256>>>(mask, nmout);
    attn_kernel<<<B_ * H_, 256>>>(mask, resid, out);
}

// round 4
// speedup vs baseline: 1.7920x; 1.7920x over previous
#include <cuda_runtime.h>
#include <cuda_bf16.h>
#include <cstdint>

// Problem constants
#define B_   64
#define S_   512
#define D_   768
#define H_   12
#define DH_  64
#define P_   256
#define N3_  2304
#define KE_  1536   // stored extended K (hi|lo concat)

#define ATTN_SZ   (B_*P_*D_)
#define NM_OFF    (ATTN_SZ)
#define RQ_OFF    (ATTN_SZ + B_*P_)

// Scratch
__device__ float          g_k[B_*H_*S_*DH_];
__device__ float          g_v[B_*H_*S_*DH_];
__device__ __nv_bfloat16  g_aext[B_*S_*KE_];     // [32768][1536] hi|lo
__device__ __nv_bfloat16  g_bext[N3_*KE_];       // [2304][1536]  W^T hi|lo

// ---------------- PTX helpers ----------------
__device__ __forceinline__ uint32_t smem_u32(const void* p) {
    uint32_t a;
    asm("{ .reg .u64 t; cvta.to.shared.u64 t, %1; cvt.u32.u64 %0, t; }" : "=r"(a) : "l"(p));
    return a;
}
#define SWZ128(o) ((o) ^ (((o) >> 3) & 0x70))

__device__ __forceinline__ void cp_async16(uint32_t dst, const void* src) {
    asm volatile("cp.async.cg.shared.global [%0], [%1], 16;" :: "r"(dst), "l"(src) : "memory");
}
__device__ __forceinline__ void cp_commit() {
    asm volatile("cp.async.commit_group;" ::: "memory");
}
template<int N>
__device__ __forceinline__ void cp_wait() {
    asm volatile("cp.async.wait_group %0;" :: "n"(N) : "memory");
}
__device__ __forceinline__ void ldsm4(uint32_t* r, uint32_t addr) {
    asm volatile("ldmatrix.sync.aligned.m8n8.x4.shared.b16 {%0,%1,%2,%3}, [%4];"
        : "=r"(r[0]), "=r"(r[1]), "=r"(r[2]), "=r"(r[3]) : "r"(addr));
}
__device__ __forceinline__ void mma16816(float* c, const uint32_t* a, uint32_t b0, uint32_t b1) {
    asm volatile("mma.sync.aligned.m16n8k16.row.col.f32.bf16.bf16.f32 "
        "{%0,%1,%2,%3}, {%4,%5,%6,%7}, {%8,%9}, {%0,%1,%2,%3};"
        : "+f"(c[0]), "+f"(c[1]), "+f"(c[2]), "+f"(c[3])
        : "r"(a[0]), "r"(a[1]), "r"(a[2]), "r"(a[3]), "r"(b0), "r"(b1));
}

// ---------------- packed f32x2 helpers (attention) ----------------
__device__ __forceinline__ unsigned long long splat2(float x) {
    unsigned long long r; unsigned u = __float_as_uint(x);
    asm("mov.b64 %0, {%1, %1};" : "=l"(r) : "r"(u));
    return r;
}
__device__ __forceinline__ unsigned long long pack2(float a, float b) {
    unsigned long long r; unsigned ua = __float_as_uint(a), ub = __float_as_uint(b);
    asm("mov.b64 %0, {%1, %2};" : "=l"(r) : "r"(ua), "r"(ub));
    return r;
}
__device__ __forceinline__ void fma2(unsigned long long &d, unsigned long long a, unsigned long long b) {
    asm("fma.rn.f32x2 %0, %1, %2, %0;" : "+l"(d) : "l"(a), "l"(b));
}
__device__ __forceinline__ void fma2o(unsigned long long &d, unsigned long long a, unsigned long long b, unsigned long long c) {
    asm("fma.rn.f32x2 %0, %1, %2, %3;" : "=l"(d) : "l"(a), "l"(b), "l"(c));
}
__device__ __forceinline__ void add2(unsigned long long &d, unsigned long long a) {
    asm("add.rn.f32x2 %0, %0, %1;" : "+l"(d) : "l"(a));
}
__device__ __forceinline__ float2 unpack2(unsigned long long v) {
    unsigned lo, hi;
    asm("mov.b64 {%0, %1}, %2;" : "=r"(lo), "=r"(hi) : "l"(v));
    return make_float2(__uint_as_float(lo), __uint_as_float(hi));
}

// ---------------- Prepass A: f32 -> bf16 hi|lo concat along K ----------------
__global__ __launch_bounds__(256)
void split_a(const float* __restrict__ A)
{
    int idx = blockIdx.x * 256 + threadIdx.x;
    int m = idx / 192;
    int k4 = (idx - m * 192) * 4;
    float4 a = *(const float4*)&A[m * D_ + k4];
    __nv_bfloat16 h0 = __float2bfloat16_rn(a.x), h1 = __float2bfloat16_rn(a.y);
    __nv_bfloat16 h2 = __float2bfloat16_rn(a.z), h3 = __float2bfloat16_rn(a.w);
    __nv_bfloat16 l0 = __float2bfloat16_rn(a.x - __bfloat162float(h0));
    __nv_bfloat16 l1 = __float2bfloat16_rn(a.y - __bfloat162float(h1));
    __nv_bfloat16 l2 = __float2bfloat16_rn(a.z - __bfloat162float(h2));
    __nv_bfloat16 l3 = __float2bfloat16_rn(a.w - __bfloat162float(h3));
    uint2 ph, pl;
    ph.x = (uint32_t)__bfloat16_as_ushort(h0) | ((uint32_t)__bfloat16_as_ushort(h1) << 16);
    ph.y = (uint32_t)__bfloat16_as_ushort(h2) | ((uint32_t)__bfloat16_as_ushort(h3) << 16);
    pl.x = (uint32_t)__bfloat16_as_ushort(l0) | ((uint32_t)__bfloat16_as_ushort(l1) << 16);
    pl.y = (uint32_t)__bfloat16_as_ushort(l2) | ((uint32_t)__bfloat16_as_ushort(l3) << 16);
    *(uint2*)&g_aext[(size_t)m * KE_ + k4]       = ph;
    *(uint2*)&g_aext[(size_t)m * KE_ + D_ + k4]  = pl;
}

// ---------------- Prepass W: transpose + split ----------------
__global__ __launch_bounds__(256)
void split_wT(const float* __restrict__ W)
{
    __shared__ float t[32][33];
    int n0 = blockIdx.x * 32, k0 = blockIdx.y * 32;
    int tx = threadIdx.x, ty = threadIdx.y;
    #pragma unroll
    for (int j = 0; j < 4; j++)
        t[ty + j * 8][tx] = W[(size_t)(k0 + ty + j * 8) * N3_ + n0 + tx];
    __syncthreads();
    #pragma unroll
    for (int j = 0; j < 4; j++) {
        int n = n0 + ty + j * 8;
        int k = k0 + tx;
        float v = t[tx][ty + j * 8];
        __nv_bfloat16 h = __float2bfloat16_rn(v);
        __nv_bfloat16 l = __float2bfloat16_rn(v - __bfloat162float(h));
        g_bext[(size_t)n * KE_ + k]      = h;
        g_bext[(size_t)n * KE_ + D_ + k] = l;
    }
}

// ---------------- mma.sync GEMM with 3-term split pairing ----------------
// Logical K = 36 chunks of 64:
//   kt  0..11: Ah(kt)    x Bh(kt)
//   kt 12..23: Al(kt-12) x Bh(kt-12)   [a chunk 12..23 is Al]
//   kt 24..35: Ah(kt-24) x Bl(kt-12)   [b chunk 12..23 is Bl]
// => C = Ah·Bh + Al·Bh + Ah·Bl  (residual Al·Bl ~ 2^-18)
#define NKC   36
#define ABYTES 16384            // 128 rows x 128B
#define BUFB  32768             // A + B per buffer
#define PITCH 132

__global__ __launch_bounds__(256)
void gemm_mma(const float* __restrict__ Wb, const int* __restrict__ maskp,
              float* __restrict__ resid)
{
    extern __shared__ char dsm[];
    __shared__ __align__(16) float s_bias[128];

    char* smem_al = (char*)(((uintptr_t)dsm + 1023) & ~(uintptr_t)1023);
    const uint32_t sbase = smem_u32(smem_al);

    const int tid = threadIdx.x;
    const int wid = tid >> 5, lane = tid & 31;
    const int wm = wid & 3, wn = wid >> 2;
    const int n0 = blockIdx.x * 128;
    const int m0 = blockIdx.y * 128;

    if (tid < 128) s_bias[tid] = Wb[n0 + tid];

    const char* agbase = (const char*)g_aext + (size_t)m0 * (KE_ * 2);
    const char* bgbase = (const char*)g_bext + (size_t)n0 * (KE_ * 2);

    int ld_row[4], ld_seg[4];
    #pragma unroll
    for (int p = 0; p < 4; p++) {
        int idx = p * 256 + tid;
        ld_row[p] = idx >> 3;
        ld_seg[p] = (idx & 7) * 16;
    }

    auto issue = [&](int kt, int buf) {
        int a_idx = (kt >= 24) ? kt - 24 : kt;
        int b_idx = (kt >= 12) ? kt - 12 : kt;
        const char* ag = agbase + a_idx * 128;
        const char* bg = bgbase + b_idx * 128;
        uint32_t base = sbase + buf * BUFB;
        #pragma unroll
        for (int p = 0; p < 4; p++) {
            uint32_t off = SWZ128(ld_row[p] * 128 + ld_seg[p]);
            cp_async16(base + off, ag + (size_t)ld_row[p] * (KE_ * 2) + ld_seg[p]);
        }
        #pragma unroll
        for (int p = 0; p < 4; p++) {
            uint32_t off = SWZ128(ld_row[p] * 128 + ld_seg[p]);
            cp_async16(base + ABYTES + off, bg + (size_t)ld_row[p] * (KE_ * 2) + ld_seg[p]);
        }
        cp_commit();
    };

    float c[2][8][4];
    #pragma unroll
    for (int i = 0; i < 2; i++)
        #pragma unroll
        for (int j = 0; j < 8; j++)
            #pragma unroll
            for (int q = 0; q < 4; q++) c[i][j][q] = 0.0f;

    uint32_t a_off[2][4], b_off[4][4];
    #pragma unroll
    for (int mi = 0; mi < 2; mi++)
        #pragma unroll
        for (int ks = 0; ks < 4; ks++) {
            int r = wm * 32 + mi * 16 + (lane & 15);
            int cb = ks * 32 + (lane >> 4) * 16;
            a_off[mi][ks] = SWZ128(r * 128 + cb);
        }
    #pragma unroll
    for (int ni = 0; ni < 4; ni++)
        #pragma unroll
        for (int ks = 0; ks < 4; ks++) {
            int r = wn * 64 + ni * 16 + (lane & 7) + ((lane >> 4) << 3);
            int cb = ks * 32 + ((lane >> 3) & 1) * 16;
            b_off[ni][ks] = ABYTES + SWZ128(r * 128 + cb);
        }

    issue(0, 0);

    for (int kt = 0; kt < NKC; kt++) {
        if (kt + 1 < NKC) {
            issue(kt + 1, (kt + 1) & 1);
            cp_wait<1>();
        } else {
            cp_wait<0>();
        }
        __syncthreads();

        uint32_t bufb = sbase + (kt & 1) * BUFB;
        #pragma unroll
        for (int ks = 0; ks < 4; ks++) {
            uint32_t a0[4], a1[4];
            ldsm4(a0, bufb + a_off[0][ks]);
            ldsm4(a1, bufb + a_off[1][ks]);
            uint32_t bb[4][4];
            #pragma unroll
            for (int ni = 0; ni < 4; ni++)
                ldsm4(bb[ni], bufb + b_off[ni][ks]);
            #pragma unroll
            for (int ni = 0; ni < 4; ni++) {
                mma16816(c[0][2 * ni],     a0, bb[ni][0], bb[ni][1]);
                mma16816(c[0][2 * ni + 1], a0, bb[ni][2], bb[ni][3]);
                mma16816(c[1][2 * ni],     a1, bb[ni][0], bb[ni][1]);
                mma16816(c[1][2 * ni + 1], a1, bb[ni][2], bb[ni][3]);
            }
        }
        __syncthreads();
    }

    // ---- stage C to smem ----
    float* Csm = (float*)smem_al;
    #pragma unroll
    for (int mi = 0; mi < 2; mi++)
        #pragma unroll
        for (int nj = 0; nj < 8; nj++) {
            int row = wm * 32 + mi * 16 + (lane >> 2);
            int col = wn * 64 + nj * 8 + (lane & 3) * 2;
            *(float2*)&Csm[row * PITCH + col]       = make_float2(c[mi][nj][0], c[mi][nj][1]);
            *(float2*)&Csm[(row + 8) * PITCH + col] = make_float2(c[mi][nj][2], c[mi][nj][3]);
        }
    __syncthreads();

    // ---- epilogue routing ----
    const int region = n0 / D_;
    const int b = m0 >> 9;

    if (region == 0) {
        int pr = tid >> 2;
        int cg = (tid & 3) * 32;
        int r0 = 2 * pr, r1 = r0 + 1;
        float mk0 = (float)maskp[m0 + r0];
        float mk1 = (float)maskp[m0 + r1];
        float inv = 1.0f / fmaxf(mk0 + mk1, 1.0f);
        int pglob = ((m0 & (S_ - 1)) >> 1) + pr;
        float* dst = resid + ((size_t)(b * P_ + pglob)) * D_ + n0 + cg;
        #pragma unroll
        for (int i = 0; i < 8; i++) {
            float4 x = *(float4*)&Csm[r0 * PITCH + cg + i * 4];
            float4 y = *(float4*)&Csm[r1 * PITCH + cg + i * 4];
            float4 bi = *(float4*)&s_bias[cg + i * 4];
            float4 o;
            o.x = ((x.x + bi.x) * mk0 + (y.x + bi.x) * mk1) * inv;
            o.y = ((x.y + bi.y) * mk0 + (y.y + bi.y) * mk1) * inv;
            o.z = ((x.z + bi.z) * mk0 + (y.z + bi.z) * mk1) * inv;
            o.w = ((x.w + bi.w) * mk0 + (y.w + bi.w) * mk1) * inv;
            *(float4*)(dst + i * 4) = o;
        }
    } else {
        int row = tid >> 1, half = tid & 1;
        int m = m0 + row;
        int s = m & (S_ - 1);
        float mk = (float)maskp[m];
        int head = ((n0 - region * D_) >> 6) + half;
        float* g = (region == 1) ? g_k : g_v;
        float* dst = g + (((size_t)(b * H_ + head)) * S_ + s) * DH_;
        int cbase = half * 64;
        #pragma unroll
        for (int i = 0; i < 16; i++) {
            float4 x = *(float4*)&Csm[row * PITCH + cbase + i * 4];
            float4 bi = *(float4*)&s_bias[cbase + i * 4];
            *(float4*)(dst + i * 4) = make_float4((x.x + bi.x) * mk, (x.y + bi.y) * mk,
                                                  (x.z + bi.z) * mk, (x.w + bi.w) * mk);
        }
    }
}

// ---------------- new_mask ----------------
__global__ void nm_kernel(const int* __restrict__ mask, float* __restrict__ out_nm)
{
    int i = blockIdx.x * blockDim.x + threadIdx.x;
    int b = i >> 8, p = i & 255;
    int m = mask[b * S_ + 2 * p] | mask[b * S_ + 2 * p + 1];
    out_nm[i] = (float)m;
}

// ---------------- attention (unchanged, validated round 1) ----------------
#define SC 64
__global__ __launch_bounds__(256)
void attn_kernel(const int* __restrict__ mask, const float* __restrict__ resid,
                 float* __restrict__ out)
{
    __shared__ float Ks[SC * DH_];
    __shared__ float Vs[SC * DH_];
    __shared__ float sb[SC];

    const int bh = blockIdx.x;
    const int b = bh / H_, h = bh - b * H_;
    const int p = threadIdx.x;

    const float slope = (h < 8) ? exp2f(-(float)(h + 1)) : exp2f(-0.5f - (float)(h - 8));
    const float pf = (float)p;

    const float* qrow = resid + (b * P_ + p) * D_ + h * DH_;
    unsigned long long q2[32];
    #pragma unroll
    for (int d4 = 0; d4 < 16; d4++) {
        float4 v = *(const float4*)(qrow + d4 * 4);
        q2[d4 * 2]     = pack2(v.x, v.y);
        q2[d4 * 2 + 1] = pack2(v.z, v.w);
    }
    const int nm = mask[b * S_ + 2 * p] | mask[b * S_ + 2 * p + 1];

    unsigned long long acc2[32];
    #pragma unroll
    for (int j = 0; j < 32; j++) acc2[j] = 0ull;
    float mrun = -1e30f, lsum = 0.0f;

    const float* kg = g_k + (size_t)bh * (S_ * DH_);
    const float* vg = g_v + (size_t)bh * (S_ * DH_);

    for (int s0 = 0; s0 < S_; s0 += SC) {
        const float4* ksrc = (const float4*)(kg + s0 * DH_);
        const float4* vsrc = (const float4*)(vg + s0 * DH_);
        #pragma unroll
        for (int t = 0; t < 4; t++) {
            ((float4*)Ks)[t * 256 + threadIdx.x] = ksrc[t * 256 + threadIdx.x];
            ((float4*)Vs)[t * 256 + threadIdx.x] = vsrc[t * 256 + threadIdx.x];
        }
        if (threadIdx.x < SC)
            sb[threadIdx.x] = mask[b * S_ + s0 + threadIdx.x] ? 0.0f : -10000.0f;
        __syncthreads();

        if (nm) {
            for (int ss = 0; ss < SC; ss++) {
                const ulonglong2* kr = (const ulonglong2*)(Ks + ss * DH_);
                unsigned long long p0 = 0ull, p1 = 0ull, p2 = 0ull, p3 = 0ull;
                #pragma unroll
                for (int j = 0; j < 8; j++) {
                    ulonglong2 ta = kr[j];
                    ulonglong2 tb = kr[8 + j];
                    fma2(p0, q2[2 * j],      ta.x);
                    fma2(p1, q2[2 * j + 1],  ta.y);
                    fma2(p2, q2[16 + 2 * j], tb.x);
                    fma2(p3, q2[17 + 2 * j], tb.y);
                }
                add2(p0, p1); add2(p2, p3); add2(p0, p2);
                float2 dt = unpack2(p0);
                float sc = (dt.x + dt.y) * 0.125f + sb[ss]
                         - slope * fabsf((float)(s0 + ss) - pf);

                const ulonglong2* vr = (const ulonglong2*)(Vs + ss * DH_);
                if (sc <= mrun) {
                    float pr = __expf(sc - mrun);
                    lsum += pr;
                    unsigned long long pr2 = splat2(pr);
                    #pragma unroll
                    for (int j = 0; j < 16; j++) {
                        ulonglong2 t = vr[j];
                        fma2(acc2[2 * j],     pr2, t.x);
                        fma2(acc2[2 * j + 1], pr2, t.y);
                    }
                } else {
                    float corr = __expf(mrun - sc);
                    mrun = sc;
                    lsum = lsum * corr + 1.0f;
                    unsigned long long c2s = splat2(corr);
                    #pragma unroll
                    for (int j = 0; j < 16; j++) {
                        ulonglong2 t = vr[j];
                        fma2o(acc2[2 * j],     acc2[2 * j],     c2s, t.x);
                        fma2o(acc2[2 * j + 1], acc2[2 * j + 1], c2s, t.y);
                    }
                }
            }
        }
        __syncthreads();
    }

    float* dst = out + (b * P_ + p) * D_ + h * DH_;
    if (nm) {
        float invl = 1.0f / lsum;
        #pragma unroll
        for (int g = 0; g < 16; g++) {
            float2 u = unpack2(acc2[2 * g]);
            float2 w = unpack2(acc2[2 * g + 1]);
            *(float4*)(dst + 4 * g) = make_float4(u.x * invl, u.y * invl,
                                                  w.x * invl, w.y * invl);
        }
    } else {
        float4 z = make_float4(0.f, 0.f, 0.f, 0.f);
        #pragma unroll
        for (int g = 0; g < 16; g++) *(float4*)(dst + 4 * g) = z;
    }
}

// ---------------- launch ----------------
extern "C" void kernel_launch(void* const* d_in, const int* in_sizes, int n_in,
                              void* d_out, int out_size)
{
    const float* hidden = (const float*)d_in[0];
    const int*   mask   = (const int*)d_in[1];
    const float* W      = (const float*)d_in[2];
    const float* Wb     = (const float*)d_in[3];
    float* out = (float*)d_out;

    float* resid = out + RQ_OFF;
    float* nmout = out + NM_OFF;

    (void)cudaFuncSetAttribute(gemm_mma, cudaFuncAttributeMaxDynamicSharedMemorySize, 69632);

    split_a<<<(B_*S_*D_/4 + 255) / 256, 256>>>(hidden);
    split_wT<<<dim3(N3_/32, D_/32), dim3(32, 8)>>>(W);
    gemm_mma<<<dim3(N3_/128, (B_*S_)/128), 256, 69632>>>(Wb, mask, resid);
    nm_kernel<<<(B_*P_)/256, 256>>>(mask, nmout);
    attn_kernel<<<B_*H_, 256>>>(mask, resid, out);
}

// round 5
// speedup vs baseline: 3.1711x; 1.7695x over previous
#include <cuda_runtime.h>
#include <cuda_bf16.h>
#include <cstdint>

// Problem constants
#define B_   64
#define S_   512
#define D_   768
#define H_   12
#define DH_  64
#define P_   256
#define N3_  2304
#define KE_  1536   // stored extended K (hi|lo concat)

#define ATTN_SZ   (B_*P_*D_)
#define NM_OFF    (ATTN_SZ)
#define RQ_OFF    (ATTN_SZ + B_*P_)

// Scratch: K,V stored as packed bf16 (low16=hi part, high16=lo residual)
__device__ uint32_t       g_k[B_*H_*S_*DH_];
__device__ uint32_t       g_v[B_*H_*S_*DH_];
__device__ __nv_bfloat16  g_aext[B_*S_*KE_];     // [32768][1536] hi|lo
__device__ __nv_bfloat16  g_bext[N3_*KE_];       // [2304][1536]  W^T hi|lo

// ---------------- PTX helpers ----------------
__device__ __forceinline__ uint32_t smem_u32(const void* p) {
    uint32_t a;
    asm("{ .reg .u64 t; cvta.to.shared.u64 t, %1; cvt.u32.u64 %0, t; }" : "=r"(a) : "l"(p));
    return a;
}
#define SWZ128(o) ((o) ^ (((o) >> 3) & 0x70))

__device__ __forceinline__ void cp_async16(uint32_t dst, const void* src) {
    asm volatile("cp.async.cg.shared.global [%0], [%1], 16;" :: "r"(dst), "l"(src) : "memory");
}
__device__ __forceinline__ void cp_commit() {
    asm volatile("cp.async.commit_group;" ::: "memory");
}
template<int N>
__device__ __forceinline__ void cp_wait() {
    asm volatile("cp.async.wait_group %0;" :: "n"(N) : "memory");
}
__device__ __forceinline__ void ldsm4(uint32_t* r, uint32_t addr) {
    asm volatile("ldmatrix.sync.aligned.m8n8.x4.shared.b16 {%0,%1,%2,%3}, [%4];"
        : "=r"(r[0]), "=r"(r[1]), "=r"(r[2]), "=r"(r[3]) : "r"(addr));
}
__device__ __forceinline__ void ldsm4t(uint32_t* r, uint32_t addr) {
    asm volatile("ldmatrix.sync.aligned.m8n8.x4.trans.shared.b16 {%0,%1,%2,%3}, [%4];"
        : "=r"(r[0]), "=r"(r[1]), "=r"(r[2]), "=r"(r[3]) : "r"(addr));
}
__device__ __forceinline__ void mma16816(float* c, const uint32_t* a, uint32_t b0, uint32_t b1) {
    asm volatile("mma.sync.aligned.m16n8k16.row.col.f32.bf16.bf16.f32 "
        "{%0,%1,%2,%3}, {%4,%5,%6,%7}, {%8,%9}, {%0,%1,%2,%3};"
        : "+f"(c[0]), "+f"(c[1]), "+f"(c[2]), "+f"(c[3])
        : "r"(a[0]), "r"(a[1]), "r"(a[2]), "r"(a[3]), "r"(b0), "r"(b1));
}
__device__ __forceinline__ uint32_t cvt_bf16x2(float hi, float lo) {
    uint32_t r;
    asm("cvt.rn.bf16x2.f32 %0, %1, %2;" : "=r"(r) : "f"(hi), "f"(lo));
    return r;
}
__device__ __forceinline__ uint32_t pack_hl(float x) {
    __nv_bfloat16 h = __float2bfloat16_rn(x);
    float hf = __bfloat162float(h);
    __nv_bfloat16 l = __float2bfloat16_rn(x - hf);
    return (uint32_t)__bfloat16_as_ushort(h) | ((uint32_t)__bfloat16_as_ushort(l) << 16);
}

// ---------------- Prepass A: f32 -> bf16 hi|lo concat along K ----------------
__global__ __launch_bounds__(256)
void split_a(const float* __restrict__ A)
{
    int idx = blockIdx.x * 256 + threadIdx.x;
    int m = idx / 192;
    int k4 = (idx - m * 192) * 4;
    float4 a = *(const float4*)&A[m * D_ + k4];
    __nv_bfloat16 h0 = __float2bfloat16_rn(a.x), h1 = __float2bfloat16_rn(a.y);
    __nv_bfloat16 h2 = __float2bfloat16_rn(a.z), h3 = __float2bfloat16_rn(a.w);
    __nv_bfloat16 l0 = __float2bfloat16_rn(a.x - __bfloat162float(h0));
    __nv_bfloat16 l1 = __float2bfloat16_rn(a.y - __bfloat162float(h1));
    __nv_bfloat16 l2 = __float2bfloat16_rn(a.z - __bfloat162float(h2));
    __nv_bfloat16 l3 = __float2bfloat16_rn(a.w - __bfloat162float(h3));
    uint2 ph, pl;
    ph.x = (uint32_t)__bfloat16_as_ushort(h0) | ((uint32_t)__bfloat16_as_ushort(h1) << 16);
    ph.y = (uint32_t)__bfloat16_as_ushort(h2) | ((uint32_t)__bfloat16_as_ushort(h3) << 16);
    pl.x = (uint32_t)__bfloat16_as_ushort(l0) | ((uint32_t)__bfloat16_as_ushort(l1) << 16);
    pl.y = (uint32_t)__bfloat16_as_ushort(l2) | ((uint32_t)__bfloat16_as_ushort(l3) << 16);
    *(uint2*)&g_aext[(size_t)m * KE_ + k4]       = ph;
    *(uint2*)&g_aext[(size_t)m * KE_ + D_ + k4]  = pl;
}

// ---------------- Prepass W: transpose + split ----------------
__global__ __launch_bounds__(256)
void split_wT(const float* __restrict__ W)
{
    __shared__ float t[32][33];
    int n0 = blockIdx.x * 32, k0 = blockIdx.y * 32;
    int tx = threadIdx.x, ty = threadIdx.y;
    #pragma unroll
    for (int j = 0; j < 4; j++)
        t[ty + j * 8][tx] = W[(size_t)(k0 + ty + j * 8) * N3_ + n0 + tx];
    __syncthreads();
    #pragma unroll
    for (int j = 0; j < 4; j++) {
        int n = n0 + ty + j * 8;
        int k = k0 + tx;
        float v = t[tx][ty + j * 8];
        __nv_bfloat16 h = __float2bfloat16_rn(v);
        __nv_bfloat16 l = __float2bfloat16_rn(v - __bfloat162float(h));
        g_bext[(size_t)n * KE_ + k]      = h;
        g_bext[(size_t)n * KE_ + D_ + k] = l;
    }
}

// ---------------- mma.sync GEMM with 3-term split pairing ----------------
#define NKC   36
#define ABYTES 16384
#define BUFB  32768
#define PITCH 132

__global__ __launch_bounds__(256)
void gemm_mma(const float* __restrict__ Wb, const int* __restrict__ maskp,
              float* __restrict__ resid)
{
    extern __shared__ char dsm[];
    __shared__ __align__(16) float s_bias[128];

    char* smem_al = (char*)(((uintptr_t)dsm + 1023) & ~(uintptr_t)1023);
    const uint32_t sbase = smem_u32(smem_al);

    const int tid = threadIdx.x;
    const int wid = tid >> 5, lane = tid & 31;
    const int wm = wid & 3, wn = wid >> 2;
    const int n0 = blockIdx.x * 128;
    const int m0 = blockIdx.y * 128;

    if (tid < 128) s_bias[tid] = Wb[n0 + tid];

    const char* agbase = (const char*)g_aext + (size_t)m0 * (KE_ * 2);
    const char* bgbase = (const char*)g_bext + (size_t)n0 * (KE_ * 2);

    int ld_row[4], ld_seg[4];
    #pragma unroll
    for (int p = 0; p < 4; p++) {
        int idx = p * 256 + tid;
        ld_row[p] = idx >> 3;
        ld_seg[p] = (idx & 7) * 16;
    }

    auto issue = [&](int kt, int buf) {
        int a_idx = (kt >= 24) ? kt - 24 : kt;
        int b_idx = (kt >= 12) ? kt - 12 : kt;
        const char* ag = agbase + a_idx * 128;
        const char* bg = bgbase + b_idx * 128;
        uint32_t base = sbase + buf * BUFB;
        #pragma unroll
        for (int p = 0; p < 4; p++) {
            uint32_t off = SWZ128(ld_row[p] * 128 + ld_seg[p]);
            cp_async16(base + off, ag + (size_t)ld_row[p] * (KE_ * 2) + ld_seg[p]);
        }
        #pragma unroll
        for (int p = 0; p < 4; p++) {
            uint32_t off = SWZ128(ld_row[p] * 128 + ld_seg[p]);
            cp_async16(base + ABYTES + off, bg + (size_t)ld_row[p] * (KE_ * 2) + ld_seg[p]);
        }
        cp_commit();
    };

    float c[2][8][4];
    #pragma unroll
    for (int i = 0; i < 2; i++)
        #pragma unroll
        for (int j = 0; j < 8; j++)
            #pragma unroll
            for (int q = 0; q < 4; q++) c[i][j][q] = 0.0f;

    uint32_t a_off[2][4], b_off[4][4];
    #pragma unroll
    for (int mi = 0; mi < 2; mi++)
        #pragma unroll
        for (int ks = 0; ks < 4; ks++) {
            int r = wm * 32 + mi * 16 + (lane & 15);
            int cb = ks * 32 + (lane >> 4) * 16;
            a_off[mi][ks] = SWZ128(r * 128 + cb);
        }
    #pragma unroll
    for (int ni = 0; ni < 4; ni++)
        #pragma unroll
        for (int ks = 0; ks < 4; ks++) {
            int r = wn * 64 + ni * 16 + (lane & 7) + ((lane >> 4) << 3);
            int cb = ks * 32 + ((lane >> 3) & 1) * 16;
            b_off[ni][ks] = ABYTES + SWZ128(r * 128 + cb);
        }

    issue(0, 0);

    for (int kt = 0; kt < NKC; kt++) {
        if (kt + 1 < NKC) {
            issue(kt + 1, (kt + 1) & 1);
            cp_wait<1>();
        } else {
            cp_wait<0>();
        }
        __syncthreads();

        uint32_t bufb = sbase + (kt & 1) * BUFB;
        #pragma unroll
        for (int ks = 0; ks < 4; ks++) {
            uint32_t a0[4], a1[4];
            ldsm4(a0, bufb + a_off[0][ks]);
            ldsm4(a1, bufb + a_off[1][ks]);
            uint32_t bb[4][4];
            #pragma unroll
            for (int ni = 0; ni < 4; ni++)
                ldsm4(bb[ni], bufb + b_off[ni][ks]);
            #pragma unroll
            for (int ni = 0; ni < 4; ni++) {
                mma16816(c[0][2 * ni],     a0, bb[ni][0], bb[ni][1]);
                mma16816(c[0][2 * ni + 1], a0, bb[ni][2], bb[ni][3]);
                mma16816(c[1][2 * ni],     a1, bb[ni][0], bb[ni][1]);
                mma16816(c[1][2 * ni + 1], a1, bb[ni][2], bb[ni][3]);
            }
        }
        __syncthreads();
    }

    // ---- stage C to smem ----
    float* Csm = (float*)smem_al;
    #pragma unroll
    for (int mi = 0; mi < 2; mi++)
        #pragma unroll
        for (int nj = 0; nj < 8; nj++) {
            int row = wm * 32 + mi * 16 + (lane >> 2);
            int col = wn * 64 + nj * 8 + (lane & 3) * 2;
            *(float2*)&Csm[row * PITCH + col]       = make_float2(c[mi][nj][0], c[mi][nj][1]);
            *(float2*)&Csm[(row + 8) * PITCH + col] = make_float2(c[mi][nj][2], c[mi][nj][3]);
        }
    __syncthreads();

    // ---- epilogue routing ----
    const int region = n0 / D_;
    const int b = m0 >> 9;

    if (region == 0) {
        int pr = tid >> 2;
        int cg = (tid & 3) * 32;
        int r0 = 2 * pr, r1 = r0 + 1;
        float mk0 = (float)maskp[m0 + r0];
        float mk1 = (float)maskp[m0 + r1];
        float inv = 1.0f / fmaxf(mk0 + mk1, 1.0f);
        int pglob = ((m0 & (S_ - 1)) >> 1) + pr;
        float* dst = resid + ((size_t)(b * P_ + pglob)) * D_ + n0 + cg;
        #pragma unroll
        for (int i = 0; i < 8; i++) {
            float4 x = *(float4*)&Csm[r0 * PITCH + cg + i * 4];
            float4 y = *(float4*)&Csm[r1 * PITCH + cg + i * 4];
            float4 bi = *(float4*)&s_bias[cg + i * 4];
            float4 o;
            o.x = ((x.x + bi.x) * mk0 + (y.x + bi.x) * mk1) * inv;
            o.y = ((x.y + bi.y) * mk0 + (y.y + bi.y) * mk1) * inv;
            o.z = ((x.z + bi.z) * mk0 + (y.z + bi.z) * mk1) * inv;
            o.w = ((x.w + bi.w) * mk0 + (y.w + bi.w) * mk1) * inv;
            *(float4*)(dst + i * 4) = o;
        }
    } else {
        int row = tid >> 1, half = tid & 1;
        int m = m0 + row;
        int s = m & (S_ - 1);
        float mk = (float)maskp[m];
        int head = ((n0 - region * D_) >> 6) + half;
        uint32_t* g = (region == 1) ? g_k : g_v;
        uint32_t* dst = g + (((size_t)(b * H_ + head)) * S_ + s) * DH_;
        int cbase = half * 64;
        #pragma unroll
        for (int i = 0; i < 16; i++) {
            float4 x = *(float4*)&Csm[row * PITCH + cbase + i * 4];
            float4 bi = *(float4*)&s_bias[cbase + i * 4];
            uint4 o;
            o.x = pack_hl((x.x + bi.x) * mk);
            o.y = pack_hl((x.y + bi.y) * mk);
            o.z = pack_hl((x.z + bi.z) * mk);
            o.w = pack_hl((x.w + bi.w) * mk);
            *(uint4*)(dst + i * 4) = o;
        }
    }
}

// ---------------- new_mask ----------------
__global__ void nm_kernel(const int* __restrict__ mask, float* __restrict__ out_nm)
{
    int i = blockIdx.x * blockDim.x + threadIdx.x;
    int b = i >> 8, p = i & 255;
    int m = mask[b * S_ + 2 * p] | mask[b * S_ + 2 * p + 1];
    out_nm[i] = (float)m;
}

// ---------------- attention: FA2-style mma.sync ----------------
// grid (2 ptiles, H, B), 128 threads (4 warps), warp = 32 P-rows, S-chunks of 32.
__global__ __launch_bounds__(128)
void attn_mma(const int* __restrict__ maskp, const float* __restrict__ resid,
              float* __restrict__ out)
{
    __shared__ __align__(16) uint8_t sKh[4096];
    __shared__ __align__(16) uint8_t sKl[4096];
    __shared__ __align__(16) uint8_t sVh[4096];
    __shared__ __align__(16) uint8_t sVl[4096];
    __shared__ float sb_sm[32];

    const int tid = threadIdx.x;
    const int lane = tid & 31, w = tid >> 5;
    const int b = blockIdx.z, h = blockIdx.y;
    const int p0 = blockIdx.x * 128 + w * 32;   // warp row base in [0,256)

    const float slope = (h < 8) ? exp2f(-(float)(h + 1)) : exp2f(-0.5f - (float)(h - 8));

    const uint32_t kh_base = smem_u32(sKh);
    const uint32_t kl_base = smem_u32(sKl);
    const uint32_t vh_base = smem_u32(sVh);
    const uint32_t vl_base = smem_u32(sVl);

    // ---- Q fragments (built once, direct gmem loads) ----
    uint32_t qh[2][4][4], ql[2][4][4];
    {
        const float* qb = resid + (size_t)(b * P_) * D_ + h * 64;
        #pragma unroll
        for (int mi = 0; mi < 2; mi++)
            #pragma unroll
            for (int ks = 0; ks < 4; ks++) {
                int r0 = p0 + mi * 16 + (lane >> 2);
                int c0 = ks * 16 + (lane & 3) * 2;
                float2 v[4];
                v[0] = *(const float2*)(qb + (size_t)r0 * D_ + c0);
                v[1] = *(const float2*)(qb + (size_t)(r0 + 8) * D_ + c0);
                v[2] = *(const float2*)(qb + (size_t)r0 * D_ + c0 + 8);
                v[3] = *(const float2*)(qb + (size_t)(r0 + 8) * D_ + c0 + 8);
                #pragma unroll
                for (int j = 0; j < 4; j++) {
                    uint32_t hp = cvt_bf16x2(v[j].y, v[j].x);
                    float h0 = __uint_as_float(hp << 16);
                    float h1 = __uint_as_float(hp & 0xFFFF0000u);
                    qh[mi][ks][j] = hp;
                    ql[mi][ks][j] = cvt_bf16x2(v[j].y - h1, v[j].x - h0);
                }
            }
    }

    // ldmatrix offsets (chunk-invariant)
    uint32_t koff[2][4];
    #pragma unroll
    for (int n16 = 0; n16 < 2; n16++)
        #pragma unroll
        for (int ks = 0; ks < 4; ks++) {
            int r = n16 * 16 + (lane & 7) + ((lane >> 4) << 3);
            int cb = ks * 32 + ((lane >> 3) & 1) * 16;
            koff[n16][ks] = SWZ128(r * 128 + cb);
        }
    uint32_t voff[2][4];
    #pragma unroll
    for (int ksP = 0; ksP < 2; ksP++)
        #pragma unroll
        for (int d16 = 0; d16 < 4; d16++) {
            int r = ksP * 16 + ((lane >> 3) & 1) * 8 + (lane & 7);
            int cb = d16 * 32 + ((lane >> 4) & 1) * 16;
            voff[ksP][d16] = SWZ128(r * 128 + cb);
        }

    float o[2][8][4];
    #pragma unroll
    for (int mi = 0; mi < 2; mi++)
        #pragma unroll
        for (int j = 0; j < 8; j++)
            #pragma unroll
            for (int q = 0; q < 4; q++) o[mi][j][q] = 0.0f;
    float mrun[2][2] = {{-1e30f, -1e30f}, {-1e30f, -1e30f}};
    float lsum[2][2] = {{0.0f, 0.0f}, {0.0f, 0.0f}};

    const uint32_t* kg = g_k + (size_t)(b * H_ + h) * S_ * DH_;
    const uint32_t* vg = g_v + (size_t)(b * H_ + h) * S_ * DH_;

    const int ldrow = tid >> 2;
    const int lddb  = (tid & 3) * 16;

    for (int cc = 0; cc < 16; cc++) {
        const int s0 = cc * 32;
        // ---- load K/V chunk, unpack hi/lo to smem ----
        {
            const uint4* ks4 = (const uint4*)(kg + (size_t)(s0 + ldrow) * 64 + lddb);
            const uint4* vs4 = (const uint4*)(vg + (size_t)(s0 + ldrow) * 64 + lddb);
            #pragma unroll
            for (int i = 0; i < 4; i++) {
                uint32_t off = SWZ128(ldrow * 128 + lddb * 2 + i * 8);
                uint4 pk = ks4[i];
                *(uint2*)(sKh + off) = make_uint2((pk.x & 0xFFFF) | (pk.y << 16),
                                                  (pk.z & 0xFFFF) | (pk.w << 16));
                *(uint2*)(sKl + off) = make_uint2((pk.x >> 16) | (pk.y & 0xFFFF0000u),
                                                  (pk.z >> 16) | (pk.w & 0xFFFF0000u));
                uint4 pv = vs4[i];
                *(uint2*)(sVh + off) = make_uint2((pv.x & 0xFFFF) | (pv.y << 16),
                                                  (pv.z & 0xFFFF) | (pv.w << 16));
                *(uint2*)(sVl + off) = make_uint2((pv.x >> 16) | (pv.y & 0xFFFF0000u),
                                                  (pv.z >> 16) | (pv.w & 0xFFFF0000u));
            }
            if (tid < 32)
                sb_sm[tid] = maskp[b * S_ + s0 + tid] ? 0.0f : -10000.0f;
        }
        __syncthreads();

        // ---- QK: scores 32x32 per warp (3-term split) ----
        float sc[2][4][4];
        #pragma unroll
        for (int mi = 0; mi < 2; mi++)
            #pragma unroll
            for (int j = 0; j < 4; j++)
                #pragma unroll
                for (int q = 0; q < 4; q++) sc[mi][j][q] = 0.0f;

        #pragma unroll
        for (int n16 = 0; n16 < 2; n16++) {
            #pragma unroll
            for (int ks = 0; ks < 4; ks++) {
                uint32_t bh4[4], bl4[4];
                ldsm4(bh4, kh_base + koff[n16][ks]);
                ldsm4(bl4, kl_base + koff[n16][ks]);
                #pragma unroll
                for (int mi = 0; mi < 2; mi++) {
                    mma16816(sc[mi][2*n16],   qh[mi][ks], bh4[0], bh4[1]);
                    mma16816(sc[mi][2*n16],   ql[mi][ks], bh4[0], bh4[1]);
                    mma16816(sc[mi][2*n16],   qh[mi][ks], bl4[0], bl4[1]);
                    mma16816(sc[mi][2*n16+1], qh[mi][ks], bh4[2], bh4[3]);
                    mma16816(sc[mi][2*n16+1], ql[mi][ks], bh4[2], bh4[3]);
                    mma16816(sc[mi][2*n16+1], qh[mi][ks], bl4[2], bl4[3]);
                }
            }
        }

        // ---- bias + online softmax ----
        #pragma unroll
        for (int mi = 0; mi < 2; mi++) {
            float r0f = (float)(p0 + mi * 16 + (lane >> 2));
            float r1f = r0f + 8.0f;
            float mx0 = -1e30f, mx1 = -1e30f;
            #pragma unroll
            for (int n8 = 0; n8 < 4; n8++) {
                int cl = n8 * 8 + (lane & 3) * 2;
                float colf = (float)(s0 + cl);
                float sb0 = sb_sm[cl], sb1 = sb_sm[cl + 1];
                sc[mi][n8][0] = sc[mi][n8][0] * 0.125f + sb0 - slope * fabsf(colf - r0f);
                sc[mi][n8][1] = sc[mi][n8][1] * 0.125f + sb1 - slope * fabsf(colf + 1.0f - r0f);
                sc[mi][n8][2] = sc[mi][n8][2] * 0.125f + sb0 - slope * fabsf(colf - r1f);
                sc[mi][n8][3] = sc[mi][n8][3] * 0.125f + sb1 - slope * fabsf(colf + 1.0f - r1f);
                mx0 = fmaxf(mx0, fmaxf(sc[mi][n8][0], sc[mi][n8][1]));
                mx1 = fmaxf(mx1, fmaxf(sc[mi][n8][2], sc[mi][n8][3]));
            }
            mx0 = fmaxf(mx0, __shfl_xor_sync(0xffffffffu, mx0, 1));
            mx0 = fmaxf(mx0, __shfl_xor_sync(0xffffffffu, mx0, 2));
            mx1 = fmaxf(mx1, __shfl_xor_sync(0xffffffffu, mx1, 1));
            mx1 = fmaxf(mx1, __shfl_xor_sync(0xffffffffu, mx1, 2));
            float mn0 = fmaxf(mrun[mi][0], mx0);
            float mn1 = fmaxf(mrun[mi][1], mx1);
            float cr0 = __expf(mrun[mi][0] - mn0);
            float cr1 = __expf(mrun[mi][1] - mn1);
            mrun[mi][0] = mn0; mrun[mi][1] = mn1;
            float rs0 = 0.0f, rs1 = 0.0f;
            #pragma unroll
            for (int n8 = 0; n8 < 4; n8++) {
                sc[mi][n8][0] = __expf(sc[mi][n8][0] - mn0);
                sc[mi][n8][1] = __expf(sc[mi][n8][1] - mn0);
                sc[mi][n8][2] = __expf(sc[mi][n8][2] - mn1);
                sc[mi][n8][3] = __expf(sc[mi][n8][3] - mn1);
                rs0 += sc[mi][n8][0] + sc[mi][n8][1];
                rs1 += sc[mi][n8][2] + sc[mi][n8][3];
            }
            rs0 += __shfl_xor_sync(0xffffffffu, rs0, 1);
            rs0 += __shfl_xor_sync(0xffffffffu, rs0, 2);
            rs1 += __shfl_xor_sync(0xffffffffu, rs1, 1);
            rs1 += __shfl_xor_sync(0xffffffffu, rs1, 2);
            lsum[mi][0] = lsum[mi][0] * cr0 + rs0;
            lsum[mi][1] = lsum[mi][1] * cr1 + rs1;
            #pragma unroll
            for (int d8 = 0; d8 < 8; d8++) {
                o[mi][d8][0] *= cr0; o[mi][d8][1] *= cr0;
                o[mi][d8][2] *= cr1; o[mi][d8][3] *= cr1;
            }
        }

        // ---- PV: 3-term split (ph*vh + pl*vh + ph*vl) ----
        #pragma unroll
        for (int ksP = 0; ksP < 2; ksP++) {
            uint32_t ph[2][4], pl[2][4];
            #pragma unroll
            for (int mi = 0; mi < 2; mi++) {
                float e0 = sc[mi][2*ksP][0], e1 = sc[mi][2*ksP][1];
                float e2 = sc[mi][2*ksP][2], e3 = sc[mi][2*ksP][3];
                float f0 = sc[mi][2*ksP+1][0], f1 = sc[mi][2*ksP+1][1];
                float f2 = sc[mi][2*ksP+1][2], f3 = sc[mi][2*ksP+1][3];
                ph[mi][0] = cvt_bf16x2(e1, e0);
                ph[mi][1] = cvt_bf16x2(e3, e2);
                ph[mi][2] = cvt_bf16x2(f1, f0);
                ph[mi][3] = cvt_bf16x2(f3, f2);
                #pragma unroll
                for (int j = 0; j < 4; j++) {
                    float lo = (j==0)?e0:(j==1)?e2:(j==2)?f0:f2;
                    float hi = (j==0)?e1:(j==1)?e3:(j==2)?f1:f3;
                    float h0 = __uint_as_float(ph[mi][j] << 16);
                    float h1 = __uint_as_float(ph[mi][j] & 0xFFFF0000u);
                    pl[mi][j] = cvt_bf16x2(hi - h1, lo - h0);
                }
            }
            #pragma unroll
            for (int d16 = 0; d16 < 4; d16++) {
                uint32_t vh4[4], vl4[4];
                ldsm4t(vh4, vh_base + voff[ksP][d16]);
                ldsm4t(vl4, vl_base + voff[ksP][d16]);
                #pragma unroll
                for (int mi = 0; mi < 2; mi++) {
                    mma16816(o[mi][2*d16],   ph[mi], vh4[0], vh4[1]);
                    mma16816(o[mi][2*d16],   pl[mi], vh4[0], vh4[1]);
                    mma16816(o[mi][2*d16],   ph[mi], vl4[0], vl4[1]);
                    mma16816(o[mi][2*d16+1], ph[mi], vh4[2], vh4[3]);
                    mma16816(o[mi][2*d16+1], pl[mi], vh4[2], vh4[3]);
                    mma16816(o[mi][2*d16+1], ph[mi], vl4[2], vl4[3]);
                }
            }
        }
        __syncthreads();
    }

    // ---- finalize: /lsum, *new_mask, store ----
    #pragma unroll
    for (int mi = 0; mi < 2; mi++) {
        int rp0 = p0 + mi * 16 + (lane >> 2);
        int rp1 = rp0 + 8;
        int nm0 = maskp[b * S_ + 2 * rp0] | maskp[b * S_ + 2 * rp0 + 1];
        int nm1 = maskp[b * S_ + 2 * rp1] | maskp[b * S_ + 2 * rp1 + 1];
        float s0v = nm0 ? (1.0f / lsum[mi][0]) : 0.0f;
        float s1v = nm1 ? (1.0f / lsum[mi][1]) : 0.0f;
        float* dst0 = out + (size_t)(b * P_ + rp0) * D_ + h * 64 + (lane & 3) * 2;
        float* dst1 = out + (size_t)(b * P_ + rp1) * D_ + h * 64 + (lane & 3) * 2;
        #pragma unroll
        for (int d8 = 0; d8 < 8; d8++) {
            *(float2*)(dst0 + d8 * 8) = make_float2(o[mi][d8][0] * s0v, o[mi][d8][1] * s0v);
            *(float2*)(dst1 + d8 * 8) = make_float2(o[mi][d8][2] * s1v, o[mi][d8][3] * s1v);
        }
    }
}

// ---------------- launch ----------------
extern "C" void kernel_launch(void* const* d_in, const int* in_sizes, int n_in,
                              void* d_out, int out_size)
{
    const float* hidden = (const float*)d_in[0];
    const int*   mask   = (const int*)d_in[1];
    const float* W      = (const float*)d_in[2];
    const float* Wb     = (const float*)d_in[3];
    float* out = (float*)d_out;

    float* resid = out + RQ_OFF;
    float* nmout = out + NM_OFF;

    (void)cudaFuncSetAttribute(gemm_mma, cudaFuncAttributeMaxDynamicSharedMemorySize, 69632);

    split_a<<<(B_*S_*D_/4 + 255) / 256, 256>>>(hidden);
    split_wT<<<dim3(N3_/32, D_/32), dim3(32, 8)>>>(W);
    gemm_mma<<<dim3(N3_/128, (B_*S_)/128), 256, 69632>>>(Wb, mask, resid);
    nm_kernel<<<(B_*P_)/256, 256>>>(mask, nmout);
    attn_mma<<<dim3(2, H_, B_), 128>>>(mask, resid, out);
}

// round 6
// speedup vs baseline: 4.4850x; 1.4143x over previous
#include <cuda_runtime.h>
#include <cuda_bf16.h>
#include <cstdint>

// Problem constants
#define B_   64
#define S_   512
#define D_   768
#define H_   12
#define DH_  64
#define P_   256
#define N3_  2304
#define KE_  1536   // stored extended K (hi|lo concat)

#define ATTN_SZ   (B_*P_*D_)
#define NM_OFF    (ATTN_SZ)
#define RQ_OFF    (ATTN_SZ + B_*P_)

// Scratch
__device__ uint32_t       g_k[B_*H_*S_*DH_];     // packed bf16 hi|lo
__device__ uint32_t       g_v[B_*H_*S_*DH_];
__device__ __nv_bfloat16  g_aextc[B_*S_*KE_];    // compacted unmasked rows, hi|lo
__device__ __nv_bfloat16  g_apool[B_*P_*KE_];    // pooled rows, hi|lo
__device__ __nv_bfloat16  g_bext[N3_*KE_];       // [2304][1536]  W^T hi|lo
// compaction bookkeeping
__device__ int g_cnt[B_];
__device__ int g_lp[B_*S_];
__device__ int g_boff[B_];
__device__ int g_mc[1];
__device__ int g_ntiles[1];
__device__ int g_gidx[B_*S_ + 128];

// ---------------- PTX helpers ----------------
__device__ __forceinline__ uint32_t smem_u32(const void* p) {
    uint32_t a;
    asm("{ .reg .u64 t; cvta.to.shared.u64 t, %1; cvt.u32.u64 %0, t; }" : "=r"(a) : "l"(p));
    return a;
}
#define SWZ128(o) ((o) ^ (((o) >> 3) & 0x70))

__device__ __forceinline__ void cp_async16(uint32_t dst, const void* src) {
    asm volatile("cp.async.cg.shared.global [%0], [%1], 16;" :: "r"(dst), "l"(src) : "memory");
}
__device__ __forceinline__ void cp_commit() {
    asm volatile("cp.async.commit_group;" ::: "memory");
}
template<int N>
__device__ __forceinline__ void cp_wait() {
    asm volatile("cp.async.wait_group %0;" :: "n"(N) : "memory");
}
__device__ __forceinline__ void ldsm4(uint32_t* r, uint32_t addr) {
    asm volatile("ldmatrix.sync.aligned.m8n8.x4.shared.b16 {%0,%1,%2,%3}, [%4];"
        : "=r"(r[0]), "=r"(r[1]), "=r"(r[2]), "=r"(r[3]) : "r"(addr));
}
__device__ __forceinline__ void ldsm4t(uint32_t* r, uint32_t addr) {
    asm volatile("ldmatrix.sync.aligned.m8n8.x4.trans.shared.b16 {%0,%1,%2,%3}, [%4];"
        : "=r"(r[0]), "=r"(r[1]), "=r"(r[2]), "=r"(r[3]) : "r"(addr));
}
__device__ __forceinline__ void mma16816(float* c, const uint32_t* a, uint32_t b0, uint32_t b1) {
    asm volatile("mma.sync.aligned.m16n8k16.row.col.f32.bf16.bf16.f32 "
        "{%0,%1,%2,%3}, {%4,%5,%6,%7}, {%8,%9}, {%0,%1,%2,%3};"
        : "+f"(c[0]), "+f"(c[1]), "+f"(c[2]), "+f"(c[3])
        : "r"(a[0]), "r"(a[1]), "r"(a[2]), "r"(a[3]), "r"(b0), "r"(b1));
}
__device__ __forceinline__ uint32_t cvt_bf16x2(float hi, float lo) {
    uint32_t r;
    asm("cvt.rn.bf16x2.f32 %0, %1, %2;" : "=r"(r) : "f"(hi), "f"(lo));
    return r;
}
__device__ __forceinline__ uint32_t pack_hl(float x) {
    __nv_bfloat16 h = __float2bfloat16_rn(x);
    float hf = __bfloat162float(h);
    __nv_bfloat16 l = __float2bfloat16_rn(x - hf);
    return (uint32_t)__bfloat16_as_ushort(h) | ((uint32_t)__bfloat16_as_ushort(l) << 16);
}
__device__ __forceinline__ void split4(float4 a, uint2& ph, uint2& pl) {
    __nv_bfloat16 h0 = __float2bfloat16_rn(a.x), h1 = __float2bfloat16_rn(a.y);
    __nv_bfloat16 h2 = __float2bfloat16_rn(a.z), h3 = __float2bfloat16_rn(a.w);
    __nv_bfloat16 l0 = __float2bfloat16_rn(a.x - __bfloat162float(h0));
    __nv_bfloat16 l1 = __float2bfloat16_rn(a.y - __bfloat162float(h1));
    __nv_bfloat16 l2 = __float2bfloat16_rn(a.z - __bfloat162float(h2));
    __nv_bfloat16 l3 = __float2bfloat16_rn(a.w - __bfloat162float(h3));
    ph.x = (uint32_t)__bfloat16_as_ushort(h0) | ((uint32_t)__bfloat16_as_ushort(h1) << 16);
    ph.y = (uint32_t)__bfloat16_as_ushort(h2) | ((uint32_t)__bfloat16_as_ushort(h3) << 16);
    pl.x = (uint32_t)__bfloat16_as_ushort(l0) | ((uint32_t)__bfloat16_as_ushort(l1) << 16);
    pl.y = (uint32_t)__bfloat16_as_ushort(l2) | ((uint32_t)__bfloat16_as_ushort(l3) << 16);
}

// ---------------- compaction prepasses ----------------
__global__ __launch_bounds__(512)
void scan_a(const int* __restrict__ mask)
{
    __shared__ int wsum[16];
    __shared__ int woff[16];
    int b = blockIdx.x, s = threadIdx.x;
    int v = mask[b * S_ + s] != 0;
    unsigned bal = __ballot_sync(0xffffffffu, v);
    int lane = s & 31, w = s >> 5;
    int wpre = __popc(bal & ((1u << lane) - 1u));
    if (lane == 31) wsum[w] = __popc(bal);
    __syncthreads();
    if (s == 0) {
        int acc = 0;
        #pragma unroll
        for (int i = 0; i < 16; i++) { woff[i] = acc; acc += wsum[i]; }
        g_cnt[b] = acc;
    }
    __syncthreads();
    if (v) g_lp[b * S_ + s] = woff[w] + wpre;
}

__global__ void scan_b()
{
    int acc = 0;
    for (int i = 0; i < B_; i++) { g_boff[i] = acc; acc += g_cnt[i]; }
    g_mc[0] = acc;
    int nt = (acc + 127) >> 7;
    g_ntiles[0] = nt;
    int pad = nt * 128;
    for (int i = acc; i < pad; i++) g_gidx[i] = 0;
}

__global__ __launch_bounds__(512)
void scatter_idx(const int* __restrict__ mask)
{
    int b = blockIdx.x, s = threadIdx.x, m = b * S_ + s;
    if (mask[m]) g_gidx[g_boff[b] + g_lp[m]] = m;
}

// ---------------- split compacted A rows ----------------
__global__ __launch_bounds__(256)
void split_ac(const float* __restrict__ A)
{
    int idx = blockIdx.x * 256 + threadIdx.x;
    int i = idx / 192;
    if (i >= g_mc[0]) return;
    int k4 = (idx - i * 192) * 4;
    int m = g_gidx[i];
    float4 a = *(const float4*)&A[(size_t)m * D_ + k4];
    uint2 ph, pl; split4(a, ph, pl);
    *(uint2*)&g_aextc[(size_t)i * KE_ + k4]      = ph;
    *(uint2*)&g_aextc[(size_t)i * KE_ + D_ + k4] = pl;
}

// ---------------- split pooled A rows (for q) ----------------
__global__ __launch_bounds__(256)
void split_pool(const float* __restrict__ A, const int* __restrict__ mask)
{
    int idx = blockIdx.x * 256 + threadIdx.x;     // 16384*192
    int p = idx / 192;
    int k4 = (idx - p * 192) * 4;
    int b = p >> 8, pl_ = p & 255;
    int m0 = b * S_ + 2 * pl_;
    float mk0 = (float)mask[m0], mk1 = (float)mask[m0 + 1];
    float inv = 1.0f / fmaxf(mk0 + mk1, 1.0f);
    float4 a0 = *(const float4*)&A[(size_t)m0 * D_ + k4];
    float4 a1 = *(const float4*)&A[(size_t)(m0 + 1) * D_ + k4];
    float4 ap = make_float4((mk0 * a0.x + mk1 * a1.x) * inv,
                            (mk0 * a0.y + mk1 * a1.y) * inv,
                            (mk0 * a0.z + mk1 * a1.z) * inv,
                            (mk0 * a0.w + mk1 * a1.w) * inv);
    uint2 ph, pl; split4(ap, ph, pl);
    *(uint2*)&g_apool[(size_t)p * KE_ + k4]      = ph;
    *(uint2*)&g_apool[(size_t)p * KE_ + D_ + k4] = pl;
}

// ---------------- Prepass W: transpose + split ----------------
__global__ __launch_bounds__(256)
void split_wT(const float* __restrict__ W)
{
    __shared__ float t[32][33];
    int n0 = blockIdx.x * 32, k0 = blockIdx.y * 32;
    int tx = threadIdx.x, ty = threadIdx.y;
    #pragma unroll
    for (int j = 0; j < 4; j++)
        t[ty + j * 8][tx] = W[(size_t)(k0 + ty + j * 8) * N3_ + n0 + tx];
    __syncthreads();
    #pragma unroll
    for (int j = 0; j < 4; j++) {
        int n = n0 + ty + j * 8;
        int k = k0 + tx;
        float v = t[tx][ty + j * 8];
        __nv_bfloat16 h = __float2bfloat16_rn(v);
        __nv_bfloat16 l = __float2bfloat16_rn(v - __bfloat162float(h));
        g_bext[(size_t)n * KE_ + k]      = h;
        g_bext[(size_t)n * KE_ + D_ + k] = l;
    }
}

// ---------------- shared mainloop macro pieces ----------------
#define NKC   36
#define ABYTES 16384
#define BUFB  32768
#define PITCH 132

// ---------------- q GEMM: M=16384 pooled rows, N=768 ----------------
__global__ __launch_bounds__(256)
void q_gemm(const float* __restrict__ Wb, const int* __restrict__ maskp,
            float* __restrict__ resid)
{
    extern __shared__ char dsm[];
    __shared__ __align__(16) float s_bias[128];

    char* smem_al = (char*)(((uintptr_t)dsm + 1023) & ~(uintptr_t)1023);
    const uint32_t sbase = smem_u32(smem_al);

    const int tid = threadIdx.x;
    const int wid = tid >> 5, lane = tid & 31;
    const int wm = wid & 3, wn = wid >> 2;
    const int n0 = blockIdx.x * 128;
    const int m0 = blockIdx.y * 128;

    if (tid < 128) s_bias[tid] = Wb[n0 + tid];

    const char* agbase = (const char*)g_apool + (size_t)m0 * (KE_ * 2);
    const char* bgbase = (const char*)g_bext + (size_t)n0 * (KE_ * 2);

    int ld_row[4], ld_seg[4];
    #pragma unroll
    for (int p = 0; p < 4; p++) {
        int idx = p * 256 + tid;
        ld_row[p] = idx >> 3;
        ld_seg[p] = (idx & 7) * 16;
    }

    auto issue = [&](int kt, int buf) {
        int a_idx = (kt >= 24) ? kt - 24 : kt;
        int b_idx = (kt >= 12) ? kt - 12 : kt;
        const char* ag = agbase + a_idx * 128;
        const char* bg = bgbase + b_idx * 128;
        uint32_t base = sbase + buf * BUFB;
        #pragma unroll
        for (int p = 0; p < 4; p++) {
            uint32_t off = SWZ128(ld_row[p] * 128 + ld_seg[p]);
            cp_async16(base + off, ag + (size_t)ld_row[p] * (KE_ * 2) + ld_seg[p]);
        }
        #pragma unroll
        for (int p = 0; p < 4; p++) {
            uint32_t off = SWZ128(ld_row[p] * 128 + ld_seg[p]);
            cp_async16(base + ABYTES + off, bg + (size_t)ld_row[p] * (KE_ * 2) + ld_seg[p]);
        }
        cp_commit();
    };

    float c[2][8][4];
    #pragma unroll
    for (int i = 0; i < 2; i++)
        #pragma unroll
        for (int j = 0; j < 8; j++)
            #pragma unroll
            for (int q = 0; q < 4; q++) c[i][j][q] = 0.0f;

    uint32_t a_off[2][4], b_off[4][4];
    #pragma unroll
    for (int mi = 0; mi < 2; mi++)
        #pragma unroll
        for (int ks = 0; ks < 4; ks++) {
            int r = wm * 32 + mi * 16 + (lane & 15);
            int cb = ks * 32 + (lane >> 4) * 16;
            a_off[mi][ks] = SWZ128(r * 128 + cb);
        }
    #pragma unroll
    for (int ni = 0; ni < 4; ni++)
        #pragma unroll
        for (int ks = 0; ks < 4; ks++) {
            int r = wn * 64 + ni * 16 + (lane & 7) + ((lane >> 4) << 3);
            int cb = ks * 32 + ((lane >> 3) & 1) * 16;
            b_off[ni][ks] = ABYTES + SWZ128(r * 128 + cb);
        }

    issue(0, 0);

    for (int kt = 0; kt < NKC; kt++) {
        if (kt + 1 < NKC) { issue(kt + 1, (kt + 1) & 1); cp_wait<1>(); }
        else cp_wait<0>();
        __syncthreads();

        uint32_t bufb = sbase + (kt & 1) * BUFB;
        #pragma unroll
        for (int ks = 0; ks < 4; ks++) {
            uint32_t a0[4], a1[4];
            ldsm4(a0, bufb + a_off[0][ks]);
            ldsm4(a1, bufb + a_off[1][ks]);
            uint32_t bb[4][4];
            #pragma unroll
            for (int ni = 0; ni < 4; ni++)
                ldsm4(bb[ni], bufb + b_off[ni][ks]);
            #pragma unroll
            for (int ni = 0; ni < 4; ni++) {
                mma16816(c[0][2 * ni],     a0, bb[ni][0], bb[ni][1]);
                mma16816(c[0][2 * ni + 1], a0, bb[ni][2], bb[ni][3]);
                mma16816(c[1][2 * ni],     a1, bb[ni][0], bb[ni][1]);
                mma16816(c[1][2 * ni + 1], a1, bb[ni][2], bb[ni][3]);
            }
        }
        __syncthreads();
    }

    float* Csm = (float*)smem_al;
    #pragma unroll
    for (int mi = 0; mi < 2; mi++)
        #pragma unroll
        for (int nj = 0; nj < 8; nj++) {
            int row = wm * 32 + mi * 16 + (lane >> 2);
            int col = wn * 64 + nj * 8 + (lane & 3) * 2;
            *(float2*)&Csm[row * PITCH + col]       = make_float2(c[mi][nj][0], c[mi][nj][1]);
            *(float2*)&Csm[(row + 8) * PITCH + col] = make_float2(c[mi][nj][2], c[mi][nj][3]);
        }
    __syncthreads();

    // epilogue: out = C + bias*(msum>0)
    int row = tid >> 1, half = tid & 1;
    int p = m0 + row;
    int b = p >> 8, pl_ = p & 255;
    int mm = b * S_ + 2 * pl_;
    float cb = (maskp[mm] | maskp[mm + 1]) ? 1.0f : 0.0f;
    float* dst = resid + (size_t)p * D_ + n0 + half * 64;
    int cbase = half * 64;
    #pragma unroll
    for (int i = 0; i < 16; i++) {
        float4 x = *(float4*)&Csm[row * PITCH + cbase + i * 4];
        float4 bi = *(float4*)&s_bias[cbase + i * 4];
        *(float4*)(dst + i * 4) = make_float4(x.x + bi.x * cb, x.y + bi.y * cb,
                                              x.z + bi.z * cb, x.w + bi.w * cb);
    }
}

// ---------------- kv GEMM: compacted M, N=1536 (cols 768..2303) ----------------
__global__ __launch_bounds__(256)
void kv_gemm(const float* __restrict__ Wb)
{
    extern __shared__ char dsm[];
    __shared__ __align__(16) float s_bias[128];
    __shared__ int s_gidx[128];

    if (blockIdx.y >= (unsigned)g_ntiles[0]) return;

    char* smem_al = (char*)(((uintptr_t)dsm + 1023) & ~(uintptr_t)1023);
    const uint32_t sbase = smem_u32(smem_al);

    const int tid = threadIdx.x;
    const int wid = tid >> 5, lane = tid & 31;
    const int wm = wid & 3, wn = wid >> 2;
    const int n0 = 768 + blockIdx.x * 128;
    const int m0 = blockIdx.y * 128;
    const int mc = g_mc[0];

    if (tid < 128) {
        s_bias[tid] = Wb[n0 + tid];
        s_gidx[tid] = g_gidx[m0 + tid];
    }

    const char* agbase = (const char*)g_aextc + (size_t)m0 * (KE_ * 2);
    const char* bgbase = (const char*)g_bext + (size_t)n0 * (KE_ * 2);

    int ld_row[4], ld_seg[4];
    #pragma unroll
    for (int p = 0; p < 4; p++) {
        int idx = p * 256 + tid;
        ld_row[p] = idx >> 3;
        ld_seg[p] = (idx & 7) * 16;
    }

    auto issue = [&](int kt, int buf) {
        int a_idx = (kt >= 24) ? kt - 24 : kt;
        int b_idx = (kt >= 12) ? kt - 12 : kt;
        const char* ag = agbase + a_idx * 128;
        const char* bg = bgbase + b_idx * 128;
        uint32_t base = sbase + buf * BUFB;
        #pragma unroll
        for (int p = 0; p < 4; p++) {
            uint32_t off = SWZ128(ld_row[p] * 128 + ld_seg[p]);
            cp_async16(base + off, ag + (size_t)ld_row[p] * (KE_ * 2) + ld_seg[p]);
        }
        #pragma unroll
        for (int p = 0; p < 4; p++) {
            uint32_t off = SWZ128(ld_row[p] * 128 + ld_seg[p]);
            cp_async16(base + ABYTES + off, bg + (size_t)ld_row[p] * (KE_ * 2) + ld_seg[p]);
        }
        cp_commit();
    };

    float c[2][8][4];
    #pragma unroll
    for (int i = 0; i < 2; i++)
        #pragma unroll
        for (int j = 0; j < 8; j++)
            #pragma unroll
            for (int q = 0; q < 4; q++) c[i][j][q] = 0.0f;

    uint32_t a_off[2][4], b_off[4][4];
    #pragma unroll
    for (int mi = 0; mi < 2; mi++)
        #pragma unroll
        for (int ks = 0; ks < 4; ks++) {
            int r = wm * 32 + mi * 16 + (lane & 15);
            int cb = ks * 32 + (lane >> 4) * 16;
            a_off[mi][ks] = SWZ128(r * 128 + cb);
        }
    #pragma unroll
    for (int ni = 0; ni < 4; ni++)
        #pragma unroll
        for (int ks = 0; ks < 4; ks++) {
            int r = wn * 64 + ni * 16 + (lane & 7) + ((lane >> 4) << 3);
            int cb = ks * 32 + ((lane >> 3) & 1) * 16;
            b_off[ni][ks] = ABYTES + SWZ128(r * 128 + cb);
        }

    issue(0, 0);

    for (int kt = 0; kt < NKC; kt++) {
        if (kt + 1 < NKC) { issue(kt + 1, (kt + 1) & 1); cp_wait<1>(); }
        else cp_wait<0>();
        __syncthreads();

        uint32_t bufb = sbase + (kt & 1) * BUFB;
        #pragma unroll
        for (int ks = 0; ks < 4; ks++) {
            uint32_t a0[4], a1[4];
            ldsm4(a0, bufb + a_off[0][ks]);
            ldsm4(a1, bufb + a_off[1][ks]);
            uint32_t bb[4][4];
            #pragma unroll
            for (int ni = 0; ni < 4; ni++)
                ldsm4(bb[ni], bufb + b_off[ni][ks]);
            #pragma unroll
            for (int ni = 0; ni < 4; ni++) {
                mma16816(c[0][2 * ni],     a0, bb[ni][0], bb[ni][1]);
                mma16816(c[0][2 * ni + 1], a0, bb[ni][2], bb[ni][3]);
                mma16816(c[1][2 * ni],     a1, bb[ni][0], bb[ni][1]);
                mma16816(c[1][2 * ni + 1], a1, bb[ni][2], bb[ni][3]);
            }
        }
        __syncthreads();
    }

    float* Csm = (float*)smem_al;
    #pragma unroll
    for (int mi = 0; mi < 2; mi++)
        #pragma unroll
        for (int nj = 0; nj < 8; nj++) {
            int row = wm * 32 + mi * 16 + (lane >> 2);
            int col = wn * 64 + nj * 8 + (lane & 3) * 2;
            *(float2*)&Csm[row * PITCH + col]       = make_float2(c[mi][nj][0], c[mi][nj][1]);
            *(float2*)&Csm[(row + 8) * PITCH + col] = make_float2(c[mi][nj][2], c[mi][nj][3]);
        }
    __syncthreads();

    // epilogue: scatter (no mask multiply — all rows unmasked)
    int row = tid >> 1, half = tid & 1;
    if (m0 + row < mc) {
        int m = s_gidx[row];
        int b = m >> 9, s = m & (S_ - 1);
        int region = 1 + (n0 >= 2 * D_);
        int head = ((n0 - region * D_) >> 6) + half;
        uint32_t* g = (region == 1) ? g_k : g_v;
        uint32_t* dst = g + (((size_t)(b * H_ + head)) * S_ + s) * DH_;
        int cbase = half * 64;
        #pragma unroll
        for (int i = 0; i < 16; i++) {
            float4 x = *(float4*)&Csm[row * PITCH + cbase + i * 4];
            float4 bi = *(float4*)&s_bias[cbase + i * 4];
            uint4 o;
            o.x = pack_hl(x.x + bi.x);
            o.y = pack_hl(x.y + bi.y);
            o.z = pack_hl(x.z + bi.z);
            o.w = pack_hl(x.w + bi.w);
            *(uint4*)(dst + i * 4) = o;
        }
    }
}

// ---------------- new_mask ----------------
__global__ void nm_kernel(const int* __restrict__ mask, float* __restrict__ out_nm)
{
    int i = blockIdx.x * blockDim.x + threadIdx.x;
    int b = i >> 8, p = i & 255;
    int m = mask[b * S_ + 2 * p] | mask[b * S_ + 2 * p + 1];
    out_nm[i] = (float)m;
}

// ---------------- attention: FA2-style mma.sync (validated round 5) ----------------
__global__ __launch_bounds__(128)
void attn_mma(const int* __restrict__ maskp, const float* __restrict__ resid,
              float* __restrict__ out)
{
    __shared__ __align__(16) uint8_t sKh[4096];
    __shared__ __align__(16) uint8_t sKl[4096];
    __shared__ __align__(16) uint8_t sVh[4096];
    __shared__ __align__(16) uint8_t sVl[4096];
    __shared__ float sb_sm[32];

    const int tid = threadIdx.x;
    const int lane = tid & 31, w = tid >> 5;
    const int b = blockIdx.z, h = blockIdx.y;
    const int p0 = blockIdx.x * 128 + w * 32;

    const float slope = (h < 8) ? exp2f(-(float)(h + 1)) : exp2f(-0.5f - (float)(h - 8));

    const uint32_t kh_base = smem_u32(sKh);
    const uint32_t kl_base = smem_u32(sKl);
    const uint32_t vh_base = smem_u32(sVh);
    const uint32_t vl_base = smem_u32(sVl);

    uint32_t qh[2][4][4], ql[2][4][4];
    {
        const float* qb = resid + (size_t)(b * P_) * D_ + h * 64;
        #pragma unroll
        for (int mi = 0; mi < 2; mi++)
            #pragma unroll
            for (int ks = 0; ks < 4; ks++) {
                int r0 = p0 + mi * 16 + (lane >> 2);
                int c0 = ks * 16 + (lane & 3) * 2;
                float2 v[4];
                v[0] = *(const float2*)(qb + (size_t)r0 * D_ + c0);
                v[1] = *(const float2*)(qb + (size_t)(r0 + 8) * D_ + c0);
                v[2] = *(const float2*)(qb + (size_t)r0 * D_ + c0 + 8);
                v[3] = *(const float2*)(qb + (size_t)(r0 + 8) * D_ + c0 + 8);
                #pragma unroll
                for (int j = 0; j < 4; j++) {
                    uint32_t hp = cvt_bf16x2(v[j].y, v[j].x);
                    float h0 = __uint_as_float(hp << 16);
                    float h1 = __uint_as_float(hp & 0xFFFF0000u);
                    qh[mi][ks][j] = hp;
                    ql[mi][ks][j] = cvt_bf16x2(v[j].y - h1, v[j].x - h0);
                }
            }
    }

    uint32_t koff[2][4];
    #pragma unroll
    for (int n16 = 0; n16 < 2; n16++)
        #pragma unroll
        for (int ks = 0; ks < 4; ks++) {
            int r = n16 * 16 + (lane & 7) + ((lane >> 4) << 3);
            int cb = ks * 32 + ((lane >> 3) & 1) * 16;
            koff[n16][ks] = SWZ128(r * 128 + cb);
        }
    uint32_t voff[2][4];
    #pragma unroll
    for (int ksP = 0; ksP < 2; ksP++)
        #pragma unroll
        for (int d16 = 0; d16 < 4; d16++) {
            int r = ksP * 16 + ((lane >> 3) & 1) * 8 + (lane & 7);
            int cb = d16 * 32 + ((lane >> 4) & 1) * 16;
            voff[ksP][d16] = SWZ128(r * 128 + cb);
        }

    float o[2][8][4];
    #pragma unroll
    for (int mi = 0; mi < 2; mi++)
        #pragma unroll
        for (int j = 0; j < 8; j++)
            #pragma unroll
            for (int q = 0; q < 4; q++) o[mi][j][q] = 0.0f;
    float mrun[2][2] = {{-1e30f, -1e30f}, {-1e30f, -1e30f}};
    float lsum[2][2] = {{0.0f, 0.0f}, {0.0f, 0.0f}};

    const uint32_t* kg = g_k + (size_t)(b * H_ + h) * S_ * DH_;
    const uint32_t* vg = g_v + (size_t)(b * H_ + h) * S_ * DH_;

    const int ldrow = tid >> 2;
    const int lddb  = (tid & 3) * 16;

    for (int cc = 0; cc < 16; cc++) {
        const int s0 = cc * 32;
        {
            const uint4* ks4 = (const uint4*)(kg + (size_t)(s0 + ldrow) * 64 + lddb);
            const uint4* vs4 = (const uint4*)(vg + (size_t)(s0 + ldrow) * 64 + lddb);
            #pragma unroll
            for (int i = 0; i < 4; i++) {
                uint32_t off = SWZ128(ldrow * 128 + lddb * 2 + i * 8);
                uint4 pk = ks4[i];
                *(uint2*)(sKh + off) = make_uint2((pk.x & 0xFFFF) | (pk.y << 16),
                                                  (pk.z & 0xFFFF) | (pk.w << 16));
                *(uint2*)(sKl + off) = make_uint2((pk.x >> 16) | (pk.y & 0xFFFF0000u),
                                                  (pk.z >> 16) | (pk.w & 0xFFFF0000u));
                uint4 pv = vs4[i];
                *(uint2*)(sVh + off) = make_uint2((pv.x & 0xFFFF) | (pv.y << 16),
                                                  (pv.z & 0xFFFF) | (pv.w << 16));
                *(uint2*)(sVl + off) = make_uint2((pv.x >> 16) | (pv.y & 0xFFFF0000u),
                                                  (pv.z >> 16) | (pv.w & 0xFFFF0000u));
            }
            if (tid < 32)
                sb_sm[tid] = maskp[b * S_ + s0 + tid] ? 0.0f : -10000.0f;
        }
        __syncthreads();

        float sc[2][4][4];
        #pragma unroll
        for (int mi = 0; mi < 2; mi++)
            #pragma unroll
            for (int j = 0; j < 4; j++)
                #pragma unroll
                for (int q = 0; q < 4; q++) sc[mi][j][q] = 0.0f;

        #pragma unroll
        for (int n16 = 0; n16 < 2; n16++) {
            #pragma unroll
            for (int ks = 0; ks < 4; ks++) {
                uint32_t bh4[4], bl4[4];
                ldsm4(bh4, kh_base + koff[n16][ks]);
                ldsm4(bl4, kl_base + koff[n16][ks]);
                #pragma unroll
                for (int mi = 0; mi < 2; mi++) {
                    mma16816(sc[mi][2*n16],   qh[mi][ks], bh4[0], bh4[1]);
                    mma16816(sc[mi][2*n16],   ql[mi][ks], bh4[0], bh4[1]);
                    mma16816(sc[mi][2*n16],   qh[mi][ks], bl4[0], bl4[1]);
                    mma16816(sc[mi][2*n16+1], qh[mi][ks], bh4[2], bh4[3]);
                    mma16816(sc[mi][2*n16+1], ql[mi][ks], bh4[2], bh4[3]);
                    mma16816(sc[mi][2*n16+1], qh[mi][ks], bl4[2], bl4[3]);
                }
            }
        }

        #pragma unroll
        for (int mi = 0; mi < 2; mi++) {
            float r0f = (float)(p0 + mi * 16 + (lane >> 2));
            float r1f = r0f + 8.0f;
            float mx0 = -1e30f, mx1 = -1e30f;
            #pragma unroll
            for (int n8 = 0; n8 < 4; n8++) {
                int cl = n8 * 8 + (lane & 3) * 2;
                float colf = (float)(s0 + cl);
                float sb0 = sb_sm[cl], sb1 = sb_sm[cl + 1];
                sc[mi][n8][0] = sc[mi][n8][0] * 0.125f + sb0 - slope * fabsf(colf - r0f);
                sc[mi][n8][1] = sc[mi][n8][1] * 0.125f + sb1 - slope * fabsf(colf + 1.0f - r0f);
                sc[mi][n8][2] = sc[mi][n8][2] * 0.125f + sb0 - slope * fabsf(colf - r1f);
                sc[mi][n8][3] = sc[mi][n8][3] * 0.125f + sb1 - slope * fabsf(colf + 1.0f - r1f);
                mx0 = fmaxf(mx0, fmaxf(sc[mi][n8][0], sc[mi][n8][1]));
                mx1 = fmaxf(mx1, fmaxf(sc[mi][n8][2], sc[mi][n8][3]));
            }
            mx0 = fmaxf(mx0, __shfl_xor_sync(0xffffffffu, mx0, 1));
            mx0 = fmaxf(mx0, __shfl_xor_sync(0xffffffffu, mx0, 2));
            mx1 = fmaxf(mx1, __shfl_xor_sync(0xffffffffu, mx1, 1));
            mx1 = fmaxf(mx1, __shfl_xor_sync(0xffffffffu, mx1, 2));
            float mn0 = fmaxf(mrun[mi][0], mx0);
            float mn1 = fmaxf(mrun[mi][1], mx1);
            float cr0 = __expf(mrun[mi][0] - mn0);
            float cr1 = __expf(mrun[mi][1] - mn1);
            mrun[mi][0] = mn0; mrun[mi][1] = mn1;
            float rs0 = 0.0f, rs1 = 0.0f;
            #pragma unroll
            for (int n8 = 0; n8 < 4; n8++) {
                sc[mi][n8][0] = __expf(sc[mi][n8][0] - mn0);
                sc[mi][n8][1] = __expf(sc[mi][n8][1] - mn0);
                sc[mi][n8][2] = __expf(sc[mi][n8][2] - mn1);
                sc[mi][n8][3] = __expf(sc[mi][n8][3] - mn1);
                rs0 += sc[mi][n8][0] + sc[mi][n8][1];
                rs1 += sc[mi][n8][2] + sc[mi][n8][3];
            }
            rs0 += __shfl_xor_sync(0xffffffffu, rs0, 1);
            rs0 += __shfl_xor_sync(0xffffffffu, rs0, 2);
            rs1 += __shfl_xor_sync(0xffffffffu, rs1, 1);
            rs1 += __shfl_xor_sync(0xffffffffu, rs1, 2);
            lsum[mi][0] = lsum[mi][0] * cr0 + rs0;
            lsum[mi][1] = lsum[mi][1] * cr1 + rs1;
            #pragma unroll
            for (int d8 = 0; d8 < 8; d8++) {
                o[mi][d8][0] *= cr0; o[mi][d8][1] *= cr0;
                o[mi][d8][2] *= cr1; o[mi][d8][3] *= cr1;
            }
        }

        #pragma unroll
        for (int ksP = 0; ksP < 2; ksP++) {
            uint32_t ph[2][4], pl[2][4];
            #pragma unroll
            for (int mi = 0; mi < 2; mi++) {
                float e0 = sc[mi][2*ksP][0], e1 = sc[mi][2*ksP][1];
                float e2 = sc[mi][2*ksP][2], e3 = sc[mi][2*ksP][3];
                float f0 = sc[mi][2*ksP+1][0], f1 = sc[mi][2*ksP+1][1];
                float f2 = sc[mi][2*ksP+1][2], f3 = sc[mi][2*ksP+1][3];
                ph[mi][0] = cvt_bf16x2(e1, e0);
                ph[mi][1] = cvt_bf16x2(e3, e2);
                ph[mi][2] = cvt_bf16x2(f1, f0);
                ph[mi][3] = cvt_bf16x2(f3, f2);
                #pragma unroll
                for (int j = 0; j < 4; j++) {
                    float lo = (j==0)?e0:(j==1)?e2:(j==2)?f0:f2;
                    float hi = (j==0)?e1:(j==1)?e3:(j==2)?f1:f3;
                    float h0 = __uint_as_float(ph[mi][j] << 16);
                    float h1 = __uint_as_float(ph[mi][j] & 0xFFFF0000u);
                    pl[mi][j] = cvt_bf16x2(hi - h1, lo - h0);
                }
            }
            #pragma unroll
            for (int d16 = 0; d16 < 4; d16++) {
                uint32_t vh4[4], vl4[4];
                ldsm4t(vh4, vh_base + voff[ksP][d16]);
                ldsm4t(vl4, vl_base + voff[ksP][d16]);
                #pragma unroll
                for (int mi = 0; mi < 2; mi++) {
                    mma16816(o[mi][2*d16],   ph[mi], vh4[0], vh4[1]);
                    mma16816(o[mi][2*d16],   pl[mi], vh4[0], vh4[1]);
                    mma16816(o[mi][2*d16],   ph[mi], vl4[0], vl4[1]);
                    mma16816(o[mi][2*d16+1], ph[mi], vh4[2], vh4[3]);
                    mma16816(o[mi][2*d16+1], pl[mi], vh4[2], vh4[3]);
                    mma16816(o[mi][2*d16+1], ph[mi], vl4[2], vl4[3]);
                }
            }
        }
        __syncthreads();
    }

    #pragma unroll
    for (int mi = 0; mi < 2; mi++) {
        int rp0 = p0 + mi * 16 + (lane >> 2);
        int rp1 = rp0 + 8;
        int nm0 = maskp[b * S_ + 2 * rp0] | maskp[b * S_ + 2 * rp0 + 1];
        int nm1 = maskp[b * S_ + 2 * rp1] | maskp[b * S_ + 2 * rp1 + 1];
        float s0v = nm0 ? (1.0f / lsum[mi][0]) : 0.0f;
        float s1v = nm1 ? (1.0f / lsum[mi][1]) : 0.0f;
        float* dst0 = out + (size_t)(b * P_ + rp0) * D_ + h * 64 + (lane & 3) * 2;
        float* dst1 = out + (size_t)(b * P_ + rp1) * D_ + h * 64 + (lane & 3) * 2;
        #pragma unroll
        for (int d8 = 0; d8 < 8; d8++) {
            *(float2*)(dst0 + d8 * 8) = make_float2(o[mi][d8][0] * s0v, o[mi][d8][1] * s0v);
            *(float2*)(dst1 + d8 * 8) = make_float2(o[mi][d8][2] * s1v, o[mi][d8][3] * s1v);
        }
    }
}

// ---------------- launch ----------------
extern "C" void kernel_launch(void* const* d_in, const int* in_sizes, int n_in,
                              void* d_out, int out_size)
{
    const float* hidden = (const float*)d_in[0];
    const int*   mask   = (const int*)d_in[1];
    const float* W      = (const float*)d_in[2];
    const float* Wb     = (const float*)d_in[3];
    float* out = (float*)d_out;

    float* resid = out + RQ_OFF;
    float* nmout = out + NM_OFF;

    (void)cudaFuncSetAttribute(q_gemm,  cudaFuncAttributeMaxDynamicSharedMemorySize, 69632);
    (void)cudaFuncSetAttribute(kv_gemm, cudaFuncAttributeMaxDynamicSharedMemorySize, 69632);

    scan_a<<<B_, 512>>>(mask);
    scan_b<<<1, 1>>>();
    scatter_idx<<<B_, 512>>>(mask);
    split_ac<<<(B_*S_*192 + 255) / 256, 256>>>(hidden);
    split_pool<<<(B_*P_*192 + 255) / 256, 256>>>(hidden, mask);
    split_wT<<<dim3(N3_/32, D_/32), dim3(32, 8)>>>(W);
    q_gemm<<<dim3(6, 128), 256, 69632>>>(Wb, mask, resid);
    kv_gemm<<<dim3(12, 256), 256, 69632>>>(Wb);
    nm_kernel<<<(B_*P_)/256, 256>>>(mask, nmout);
    attn_mma<<<dim3(2, H_, B_), 128>>>(mask, resid, out);
}

// round 7
// speedup vs baseline: 4.6548x; 1.0379x over previous
#include <cuda_runtime.h>
#include <cuda_bf16.h>
#include <cstdint>

// Problem constants
#define B_   64
#define S_   512
#define D_   768
#define H_   12
#define DH_  64
#define P_   256
#define N3_  2304
#define KE_  1536   // stored extended K (hi|lo concat)

#define ATTN_SZ   (B_*P_*D_)
#define NM_OFF    (ATTN_SZ)
#define RQ_OFF    (ATTN_SZ + B_*P_)

// Scratch
__device__ uint32_t       g_k[B_*H_*S_*DH_];     // packed bf16 hi|lo
__device__ uint32_t       g_v[B_*H_*S_*DH_];
__device__ __nv_bfloat16  g_aextc[B_*S_*KE_];    // compacted unmasked rows, hi|lo
__device__ __nv_bfloat16  g_apool[B_*P_*KE_];    // pooled rows, hi|lo
__device__ __nv_bfloat16  g_bext[N3_*KE_];       // [2304][1536]  W^T hi|lo
// compaction bookkeeping
__device__ int g_cnt[B_];
__device__ int g_lp[B_*S_];
__device__ int g_boff[B_];
__device__ int g_mc[1];
__device__ int g_ntiles[1];
__device__ int g_gidx[B_*S_ + 128];

// ---------------- PTX helpers ----------------
__device__ __forceinline__ uint32_t smem_u32(const void* p) {
    uint32_t a;
    asm("{ .reg .u64 t; cvta.to.shared.u64 t, %1; cvt.u32.u64 %0, t; }" : "=r"(a) : "l"(p));
    return a;
}
#define SWZ128(o) ((o) ^ (((o) >> 3) & 0x70))

__device__ __forceinline__ void cp_async16(uint32_t dst, const void* src) {
    asm volatile("cp.async.cg.shared.global [%0], [%1], 16;" :: "r"(dst), "l"(src) : "memory");
}
__device__ __forceinline__ void cp_commit() {
    asm volatile("cp.async.commit_group;" ::: "memory");
}
template<int N>
__device__ __forceinline__ void cp_wait() {
    asm volatile("cp.async.wait_group %0;" :: "n"(N) : "memory");
}
__device__ __forceinline__ void ldsm4(uint32_t* r, uint32_t addr) {
    asm volatile("ldmatrix.sync.aligned.m8n8.x4.shared.b16 {%0,%1,%2,%3}, [%4];"
        : "=r"(r[0]), "=r"(r[1]), "=r"(r[2]), "=r"(r[3]) : "r"(addr));
}
__device__ __forceinline__ void ldsm4t(uint32_t* r, uint32_t addr) {
    asm volatile("ldmatrix.sync.aligned.m8n8.x4.trans.shared.b16 {%0,%1,%2,%3}, [%4];"
        : "=r"(r[0]), "=r"(r[1]), "=r"(r[2]), "=r"(r[3]) : "r"(addr));
}
__device__ __forceinline__ void mma16816(float* c, const uint32_t* a, uint32_t b0, uint32_t b1) {
    asm volatile("mma.sync.aligned.m16n8k16.row.col.f32.bf16.bf16.f32 "
        "{%0,%1,%2,%3}, {%4,%5,%6,%7}, {%8,%9}, {%0,%1,%2,%3};"
        : "+f"(c[0]), "+f"(c[1]), "+f"(c[2]), "+f"(c[3])
        : "r"(a[0]), "r"(a[1]), "r"(a[2]), "r"(a[3]), "r"(b0), "r"(b1));
}
__device__ __forceinline__ uint32_t cvt_bf16x2(float hi, float lo) {
    uint32_t r;
    asm("cvt.rn.bf16x2.f32 %0, %1, %2;" : "=r"(r) : "f"(hi), "f"(lo));
    return r;
}
__device__ __forceinline__ uint32_t pack_hl(float x) {
    __nv_bfloat16 h = __float2bfloat16_rn(x);
    float hf = __bfloat162float(h);
    __nv_bfloat16 l = __float2bfloat16_rn(x - hf);
    return (uint32_t)__bfloat16_as_ushort(h) | ((uint32_t)__bfloat16_as_ushort(l) << 16);
}
__device__ __forceinline__ void split4(float4 a, uint2& ph, uint2& pl) {
    __nv_bfloat16 h0 = __float2bfloat16_rn(a.x), h1 = __float2bfloat16_rn(a.y);
    __nv_bfloat16 h2 = __float2bfloat16_rn(a.z), h3 = __float2bfloat16_rn(a.w);
    __nv_bfloat16 l0 = __float2bfloat16_rn(a.x - __bfloat162float(h0));
    __nv_bfloat16 l1 = __float2bfloat16_rn(a.y - __bfloat162float(h1));
    __nv_bfloat16 l2 = __float2bfloat16_rn(a.z - __bfloat162float(h2));
    __nv_bfloat16 l3 = __float2bfloat16_rn(a.w - __bfloat162float(h3));
    ph.x = (uint32_t)__bfloat16_as_ushort(h0) | ((uint32_t)__bfloat16_as_ushort(h1) << 16);
    ph.y = (uint32_t)__bfloat16_as_ushort(h2) | ((uint32_t)__bfloat16_as_ushort(h3) << 16);
    pl.x = (uint32_t)__bfloat16_as_ushort(l0) | ((uint32_t)__bfloat16_as_ushort(l1) << 16);
    pl.y = (uint32_t)__bfloat16_as_ushort(l2) | ((uint32_t)__bfloat16_as_ushort(l3) << 16);
}

// ---------------- compaction prepasses ----------------
__global__ __launch_bounds__(512)
void scan_a(const int* __restrict__ mask)
{
    __shared__ int wsum[16];
    __shared__ int woff[16];
    int b = blockIdx.x, s = threadIdx.x;
    int v = mask[b * S_ + s] != 0;
    unsigned bal = __ballot_sync(0xffffffffu, v);
    int lane = s & 31, w = s >> 5;
    int wpre = __popc(bal & ((1u << lane) - 1u));
    if (lane == 31) wsum[w] = __popc(bal);
    __syncthreads();
    if (s == 0) {
        int acc = 0;
        #pragma unroll
        for (int i = 0; i < 16; i++) { woff[i] = acc; acc += wsum[i]; }
        g_cnt[b] = acc;
    }
    __syncthreads();
    if (v) g_lp[b * S_ + s] = woff[w] + wpre;
}

__global__ void scan_b()
{
    int acc = 0;
    for (int i = 0; i < B_; i++) { g_boff[i] = acc; acc += g_cnt[i]; }
    g_mc[0] = acc;
    int nt = (acc + 127) >> 7;
    g_ntiles[0] = nt;
    int pad = nt * 128;
    for (int i = acc; i < pad; i++) g_gidx[i] = 0;
}

__global__ __launch_bounds__(512)
void scatter_idx(const int* __restrict__ mask)
{
    int b = blockIdx.x, s = threadIdx.x, m = b * S_ + s;
    if (mask[m]) g_gidx[g_boff[b] + g_lp[m]] = m;
}

// ---------------- split compacted A rows ----------------
__global__ __launch_bounds__(256)
void split_ac(const float* __restrict__ A)
{
    int idx = blockIdx.x * 256 + threadIdx.x;
    int i = idx / 192;
    if (i >= g_mc[0]) return;
    int k4 = (idx - i * 192) * 4;
    int m = g_gidx[i];
    float4 a = *(const float4*)&A[(size_t)m * D_ + k4];
    uint2 ph, pl; split4(a, ph, pl);
    *(uint2*)&g_aextc[(size_t)i * KE_ + k4]      = ph;
    *(uint2*)&g_aextc[(size_t)i * KE_ + D_ + k4] = pl;
}

// ---------------- split pooled A rows (for q) ----------------
__global__ __launch_bounds__(256)
void split_pool(const float* __restrict__ A, const int* __restrict__ mask)
{
    int idx = blockIdx.x * 256 + threadIdx.x;     // 16384*192
    int p = idx / 192;
    int k4 = (idx - p * 192) * 4;
    int b = p >> 8, pl_ = p & 255;
    int m0 = b * S_ + 2 * pl_;
    float mk0 = (float)mask[m0], mk1 = (float)mask[m0 + 1];
    float inv = 1.0f / fmaxf(mk0 + mk1, 1.0f);
    float4 a0 = *(const float4*)&A[(size_t)m0 * D_ + k4];
    float4 a1 = *(const float4*)&A[(size_t)(m0 + 1) * D_ + k4];
    float4 ap = make_float4((mk0 * a0.x + mk1 * a1.x) * inv,
                            (mk0 * a0.y + mk1 * a1.y) * inv,
                            (mk0 * a0.z + mk1 * a1.z) * inv,
                            (mk0 * a0.w + mk1 * a1.w) * inv);
    uint2 ph, pl; split4(ap, ph, pl);
    *(uint2*)&g_apool[(size_t)p * KE_ + k4]      = ph;
    *(uint2*)&g_apool[(size_t)p * KE_ + D_ + k4] = pl;
}

// ---------------- Prepass W: transpose + split ----------------
__global__ __launch_bounds__(256)
void split_wT(const float* __restrict__ W)
{
    __shared__ float t[32][33];
    int n0 = blockIdx.x * 32, k0 = blockIdx.y * 32;
    int tx = threadIdx.x, ty = threadIdx.y;
    #pragma unroll
    for (int j = 0; j < 4; j++)
        t[ty + j * 8][tx] = W[(size_t)(k0 + ty + j * 8) * N3_ + n0 + tx];
    __syncthreads();
    #pragma unroll
    for (int j = 0; j < 4; j++) {
        int n = n0 + ty + j * 8;
        int k = k0 + tx;
        float v = t[tx][ty + j * 8];
        __nv_bfloat16 h = __float2bfloat16_rn(v);
        __nv_bfloat16 l = __float2bfloat16_rn(v - __bfloat162float(h));
        g_bext[(size_t)n * KE_ + k]      = h;
        g_bext[(size_t)n * KE_ + D_ + k] = l;
    }
}

// ---------------- unified 3-stage GEMM ----------------
// 1-D grid: blocks [0,768) = q tiles (6 n x 128 m), [768, 768+3072) = kv slots (12 n x 256 m, early-exit)
#define NKC   36
#define ABYTES 16384
#define BUFB  32768
#define PITCH 132
#define SMEM_REQ (3*BUFB + 1024)

__global__ __launch_bounds__(256, 2)
void gemm_all(const float* __restrict__ Wb, const int* __restrict__ maskp,
              float* __restrict__ resid)
{
    extern __shared__ char dsm[];
    __shared__ __align__(16) float s_bias[128];
    __shared__ int s_gidx[128];

    char* smem_al = (char*)(((uintptr_t)dsm + 1023) & ~(uintptr_t)1023);
    const uint32_t sbase = smem_u32(smem_al);

    const int bid = blockIdx.x;
    const bool isq = bid < 768;
    int n0, m0;
    const char* agbase;
    if (isq) {
        n0 = (bid % 6) * 128;
        m0 = (bid / 6) * 128;
        agbase = (const char*)g_apool + (size_t)m0 * (KE_ * 2);
    } else {
        int r = bid - 768;
        int by = r / 12;
        if (by >= g_ntiles[0]) return;
        n0 = 768 + (r % 12) * 128;
        m0 = by * 128;
        agbase = (const char*)g_aextc + (size_t)m0 * (KE_ * 2);
    }
    const char* bgbase = (const char*)g_bext + (size_t)n0 * (KE_ * 2);

    const int tid = threadIdx.x;
    const int wid = tid >> 5, lane = tid & 31;
    const int wm = wid & 3, wn = wid >> 2;
    const int mc = g_mc[0];

    if (tid < 128) {
        s_bias[tid] = Wb[n0 + tid];
        if (!isq) s_gidx[tid] = g_gidx[m0 + tid];
    }

    uint32_t ld_off[4];
    int g_offv[4];
    #pragma unroll
    for (int p = 0; p < 4; p++) {
        int idx = p * 256 + tid;
        int row = idx >> 3, seg = (idx & 7) * 16;
        ld_off[p] = SWZ128(row * 128 + seg);
        g_offv[p] = row * (KE_ * 2) + seg;
    }

    auto issue = [&](int kt) {
        int a_idx = (kt >= 24) ? kt - 24 : kt;
        int b_idx = (kt >= 12) ? kt - 12 : kt;
        const char* ag = agbase + a_idx * 128;
        const char* bg = bgbase + b_idx * 128;
        int bsel = kt - (kt / 3) * 3;
        uint32_t base = sbase + bsel * BUFB;
        #pragma unroll
        for (int p = 0; p < 4; p++)
            cp_async16(base + ld_off[p], ag + g_offv[p]);
        #pragma unroll
        for (int p = 0; p < 4; p++)
            cp_async16(base + ABYTES + ld_off[p], bg + g_offv[p]);
        cp_commit();
    };

    float c[2][8][4];
    #pragma unroll
    for (int i = 0; i < 2; i++)
        #pragma unroll
        for (int j = 0; j < 8; j++)
            #pragma unroll
            for (int q = 0; q < 4; q++) c[i][j][q] = 0.0f;

    uint32_t a_off[2][4], b_off[4][4];
    #pragma unroll
    for (int mi = 0; mi < 2; mi++)
        #pragma unroll
        for (int ks = 0; ks < 4; ks++) {
            int r = wm * 32 + mi * 16 + (lane & 15);
            int cb = ks * 32 + (lane >> 4) * 16;
            a_off[mi][ks] = SWZ128(r * 128 + cb);
        }
    #pragma unroll
    for (int ni = 0; ni < 4; ni++)
        #pragma unroll
        for (int ks = 0; ks < 4; ks++) {
            int r = wn * 64 + ni * 16 + (lane & 7) + ((lane >> 4) << 3);
            int cb = ks * 32 + ((lane >> 3) & 1) * 16;
            b_off[ni][ks] = ABYTES + SWZ128(r * 128 + cb);
        }

    issue(0);
    issue(1);

    for (int kt = 0; kt < NKC; kt++) {
        cp_wait<1>();
        __syncthreads();

        int bsel = kt - (kt / 3) * 3;
        uint32_t bufb = sbase + bsel * BUFB;
        #pragma unroll
        for (int ks = 0; ks < 4; ks++) {
            uint32_t a0[4], a1[4];
            ldsm4(a0, bufb + a_off[0][ks]);
            ldsm4(a1, bufb + a_off[1][ks]);
            uint32_t bb[4][4];
            #pragma unroll
            for (int ni = 0; ni < 4; ni++)
                ldsm4(bb[ni], bufb + b_off[ni][ks]);
            #pragma unroll
            for (int ni = 0; ni < 4; ni++) {
                mma16816(c[0][2 * ni],     a0, bb[ni][0], bb[ni][1]);
                mma16816(c[0][2 * ni + 1], a0, bb[ni][2], bb[ni][3]);
                mma16816(c[1][2 * ni],     a1, bb[ni][0], bb[ni][1]);
                mma16816(c[1][2 * ni + 1], a1, bb[ni][2], bb[ni][3]);
            }
        }
        if (kt + 2 < NKC) issue(kt + 2);
    }
    cp_wait<0>();
    __syncthreads();

    // ---- stage C to smem ----
    float* Csm = (float*)smem_al;
    #pragma unroll
    for (int mi = 0; mi < 2; mi++)
        #pragma unroll
        for (int nj = 0; nj < 8; nj++) {
            int row = wm * 32 + mi * 16 + (lane >> 2);
            int col = wn * 64 + nj * 8 + (lane & 3) * 2;
            *(float2*)&Csm[row * PITCH + col]       = make_float2(c[mi][nj][0], c[mi][nj][1]);
            *(float2*)&Csm[(row + 8) * PITCH + col] = make_float2(c[mi][nj][2], c[mi][nj][3]);
        }
    __syncthreads();

    int row = tid >> 1, half = tid & 1;
    int cbase = half * 64;
    if (isq) {
        int p = m0 + row;
        int b = p >> 8, pl_ = p & 255;
        int mm = b * S_ + 2 * pl_;
        float cb = (maskp[mm] | maskp[mm + 1]) ? 1.0f : 0.0f;
        float* dst = resid + (size_t)p * D_ + n0 + cbase;
        #pragma unroll
        for (int i = 0; i < 16; i++) {
            float4 x = *(float4*)&Csm[row * PITCH + cbase + i * 4];
            float4 bi = *(float4*)&s_bias[cbase + i * 4];
            *(float4*)(dst + i * 4) = make_float4(x.x + bi.x * cb, x.y + bi.y * cb,
                                                  x.z + bi.z * cb, x.w + bi.w * cb);
        }
    } else if (m0 + row < mc) {
        int m = s_gidx[row];
        int b = m >> 9, s = m & (S_ - 1);
        int region = 1 + (n0 >= 2 * D_);
        int head = ((n0 - region * D_) >> 6) + half;
        uint32_t* g = (region == 1) ? g_k : g_v;
        uint32_t* dst = g + (((size_t)(b * H_ + head)) * S_ + s) * DH_;
        #pragma unroll
        for (int i = 0; i < 16; i++) {
            float4 x = *(float4*)&Csm[row * PITCH + cbase + i * 4];
            float4 bi = *(float4*)&s_bias[cbase + i * 4];
            uint4 o;
            o.x = pack_hl(x.x + bi.x);
            o.y = pack_hl(x.y + bi.y);
            o.z = pack_hl(x.z + bi.z);
            o.w = pack_hl(x.w + bi.w);
            *(uint4*)(dst + i * 4) = o;
        }
    }
}

// ---------------- new_mask ----------------
__global__ void nm_kernel(const int* __restrict__ mask, float* __restrict__ out_nm)
{
    int i = blockIdx.x * blockDim.x + threadIdx.x;
    int b = i >> 8, p = i & 255;
    int m = mask[b * S_ + 2 * p] | mask[b * S_ + 2 * p + 1];
    out_nm[i] = (float)m;
}

// ---------------- attention: FA2-style mma.sync (validated round 5) ----------------
__global__ __launch_bounds__(128)
void attn_mma(const int* __restrict__ maskp, const float* __restrict__ resid,
              float* __restrict__ out)
{
    __shared__ __align__(16) uint8_t sKh[4096];
    __shared__ __align__(16) uint8_t sKl[4096];
    __shared__ __align__(16) uint8_t sVh[4096];
    __shared__ __align__(16) uint8_t sVl[4096];
    __shared__ float sb_sm[32];

    const int tid = threadIdx.x;
    const int lane = tid & 31, w = tid >> 5;
    const int b = blockIdx.z, h = blockIdx.y;
    const int p0 = blockIdx.x * 128 + w * 32;

    const float slope = (h < 8) ? exp2f(-(float)(h + 1)) : exp2f(-0.5f - (float)(h - 8));

    const uint32_t kh_base = smem_u32(sKh);
    const uint32_t kl_base = smem_u32(sKl);
    const uint32_t vh_base = smem_u32(sVh);
    const uint32_t vl_base = smem_u32(sVl);

    uint32_t qh[2][4][4], ql[2][4][4];
    {
        const float* qb = resid + (size_t)(b * P_) * D_ + h * 64;
        #pragma unroll
        for (int mi = 0; mi < 2; mi++)
            #pragma unroll
            for (int ks = 0; ks < 4; ks++) {
                int r0 = p0 + mi * 16 + (lane >> 2);
                int c0 = ks * 16 + (lane & 3) * 2;
                float2 v[4];
                v[0] = *(const float2*)(qb + (size_t)r0 * D_ + c0);
                v[1] = *(const float2*)(qb + (size_t)(r0 + 8) * D_ + c0);
                v[2] = *(const float2*)(qb + (size_t)r0 * D_ + c0 + 8);
                v[3] = *(const float2*)(qb + (size_t)(r0 + 8) * D_ + c0 + 8);
                #pragma unroll
                for (int j = 0; j < 4; j++) {
                    uint32_t hp = cvt_bf16x2(v[j].y, v[j].x);
                    float h0 = __uint_as_float(hp << 16);
                    float h1 = __uint_as_float(hp & 0xFFFF0000u);
                    qh[mi][ks][j] = hp;
                    ql[mi][ks][j] = cvt_bf16x2(v[j].y - h1, v[j].x - h0);
                }
            }
    }

    uint32_t koff[2][4];
    #pragma unroll
    for (int n16 = 0; n16 < 2; n16++)
        #pragma unroll
        for (int ks = 0; ks < 4; ks++) {
            int r = n16 * 16 + (lane & 7) + ((lane >> 4) << 3);
            int cb = ks * 32 + ((lane >> 3) & 1) * 16;
            koff[n16][ks] = SWZ128(r * 128 + cb);
        }
    uint32_t voff[2][4];
    #pragma unroll
    for (int ksP = 0; ksP < 2; ksP++)
        #pragma unroll
        for (int d16 = 0; d16 < 4; d16++) {
            int r = ksP * 16 + ((lane >> 3) & 1) * 8 + (lane & 7);
            int cb = d16 * 32 + ((lane >> 4) & 1) * 16;
            voff[ksP][d16] = SWZ128(r * 128 + cb);
        }

    float o[2][8][4];
    #pragma unroll
    for (int mi = 0; mi < 2; mi++)
        #pragma unroll
        for (int j = 0; j < 8; j++)
            #pragma unroll
            for (int q = 0; q < 4; q++) o[mi][j][q] = 0.0f;
    float mrun[2][2] = {{-1e30f, -1e30f}, {-1e30f, -1e30f}};
    float lsum[2][2] = {{0.0f, 0.0f}, {0.0f, 0.0f}};

    const uint32_t* kg = g_k + (size_t)(b * H_ + h) * S_ * DH_;
    const uint32_t* vg = g_v + (size_t)(b * H_ + h) * S_ * DH_;

    const int ldrow = tid >> 2;
    const int lddb  = (tid & 3) * 16;

    for (int cc = 0; cc < 16; cc++) {
        const int s0 = cc * 32;
        {
            const uint4* ks4 = (const uint4*)(kg + (size_t)(s0 + ldrow) * 64 + lddb);
            const uint4* vs4 = (const uint4*)(vg + (size_t)(s0 + ldrow) * 64 + lddb);
            #pragma unroll
            for (int i = 0; i < 4; i++) {
                uint32_t off = SWZ128(ldrow * 128 + lddb * 2 + i * 8);
                uint4 pk = ks4[i];
                *(uint2*)(sKh + off) = make_uint2((pk.x & 0xFFFF) | (pk.y << 16),
                                                  (pk.z & 0xFFFF) | (pk.w << 16));
                *(uint2*)(sKl + off) = make_uint2((pk.x >> 16) | (pk.y & 0xFFFF0000u),
                                                  (pk.z >> 16) | (pk.w & 0xFFFF0000u));
                uint4 pv = vs4[i];
                *(uint2*)(sVh + off) = make_uint2((pv.x & 0xFFFF) | (pv.y << 16),
                                                  (pv.z & 0xFFFF) | (pv.w << 16));
                *(uint2*)(sVl + off) = make_uint2((pv.x >> 16) | (pv.y & 0xFFFF0000u),
                                                  (pv.z >> 16) | (pv.w & 0xFFFF0000u));
            }
            if (tid < 32)
                sb_sm[tid] = maskp[b * S_ + s0 + tid] ? 0.0f : -10000.0f;
        }
        __syncthreads();

        float sc[2][4][4];
        #pragma unroll
        for (int mi = 0; mi < 2; mi++)
            #pragma unroll
            for (int j = 0; j < 4; j++)
                #pragma unroll
                for (int q = 0; q < 4; q++) sc[mi][j][q] = 0.0f;

        #pragma unroll
        for (int n16 = 0; n16 < 2; n16++) {
            #pragma unroll
            for (int ks = 0; ks < 4; ks++) {
                uint32_t bh4[4], bl4[4];
                ldsm4(bh4, kh_base + koff[n16][ks]);
                ldsm4(bl4, kl_base + koff[n16][ks]);
                #pragma unroll
                for (int mi = 0; mi < 2; mi++) {
                    mma16816(sc[mi][2*n16],   qh[mi][ks], bh4[0], bh4[1]);
                    mma16816(sc[mi][2*n16],   ql[mi][ks], bh4[0], bh4[1]);
                    mma16816(sc[mi][2*n16],   qh[mi][ks], bl4[0], bl4[1]);
                    mma16816(sc[mi][2*n16+1], qh[mi][ks], bh4[2], bh4[3]);
                    mma16816(sc[mi][2*n16+1], ql[mi][ks], bh4[2], bh4[3]);
                    mma16816(sc[mi][2*n16+1], qh[mi][ks], bl4[2], bl4[3]);
                }
            }
        }

        #pragma unroll
        for (int mi = 0; mi < 2; mi++) {
            float r0f = (float)(p0 + mi * 16 + (lane >> 2));
            float r1f = r0f + 8.0f;
            float mx0 = -1e30f, mx1 = -1e30f;
            #pragma unroll
            for (int n8 = 0; n8 < 4; n8++) {
                int cl = n8 * 8 + (lane & 3) * 2;
                float colf = (float)(s0 + cl);
                float sb0 = sb_sm[cl], sb1 = sb_sm[cl + 1];
                sc[mi][n8][0] = sc[mi][n8][0] * 0.125f + sb0 - slope * fabsf(colf - r0f);
                sc[mi][n8][1] = sc[mi][n8][1] * 0.125f + sb1 - slope * fabsf(colf + 1.0f - r0f);
                sc[mi][n8][2] = sc[mi][n8][2] * 0.125f + sb0 - slope * fabsf(colf - r1f);
                sc[mi][n8][3] = sc[mi][n8][3] * 0.125f + sb1 - slope * fabsf(colf + 1.0f - r1f);
                mx0 = fmaxf(mx0, fmaxf(sc[mi][n8][0], sc[mi][n8][1]));
                mx1 = fmaxf(mx1, fmaxf(sc[mi][n8][2], sc[mi][n8][3]));
            }
            mx0 = fmaxf(mx0, __shfl_xor_sync(0xffffffffu, mx0, 1));
            mx0 = fmaxf(mx0, __shfl_xor_sync(0xffffffffu, mx0, 2));
            mx1 = fmaxf(mx1, __shfl_xor_sync(0xffffffffu, mx1, 1));
            mx1 = fmaxf(mx1, __shfl_xor_sync(0xffffffffu, mx1, 2));
            float mn0 = fmaxf(mrun[mi][0], mx0);
            float mn1 = fmaxf(mrun[mi][1], mx1);
            float cr0 = __expf(mrun[mi][0] - mn0);
            float cr1 = __expf(mrun[mi][1] - mn1);
            mrun[mi][0] = mn0; mrun[mi][1] = mn1;
            float rs0 = 0.0f, rs1 = 0.0f;
            #pragma unroll
            for (int n8 = 0; n8 < 4; n8++) {
                sc[mi][n8][0] = __expf(sc[mi][n8][0] - mn0);
                sc[mi][n8][1] = __expf(sc[mi][n8][1] - mn0);
                sc[mi][n8][2] = __expf(sc[mi][n8][2] - mn1);
                sc[mi][n8][3] = __expf(sc[mi][n8][3] - mn1);
                rs0 += sc[mi][n8][0] + sc[mi][n8][1];
                rs1 += sc[mi][n8][2] + sc[mi][n8][3];
            }
            rs0 += __shfl_xor_sync(0xffffffffu, rs0, 1);
            rs0 += __shfl_xor_sync(0xffffffffu, rs0, 2);
            rs1 += __shfl_xor_sync(0xffffffffu, rs1, 1);
            rs1 += __shfl_xor_sync(0xffffffffu, rs1, 2);
            lsum[mi][0] = lsum[mi][0] * cr0 + rs0;
            lsum[mi][1] = lsum[mi][1] * cr1 + rs1;
            #pragma unroll
            for (int d8 = 0; d8 < 8; d8++) {
                o[mi][d8][0] *= cr0; o[mi][d8][1] *= cr0;
                o[mi][d8][2] *= cr1; o[mi][d8][3] *= cr1;
            }
        }

        #pragma unroll
        for (int ksP = 0; ksP < 2; ksP++) {
            uint32_t ph[2][4], pl[2][4];
            #pragma unroll
            for (int mi = 0; mi < 2; mi++) {
                float e0 = sc[mi][2*ksP][0], e1 = sc[mi][2*ksP][1];
                float e2 = sc[mi][2*ksP][2], e3 = sc[mi][2*ksP][3];
                float f0 = sc[mi][2*ksP+1][0], f1 = sc[mi][2*ksP+1][1];
                float f2 = sc[mi][2*ksP+1][2], f3 = sc[mi][2*ksP+1][3];
                ph[mi][0] = cvt_bf16x2(e1, e0);
                ph[mi][1] = cvt_bf16x2(e3, e2);
                ph[mi][2] = cvt_bf16x2(f1, f0);
                ph[mi][3] = cvt_bf16x2(f3, f2);
                #pragma unroll
                for (int j = 0; j < 4; j++) {
                    float lo = (j==0)?e0:(j==1)?e2:(j==2)?f0:f2;
                    float hi = (j==0)?e1:(j==1)?e3:(j==2)?f1:f3;
                    float h0 = __uint_as_float(ph[mi][j] << 16);
                    float h1 = __uint_as_float(ph[mi][j] & 0xFFFF0000u);
                    pl[mi][j] = cvt_bf16x2(hi - h1, lo - h0);
                }
            }
            #pragma unroll
            for (int d16 = 0; d16 < 4; d16++) {
                uint32_t vh4[4], vl4[4];
                ldsm4t(vh4, vh_base + voff[ksP][d16]);
                ldsm4t(vl4, vl_base + voff[ksP][d16]);
                #pragma unroll
                for (int mi = 0; mi < 2; mi++) {
                    mma16816(o[mi][2*d16],   ph[mi], vh4[0], vh4[1]);
                    mma16816(o[mi][2*d16],   pl[mi], vh4[0], vh4[1]);
                    mma16816(o[mi][2*d16],   ph[mi], vl4[0], vl4[1]);
                    mma16816(o[mi][2*d16+1], ph[mi], vh4[2], vh4[3]);
                    mma16816(o[mi][2*d16+1], pl[mi], vh4[2], vh4[3]);
                    mma16816(o[mi][2*d16+1], ph[mi], vl4[2], vl4[3]);
                }
            }
        }
        __syncthreads();
    }

    #pragma unroll
    for (int mi = 0; mi < 2; mi++) {
        int rp0 = p0 + mi * 16 + (lane >> 2);
        int rp1 = rp0 + 8;
        int nm0 = maskp[b * S_ + 2 * rp0] | maskp[b * S_ + 2 * rp0 + 1];
        int nm1 = maskp[b * S_ + 2 * rp1] | maskp[b * S_ + 2 * rp1 + 1];
        float s0v = nm0 ? (1.0f / lsum[mi][0]) : 0.0f;
        float s1v = nm1 ? (1.0f / lsum[mi][1]) : 0.0f;
        float* dst0 = out + (size_t)(b * P_ + rp0) * D_ + h * 64 + (lane & 3) * 2;
        float* dst1 = out + (size_t)(b * P_ + rp1) * D_ + h * 64 + (lane & 3) * 2;
        #pragma unroll
        for (int d8 = 0; d8 < 8; d8++) {
            *(float2*)(dst0 + d8 * 8) = make_float2(o[mi][d8][0] * s0v, o[mi][d8][1] * s0v);
            *(float2*)(dst1 + d8 * 8) = make_float2(o[mi][d8][2] * s1v, o[mi][d8][3] * s1v);
        }
    }
}

// ---------------- launch ----------------
extern "C" void kernel_launch(void* const* d_in, const int* in_sizes, int n_in,
                              void* d_out, int out_size)
{
    const float* hidden = (const float*)d_in[0];
    const int*   mask   = (const int*)d_in[1];
    const float* W      = (const float*)d_in[2];
    const float* Wb     = (const float*)d_in[3];
    float* out = (float*)d_out;

    float* resid = out + RQ_OFF;
    float* nmout = out + NM_OFF;

    (void)cudaFuncSetAttribute(gemm_all, cudaFuncAttributeMaxDynamicSharedMemorySize, SMEM_REQ);

    scan_a<<<B_, 512>>>(mask);
    scan_b<<<1, 1>>>();
    scatter_idx<<<B_, 512>>>(mask);
    split_ac<<<(B_*S_*192 + 255) / 256, 256>>>(hidden);
    split_pool<<<(B_*P_*192 + 255) / 256, 256>>>(hidden, mask);
    split_wT<<<dim3(N3_/32, D_/32), dim3(32, 8)>>>(W);
    gemm_all<<<768 + 12*256, 256, SMEM_REQ>>>(Wb, mask, resid);
    nm_kernel<<<(B_*P_)/256, 256>>>(mask, nmout);
    attn_mma<<<dim3(2, H_, B_), 128>>>(mask, resid, out);
}

// round 8
// speedup vs baseline: 6.1038x; 1.3113x over previous
#include <cuda_runtime.h>
#include <cuda_fp16.h>
#include <cstdint>

// Problem constants
#define B_   64
#define S_   512
#define D_   768
#define H_   12
#define DH_  64
#define P_   256
#define N3_  2304
#define KE_  1536   // stored extended K (hi 768 | lo 768), fp16

#define ATTN_SZ   (B_*P_*D_)
#define NM_OFF    (ATTN_SZ)
#define RQ_OFF    (ATTN_SZ + B_*P_)

// Scratch
__device__ __half g_k[B_*H_*S_*DH_];     // plain fp16
__device__ __half g_v[B_*H_*S_*DH_];
__device__ __half g_aextc[B_*S_*KE_];    // compacted unmasked rows, hi|lo
__device__ __half g_apool[B_*P_*KE_];    // pooled rows, hi|lo
__device__ __half g_bext[N3_*KE_];       // [2304][1536]  W^T hi|lo
// compaction bookkeeping
__device__ int g_cnt[B_];
__device__ int g_lp[B_*S_];
__device__ int g_boff[B_];
__device__ int g_mc[1];
__device__ int g_ntiles[1];
__device__ int g_gidx[B_*S_ + 128];

// ---------------- PTX helpers ----------------
__device__ __forceinline__ uint32_t smem_u32(const void* p) {
    uint32_t a;
    asm("{ .reg .u64 t; cvta.to.shared.u64 t, %1; cvt.u32.u64 %0, t; }" : "=r"(a) : "l"(p));
    return a;
}
#define SWZ128(o) ((o) ^ (((o) >> 3) & 0x70))

__device__ __forceinline__ void cp_async16(uint32_t dst, const void* src) {
    asm volatile("cp.async.cg.shared.global [%0], [%1], 16;" :: "r"(dst), "l"(src) : "memory");
}
__device__ __forceinline__ void cp_commit() {
    asm volatile("cp.async.commit_group;" ::: "memory");
}
template<int N>
__device__ __forceinline__ void cp_wait() {
    asm volatile("cp.async.wait_group %0;" :: "n"(N) : "memory");
}
__device__ __forceinline__ void ldsm4(uint32_t* r, uint32_t addr) {
    asm volatile("ldmatrix.sync.aligned.m8n8.x4.shared.b16 {%0,%1,%2,%3}, [%4];"
        : "=r"(r[0]), "=r"(r[1]), "=r"(r[2]), "=r"(r[3]) : "r"(addr));
}
__device__ __forceinline__ void ldsm4t(uint32_t* r, uint32_t addr) {
    asm volatile("ldmatrix.sync.aligned.m8n8.x4.trans.shared.b16 {%0,%1,%2,%3}, [%4];"
        : "=r"(r[0]), "=r"(r[1]), "=r"(r[2]), "=r"(r[3]) : "r"(addr));
}
__device__ __forceinline__ void mma16816(float* c, const uint32_t* a, uint32_t b0, uint32_t b1) {
    asm volatile("mma.sync.aligned.m16n8k16.row.col.f32.f16.f16.f32 "
        "{%0,%1,%2,%3}, {%4,%5,%6,%7}, {%8,%9}, {%0,%1,%2,%3};"
        : "+f"(c[0]), "+f"(c[1]), "+f"(c[2]), "+f"(c[3])
        : "r"(a[0]), "r"(a[1]), "r"(a[2]), "r"(a[3]), "r"(b0), "r"(b1));
}
__device__ __forceinline__ uint32_t cvt_f16x2(float hi, float lo) {
    uint32_t r;
    asm("cvt.rn.f16x2.f32 %0, %1, %2;" : "=r"(r) : "f"(hi), "f"(lo));
    return r;
}
__device__ __forceinline__ float2 unpack_h2(uint32_t u) {
    __half2 h = *reinterpret_cast<__half2*>(&u);
    return make_float2(__low2float(h), __high2float(h));
}
__device__ __forceinline__ void split4(float4 a, uint2& ph, uint2& pl) {
    __half h0 = __float2half_rn(a.x), h1 = __float2half_rn(a.y);
    __half h2 = __float2half_rn(a.z), h3 = __float2half_rn(a.w);
    __half l0 = __float2half_rn(a.x - __half2float(h0));
    __half l1 = __float2half_rn(a.y - __half2float(h1));
    __half l2 = __float2half_rn(a.z - __half2float(h2));
    __half l3 = __float2half_rn(a.w - __half2float(h3));
    ph.x = (uint32_t)__half_as_ushort(h0) | ((uint32_t)__half_as_ushort(h1) << 16);
    ph.y = (uint32_t)__half_as_ushort(h2) | ((uint32_t)__half_as_ushort(h3) << 16);
    pl.x = (uint32_t)__half_as_ushort(l0) | ((uint32_t)__half_as_ushort(l1) << 16);
    pl.y = (uint32_t)__half_as_ushort(l2) | ((uint32_t)__half_as_ushort(l3) << 16);
}

// ---------------- compaction prepasses ----------------
__global__ __launch_bounds__(512)
void scan_a(const int* __restrict__ mask)
{
    __shared__ int wsum[16];
    __shared__ int woff[16];
    int b = blockIdx.x, s = threadIdx.x;
    int v = mask[b * S_ + s] != 0;
    unsigned bal = __ballot_sync(0xffffffffu, v);
    int lane = s & 31, w = s >> 5;
    int wpre = __popc(bal & ((1u << lane) - 1u));
    if (lane == 31) wsum[w] = __popc(bal);
    __syncthreads();
    if (s == 0) {
        int acc = 0;
        #pragma unroll
        for (int i = 0; i < 16; i++) { woff[i] = acc; acc += wsum[i]; }
        g_cnt[b] = acc;
    }
    __syncthreads();
    if (v) g_lp[b * S_ + s] = woff[w] + wpre;
}

__global__ void scan_b()
{
    int acc = 0;
    for (int i = 0; i < B_; i++) { g_boff[i] = acc; acc += g_cnt[i]; }
    g_mc[0] = acc;
    int nt = (acc + 127) >> 7;
    g_ntiles[0] = nt;
    int pad = nt * 128;
    for (int i = acc; i < pad; i++) g_gidx[i] = 0;
}

__global__ __launch_bounds__(512)
void scatter_idx(const int* __restrict__ mask)
{
    int b = blockIdx.x, s = threadIdx.x, m = b * S_ + s;
    if (mask[m]) g_gidx[g_boff[b] + g_lp[m]] = m;
}

// ---------------- split compacted A rows ----------------
__global__ __launch_bounds__(256)
void split_ac(const float* __restrict__ A)
{
    int idx = blockIdx.x * 256 + threadIdx.x;
    int i = idx / 192;
    if (i >= g_mc[0]) return;
    int k4 = (idx - i * 192) * 4;
    int m = g_gidx[i];
    float4 a = *(const float4*)&A[(size_t)m * D_ + k4];
    uint2 ph, pl; split4(a, ph, pl);
    *(uint2*)&g_aextc[(size_t)i * KE_ + k4]      = ph;
    *(uint2*)&g_aextc[(size_t)i * KE_ + D_ + k4] = pl;
}

// ---------------- split pooled A rows (for q) ----------------
__global__ __launch_bounds__(256)
void split_pool(const float* __restrict__ A, const int* __restrict__ mask)
{
    int idx = blockIdx.x * 256 + threadIdx.x;     // 16384*192
    int p = idx / 192;
    int k4 = (idx - p * 192) * 4;
    int b = p >> 8, pl_ = p & 255;
    int m0 = b * S_ + 2 * pl_;
    float mk0 = (float)mask[m0], mk1 = (float)mask[m0 + 1];
    float inv = 1.0f / fmaxf(mk0 + mk1, 1.0f);
    float4 a0 = *(const float4*)&A[(size_t)m0 * D_ + k4];
    float4 a1 = *(const float4*)&A[(size_t)(m0 + 1) * D_ + k4];
    float4 ap = make_float4((mk0 * a0.x + mk1 * a1.x) * inv,
                            (mk0 * a0.y + mk1 * a1.y) * inv,
                            (mk0 * a0.z + mk1 * a1.z) * inv,
                            (mk0 * a0.w + mk1 * a1.w) * inv);
    uint2 ph, pl; split4(ap, ph, pl);
    *(uint2*)&g_apool[(size_t)p * KE_ + k4]      = ph;
    *(uint2*)&g_apool[(size_t)p * KE_ + D_ + k4] = pl;
}

// ---------------- Prepass W: transpose + split ----------------
__global__ __launch_bounds__(256)
void split_wT(const float* __restrict__ W)
{
    __shared__ float t[32][33];
    int n0 = blockIdx.x * 32, k0 = blockIdx.y * 32;
    int tx = threadIdx.x, ty = threadIdx.y;
    #pragma unroll
    for (int j = 0; j < 4; j++)
        t[ty + j * 8][tx] = W[(size_t)(k0 + ty + j * 8) * N3_ + n0 + tx];
    __syncthreads();
    #pragma unroll
    for (int j = 0; j < 4; j++) {
        int n = n0 + ty + j * 8;
        int k = k0 + tx;
        float v = t[tx][ty + j * 8];
        __half h = __float2half_rn(v);
        __half l = __float2half_rn(v - __half2float(h));
        g_bext[(size_t)n * KE_ + k]      = h;
        g_bext[(size_t)n * KE_ + D_ + k] = l;
    }
}

// ---------------- unified 3-stage GEMM (fp16, 2-term: Ah*Bh + Al*Bh) ----------------
#define NKC   24
#define ABYTES 16384
#define BUFB  32768
#define PITCH 132
#define SMEM_REQ (3*BUFB + 1024)

__global__ __launch_bounds__(256, 2)
void gemm_all(const float* __restrict__ Wb, const int* __restrict__ maskp,
              float* __restrict__ resid)
{
    extern __shared__ char dsm[];
    __shared__ __align__(16) float s_bias[128];
    __shared__ int s_gidx[128];

    char* smem_al = (char*)(((uintptr_t)dsm + 1023) & ~(uintptr_t)1023);
    const uint32_t sbase = smem_u32(smem_al);

    const int bid = blockIdx.x;
    const bool isq = bid < 768;
    int n0, m0;
    const char* agbase;
    if (isq) {
        n0 = (bid % 6) * 128;
        m0 = (bid / 6) * 128;
        agbase = (const char*)g_apool + (size_t)m0 * (KE_ * 2);
    } else {
        int r = bid - 768;
        int by = r / 12;
        if (by >= g_ntiles[0]) return;
        n0 = 768 + (r % 12) * 128;
        m0 = by * 128;
        agbase = (const char*)g_aextc + (size_t)m0 * (KE_ * 2);
    }
    const char* bgbase = (const char*)g_bext + (size_t)n0 * (KE_ * 2);

    const int tid = threadIdx.x;
    const int wid = tid >> 5, lane = tid & 31;
    const int wm = wid & 3, wn = wid >> 2;
    const int mc = g_mc[0];

    if (tid < 128) {
        s_bias[tid] = Wb[n0 + tid];
        if (!isq) s_gidx[tid] = g_gidx[m0 + tid];
    }

    uint32_t ld_off[4];
    int g_offv[4];
    #pragma unroll
    for (int p = 0; p < 4; p++) {
        int idx = p * 256 + tid;
        int row = idx >> 3, seg = (idx & 7) * 16;
        ld_off[p] = SWZ128(row * 128 + seg);
        g_offv[p] = row * (KE_ * 2) + seg;
    }

    auto issue = [&](int kt) {
        int a_idx = kt;                              // 0..11 = Ah, 12..23 = Al
        int b_idx = (kt >= 12) ? kt - 12 : kt;       // always Bh
        const char* ag = agbase + a_idx * 128;
        const char* bg = bgbase + b_idx * 128;
        int bsel = kt - (kt / 3) * 3;
        uint32_t base = sbase + bsel * BUFB;
        #pragma unroll
        for (int p = 0; p < 4; p++)
            cp_async16(base + ld_off[p], ag + g_offv[p]);
        #pragma unroll
        for (int p = 0; p < 4; p++)
            cp_async16(base + ABYTES + ld_off[p], bg + g_offv[p]);
        cp_commit();
    };

    float c[2][8][4];
    #pragma unroll
    for (int i = 0; i < 2; i++)
        #pragma unroll
        for (int j = 0; j < 8; j++)
            #pragma unroll
            for (int q = 0; q < 4; q++) c[i][j][q] = 0.0f;

    uint32_t a_off[2][4], b_off[4][4];
    #pragma unroll
    for (int mi = 0; mi < 2; mi++)
        #pragma unroll
        for (int ks = 0; ks < 4; ks++) {
            int r = wm * 32 + mi * 16 + (lane & 15);
            int cb = ks * 32 + (lane >> 4) * 16;
            a_off[mi][ks] = SWZ128(r * 128 + cb);
        }
    #pragma unroll
    for (int ni = 0; ni < 4; ni++)
        #pragma unroll
        for (int ks = 0; ks < 4; ks++) {
            int r = wn * 64 + ni * 16 + (lane & 7) + ((lane >> 4) << 3);
            int cb = ks * 32 + ((lane >> 3) & 1) * 16;
            b_off[ni][ks] = ABYTES + SWZ128(r * 128 + cb);
        }

    issue(0);
    issue(1);

    for (int kt = 0; kt < NKC; kt++) {
        cp_wait<1>();
        __syncthreads();

        int bsel = kt - (kt / 3) * 3;
        uint32_t bufb = sbase + bsel * BUFB;
        #pragma unroll
        for (int ks = 0; ks < 4; ks++) {
            uint32_t a0[4], a1[4];
            ldsm4(a0, bufb + a_off[0][ks]);
            ldsm4(a1, bufb + a_off[1][ks]);
            uint32_t bb[4][4];
            #pragma unroll
            for (int ni = 0; ni < 4; ni++)
                ldsm4(bb[ni], bufb + b_off[ni][ks]);
            #pragma unroll
            for (int ni = 0; ni < 4; ni++) {
                mma16816(c[0][2 * ni],     a0, bb[ni][0], bb[ni][1]);
                mma16816(c[0][2 * ni + 1], a0, bb[ni][2], bb[ni][3]);
                mma16816(c[1][2 * ni],     a1, bb[ni][0], bb[ni][1]);
                mma16816(c[1][2 * ni + 1], a1, bb[ni][2], bb[ni][3]);
            }
        }
        if (kt + 2 < NKC) issue(kt + 2);
    }
    cp_wait<0>();
    __syncthreads();

    // ---- stage C to smem ----
    float* Csm = (float*)smem_al;
    #pragma unroll
    for (int mi = 0; mi < 2; mi++)
        #pragma unroll
        for (int nj = 0; nj < 8; nj++) {
            int row = wm * 32 + mi * 16 + (lane >> 2);
            int col = wn * 64 + nj * 8 + (lane & 3) * 2;
            *(float2*)&Csm[row * PITCH + col]       = make_float2(c[mi][nj][0], c[mi][nj][1]);
            *(float2*)&Csm[(row + 8) * PITCH + col] = make_float2(c[mi][nj][2], c[mi][nj][3]);
        }
    __syncthreads();

    int row = tid >> 1, half = tid & 1;
    int cbase = half * 64;
    if (isq) {
        int p = m0 + row;
        int b = p >> 8, pl_ = p & 255;
        int mm = b * S_ + 2 * pl_;
        float cb = (maskp[mm] | maskp[mm + 1]) ? 1.0f : 0.0f;
        float* dst = resid + (size_t)p * D_ + n0 + cbase;
        #pragma unroll
        for (int i = 0; i < 16; i++) {
            float4 x = *(float4*)&Csm[row * PITCH + cbase + i * 4];
            float4 bi = *(float4*)&s_bias[cbase + i * 4];
            *(float4*)(dst + i * 4) = make_float4(x.x + bi.x * cb, x.y + bi.y * cb,
                                                  x.z + bi.z * cb, x.w + bi.w * cb);
        }
    } else if (m0 + row < mc) {
        int m = s_gidx[row];
        int b = m >> 9, s = m & (S_ - 1);
        int region = 1 + (n0 >= 2 * D_);
        int head = ((n0 - region * D_) >> 6) + half;
        __half* g = (region == 1) ? g_k : g_v;
        __half* dst = g + (((size_t)(b * H_ + head)) * S_ + s) * DH_;
        #pragma unroll
        for (int i = 0; i < 16; i++) {
            float4 x = *(float4*)&Csm[row * PITCH + cbase + i * 4];
            float4 bi = *(float4*)&s_bias[cbase + i * 4];
            uint2 o;
            o.x = cvt_f16x2(x.y + bi.y, x.x + bi.x);
            o.y = cvt_f16x2(x.w + bi.w, x.z + bi.z);
            *(uint2*)(dst + i * 4) = o;
        }
    }
}

// ---------------- new_mask ----------------
__global__ void nm_kernel(const int* __restrict__ mask, float* __restrict__ out_nm)
{
    int i = blockIdx.x * blockDim.x + threadIdx.x;
    int b = i >> 8, p = i & 255;
    int m = mask[b * S_ + 2 * p] | mask[b * S_ + 2 * p + 1];
    out_nm[i] = (float)m;
}

// ---------------- attention: FA2-style mma.sync, fp16 2-term ----------------
__global__ __launch_bounds__(128)
void attn_mma(const int* __restrict__ maskp, const float* __restrict__ resid,
              float* __restrict__ out)
{
    __shared__ __align__(16) uint8_t sK[4096];
    __shared__ __align__(16) uint8_t sV[4096];
    __shared__ float sb_sm[32];

    const int tid = threadIdx.x;
    const int lane = tid & 31, w = tid >> 5;
    const int b = blockIdx.z, h = blockIdx.y;
    const int p0 = blockIdx.x * 128 + w * 32;

    const float slope = (h < 8) ? exp2f(-(float)(h + 1)) : exp2f(-0.5f - (float)(h - 8));

    const uint32_t k_base = smem_u32(sK);
    const uint32_t v_base = smem_u32(sV);

    // Q fragments: fp16 hi + residual (captures Q to 2^-22)
    uint32_t qh[2][4][4], ql[2][4][4];
    {
        const float* qb = resid + (size_t)(b * P_) * D_ + h * 64;
        #pragma unroll
        for (int mi = 0; mi < 2; mi++)
            #pragma unroll
            for (int ks = 0; ks < 4; ks++) {
                int r0 = p0 + mi * 16 + (lane >> 2);
                int c0 = ks * 16 + (lane & 3) * 2;
                float2 v[4];
                v[0] = *(const float2*)(qb + (size_t)r0 * D_ + c0);
                v[1] = *(const float2*)(qb + (size_t)(r0 + 8) * D_ + c0);
                v[2] = *(const float2*)(qb + (size_t)r0 * D_ + c0 + 8);
                v[3] = *(const float2*)(qb + (size_t)(r0 + 8) * D_ + c0 + 8);
                #pragma unroll
                for (int j = 0; j < 4; j++) {
                    uint32_t hp = cvt_f16x2(v[j].y, v[j].x);
                    float2 hf = unpack_h2(hp);
                    qh[mi][ks][j] = hp;
                    ql[mi][ks][j] = cvt_f16x2(v[j].y - hf.y, v[j].x - hf.x);
                }
            }
    }

    uint32_t koff[2][4];
    #pragma unroll
    for (int n16 = 0; n16 < 2; n16++)
        #pragma unroll
        for (int ks = 0; ks < 4; ks++) {
            int r = n16 * 16 + (lane & 7) + ((lane >> 4) << 3);
            int cb = ks * 32 + ((lane >> 3) & 1) * 16;
            koff[n16][ks] = SWZ128(r * 128 + cb);
        }
    uint32_t voff[2][4];
    #pragma unroll
    for (int ksP = 0; ksP < 2; ksP++)
        #pragma unroll
        for (int d16 = 0; d16 < 4; d16++) {
            int r = ksP * 16 + ((lane >> 3) & 1) * 8 + (lane & 7);
            int cb = d16 * 32 + ((lane >> 4) & 1) * 16;
            voff[ksP][d16] = SWZ128(r * 128 + cb);
        }

    float o[2][8][4];
    #pragma unroll
    for (int mi = 0; mi < 2; mi++)
        #pragma unroll
        for (int j = 0; j < 8; j++)
            #pragma unroll
            for (int q = 0; q < 4; q++) o[mi][j][q] = 0.0f;
    float mrun[2][2] = {{-1e30f, -1e30f}, {-1e30f, -1e30f}};
    float lsum[2][2] = {{0.0f, 0.0f}, {0.0f, 0.0f}};

    const __half* kg = g_k + (size_t)(b * H_ + h) * S_ * DH_;
    const __half* vg = g_v + (size_t)(b * H_ + h) * S_ * DH_;

    const int ldrow = tid >> 2;        // 32 rows, 4 threads/row
    const int ldc   = (tid & 3) * 32;  // byte offset within 128B row

    for (int cc = 0; cc < 16; cc++) {
        const int s0 = cc * 32;
        {
            const uint4* ks4 = (const uint4*)((const char*)(kg + (size_t)(s0 + ldrow) * 64) + ldc);
            const uint4* vs4 = (const uint4*)((const char*)(vg + (size_t)(s0 + ldrow) * 64) + ldc);
            #pragma unroll
            for (int i = 0; i < 2; i++) {
                uint32_t off = SWZ128(ldrow * 128 + ldc + i * 16);
                *(uint4*)(sK + off) = ks4[i];
                *(uint4*)(sV + off) = vs4[i];
            }
            if (tid < 32)
                sb_sm[tid] = maskp[b * S_ + s0 + tid] ? 0.0f : -10000.0f;
        }
        __syncthreads();

        float sc[2][4][4];
        #pragma unroll
        for (int mi = 0; mi < 2; mi++)
            #pragma unroll
            for (int j = 0; j < 4; j++)
                #pragma unroll
                for (int q = 0; q < 4; q++) sc[mi][j][q] = 0.0f;

        // QK: (qh + ql) * kh
        #pragma unroll
        for (int n16 = 0; n16 < 2; n16++) {
            #pragma unroll
            for (int ks = 0; ks < 4; ks++) {
                uint32_t bh4[4];
                ldsm4(bh4, k_base + koff[n16][ks]);
                #pragma unroll
                for (int mi = 0; mi < 2; mi++) {
                    mma16816(sc[mi][2*n16],   qh[mi][ks], bh4[0], bh4[1]);
                    mma16816(sc[mi][2*n16],   ql[mi][ks], bh4[0], bh4[1]);
                    mma16816(sc[mi][2*n16+1], qh[mi][ks], bh4[2], bh4[3]);
                    mma16816(sc[mi][2*n16+1], ql[mi][ks], bh4[2], bh4[3]);
                }
            }
        }

        // bias + online softmax
        #pragma unroll
        for (int mi = 0; mi < 2; mi++) {
            float r0f = (float)(p0 + mi * 16 + (lane >> 2));
            float r1f = r0f + 8.0f;
            float mx0 = -1e30f, mx1 = -1e30f;
            #pragma unroll
            for (int n8 = 0; n8 < 4; n8++) {
                int cl = n8 * 8 + (lane & 3) * 2;
                float colf = (float)(s0 + cl);
                float sb0 = sb_sm[cl], sb1 = sb_sm[cl + 1];
                sc[mi][n8][0] = sc[mi][n8][0] * 0.125f + sb0 - slope * fabsf(colf - r0f);
                sc[mi][n8][1] = sc[mi][n8][1] * 0.125f + sb1 - slope * fabsf(colf + 1.0f - r0f);
                sc[mi][n8][2] = sc[mi][n8][2] * 0.125f + sb0 - slope * fabsf(colf - r1f);
                sc[mi][n8][3] = sc[mi][n8][3] * 0.125f + sb1 - slope * fabsf(colf + 1.0f - r1f);
                mx0 = fmaxf(mx0, fmaxf(sc[mi][n8][0], sc[mi][n8][1]));
                mx1 = fmaxf(mx1, fmaxf(sc[mi][n8][2], sc[mi][n8][3]));
            }
            mx0 = fmaxf(mx0, __shfl_xor_sync(0xffffffffu, mx0, 1));
            mx0 = fmaxf(mx0, __shfl_xor_sync(0xffffffffu, mx0, 2));
            mx1 = fmaxf(mx1, __shfl_xor_sync(0xffffffffu, mx1, 1));
            mx1 = fmaxf(mx1, __shfl_xor_sync(0xffffffffu, mx1, 2));
            float mn0 = fmaxf(mrun[mi][0], mx0);
            float mn1 = fmaxf(mrun[mi][1], mx1);
            float cr0 = __expf(mrun[mi][0] - mn0);
            float cr1 = __expf(mrun[mi][1] - mn1);
            mrun[mi][0] = mn0; mrun[mi][1] = mn1;
            float rs0 = 0.0f, rs1 = 0.0f;
            #pragma unroll
            for (int n8 = 0; n8 < 4; n8++) {
                sc[mi][n8][0] = __expf(sc[mi][n8][0] - mn0);
                sc[mi][n8][1] = __expf(sc[mi][n8][1] - mn0);
                sc[mi][n8][2] = __expf(sc[mi][n8][2] - mn1);
                sc[mi][n8][3] = __expf(sc[mi][n8][3] - mn1);
                rs0 += sc[mi][n8][0] + sc[mi][n8][1];
                rs1 += sc[mi][n8][2] + sc[mi][n8][3];
            }
            rs0 += __shfl_xor_sync(0xffffffffu, rs0, 1);
            rs0 += __shfl_xor_sync(0xffffffffu, rs0, 2);
            rs1 += __shfl_xor_sync(0xffffffffu, rs1, 1);
            rs1 += __shfl_xor_sync(0xffffffffu, rs1, 2);
            lsum[mi][0] = lsum[mi][0] * cr0 + rs0;
            lsum[mi][1] = lsum[mi][1] * cr1 + rs1;
            #pragma unroll
            for (int d8 = 0; d8 < 8; d8++) {
                o[mi][d8][0] *= cr0; o[mi][d8][1] *= cr0;
                o[mi][d8][2] *= cr1; o[mi][d8][3] *= cr1;
            }
        }

        // PV: (ph + pl) * vh
        #pragma unroll
        for (int ksP = 0; ksP < 2; ksP++) {
            uint32_t ph[2][4], pl[2][4];
            #pragma unroll
            for (int mi = 0; mi < 2; mi++) {
                float e0 = sc[mi][2*ksP][0], e1 = sc[mi][2*ksP][1];
                float e2 = sc[mi][2*ksP][2], e3 = sc[mi][2*ksP][3];
                float f0 = sc[mi][2*ksP+1][0], f1 = sc[mi][2*ksP+1][1];
                float f2 = sc[mi][2*ksP+1][2], f3 = sc[mi][2*ksP+1][3];
                ph[mi][0] = cvt_f16x2(e1, e0);
                ph[mi][1] = cvt_f16x2(e3, e2);
                ph[mi][2] = cvt_f16x2(f1, f0);
                ph[mi][3] = cvt_f16x2(f3, f2);
                float2 g0 = unpack_h2(ph[mi][0]);
                float2 g1 = unpack_h2(ph[mi][1]);
                float2 g2 = unpack_h2(ph[mi][2]);
                float2 g3 = unpack_h2(ph[mi][3]);
                pl[mi][0] = cvt_f16x2(e1 - g0.y, e0 - g0.x);
                pl[mi][1] = cvt_f16x2(e3 - g1.y, e2 - g1.x);
                pl[mi][2] = cvt_f16x2(f1 - g2.y, f0 - g2.x);
                pl[mi][3] = cvt_f16x2(f3 - g3.y, f2 - g3.x);
            }
            #pragma unroll
            for (int d16 = 0; d16 < 4; d16++) {
                uint32_t vh4[4];
                ldsm4t(vh4, v_base + voff[ksP][d16]);
                #pragma unroll
                for (int mi = 0; mi < 2; mi++) {
                    mma16816(o[mi][2*d16],   ph[mi], vh4[0], vh4[1]);
                    mma16816(o[mi][2*d16],   pl[mi], vh4[0], vh4[1]);
                    mma16816(o[mi][2*d16+1], ph[mi], vh4[2], vh4[3]);
                    mma16816(o[mi][2*d16+1], pl[mi], vh4[2], vh4[3]);
                }
            }
        }
        __syncthreads();
    }

    #pragma unroll
    for (int mi = 0; mi < 2; mi++) {
        int rp0 = p0 + mi * 16 + (lane >> 2);
        int rp1 = rp0 + 8;
        int nm0 = maskp[b * S_ + 2 * rp0] | maskp[b * S_ + 2 * rp0 + 1];
        int nm1 = maskp[b * S_ + 2 * rp1] | maskp[b * S_ + 2 * rp1 + 1];
        float s0v = nm0 ? (1.0f / lsum[mi][0]) : 0.0f;
        float s1v = nm1 ? (1.0f / lsum[mi][1]) : 0.0f;
        float* dst0 = out + (size_t)(b * P_ + rp0) * D_ + h * 64 + (lane & 3) * 2;
        float* dst1 = out + (size_t)(b * P_ + rp1) * D_ + h * 64 + (lane & 3) * 2;
        #pragma unroll
        for (int d8 = 0; d8 < 8; d8++) {
            *(float2*)(dst0 + d8 * 8) = make_float2(o[mi][d8][0] * s0v, o[mi][d8][1] * s0v);
            *(float2*)(dst1 + d8 * 8) = make_float2(o[mi][d8][2] * s1v, o[mi][d8][3] * s1v);
        }
    }
}

// ---------------- launch ----------------
extern "C" void kernel_launch(void* const* d_in, const int* in_sizes, int n_in,
                              void* d_out, int out_size)
{
    const float* hidden = (const float*)d_in[0];
    const int*   mask   = (const int*)d_in[1];
    const float* W      = (const float*)d_in[2];
    const float* Wb     = (const float*)d_in[3];
    float* out = (float*)d_out;

    float* resid = out + RQ_OFF;
    float* nmout = out + NM_OFF;

    (void)cudaFuncSetAttribute(gemm_all, cudaFuncAttributeMaxDynamicSharedMemorySize, SMEM_REQ);

    scan_a<<<B_, 512>>>(mask);
    scan_b<<<1, 1>>>();
    scatter_idx<<<B_, 512>>>(mask);
    split_ac<<<(B_*S_*192 + 255) / 256, 256>>>(hidden);
    split_pool<<<(B_*P_*192 + 255) / 256, 256>>>(hidden, mask);
    split_wT<<<dim3(N3_/32, D_/32), dim3(32, 8)>>>(W);
    gemm_all<<<768 + 12*256, 256, SMEM_REQ>>>(Wb, mask, resid);
    nm_kernel<<<(B_*P_)/256, 256>>>(mask, nmout);
    attn_mma<<<dim3(2, H_, B_), 128>>>(mask, resid, out);
}

// round 9
// speedup vs baseline: 6.9290x; 1.1352x over previous
#include <cuda_runtime.h>
#include <cuda_fp16.h>
#include <cstdint>

// Problem constants
#define B_   64
#define S_   512
#define D_   768
#define H_   12
#define DH_  64
#define P_   256
#define N3_  2304
#define KE_  1536   // stored extended K (hi 768 | lo 768), fp16

#define ATTN_SZ   (B_*P_*D_)
#define NM_OFF    (ATTN_SZ)
#define RQ_OFF    (ATTN_SZ + B_*P_)

// Scratch
__device__ __half g_k[B_*H_*S_*DH_];     // plain fp16
__device__ __half g_v[B_*H_*S_*DH_];
__device__ __half g_aextc[B_*S_*KE_];    // compacted unmasked rows, hi|lo
__device__ __half g_apool[B_*P_*KE_];    // pooled rows, hi|lo
__device__ __half g_bext[N3_*KE_];       // [2304][1536]  W^T hi|lo
// compaction bookkeeping
__device__ int g_cnt[B_];
__device__ int g_lp[B_*S_];
__device__ int g_boff[B_];
__device__ int g_mc[1];
__device__ int g_ntiles[1];
__device__ int g_gidx[B_*S_ + 128];

// ---------------- PTX helpers ----------------
__device__ __forceinline__ uint32_t smem_u32(const void* p) {
    uint32_t a;
    asm("{ .reg .u64 t; cvta.to.shared.u64 t, %1; cvt.u32.u64 %0, t; }" : "=r"(a) : "l"(p));
    return a;
}
#define SWZ128(o) ((o) ^ (((o) >> 3) & 0x70))

__device__ __forceinline__ void cp_async16(uint32_t dst, const void* src) {
    asm volatile("cp.async.cg.shared.global [%0], [%1], 16;" :: "r"(dst), "l"(src) : "memory");
}
__device__ __forceinline__ void cp_commit() {
    asm volatile("cp.async.commit_group;" ::: "memory");
}
template<int N>
__device__ __forceinline__ void cp_wait() {
    asm volatile("cp.async.wait_group %0;" :: "n"(N) : "memory");
}
__device__ __forceinline__ void ldsm4(uint32_t* r, uint32_t addr) {
    asm volatile("ldmatrix.sync.aligned.m8n8.x4.shared.b16 {%0,%1,%2,%3}, [%4];"
        : "=r"(r[0]), "=r"(r[1]), "=r"(r[2]), "=r"(r[3]) : "r"(addr));
}
__device__ __forceinline__ void ldsm4t(uint32_t* r, uint32_t addr) {
    asm volatile("ldmatrix.sync.aligned.m8n8.x4.trans.shared.b16 {%0,%1,%2,%3}, [%4];"
        : "=r"(r[0]), "=r"(r[1]), "=r"(r[2]), "=r"(r[3]) : "r"(addr));
}
__device__ __forceinline__ void mma16816(float* c, const uint32_t* a, uint32_t b0, uint32_t b1) {
    asm volatile("mma.sync.aligned.m16n8k16.row.col.f32.f16.f16.f32 "
        "{%0,%1,%2,%3}, {%4,%5,%6,%7}, {%8,%9}, {%0,%1,%2,%3};"
        : "+f"(c[0]), "+f"(c[1]), "+f"(c[2]), "+f"(c[3])
        : "r"(a[0]), "r"(a[1]), "r"(a[2]), "r"(a[3]), "r"(b0), "r"(b1));
}
__device__ __forceinline__ uint32_t cvt_f16x2(float hi, float lo) {
    uint32_t r;
    asm("cvt.rn.f16x2.f32 %0, %1, %2;" : "=r"(r) : "f"(hi), "f"(lo));
    return r;
}
__device__ __forceinline__ float2 unpack_h2(uint32_t u) {
    __half2 h = *reinterpret_cast<__half2*>(&u);
    return make_float2(__low2float(h), __high2float(h));
}
__device__ __forceinline__ void split4(float4 a, uint2& ph, uint2& pl) {
    __half h0 = __float2half_rn(a.x), h1 = __float2half_rn(a.y);
    __half h2 = __float2half_rn(a.z), h3 = __float2half_rn(a.w);
    __half l0 = __float2half_rn(a.x - __half2float(h0));
    __half l1 = __float2half_rn(a.y - __half2float(h1));
    __half l2 = __float2half_rn(a.z - __half2float(h2));
    __half l3 = __float2half_rn(a.w - __half2float(h3));
    ph.x = (uint32_t)__half_as_ushort(h0) | ((uint32_t)__half_as_ushort(h1) << 16);
    ph.y = (uint32_t)__half_as_ushort(h2) | ((uint32_t)__half_as_ushort(h3) << 16);
    pl.x = (uint32_t)__half_as_ushort(l0) | ((uint32_t)__half_as_ushort(l1) << 16);
    pl.y = (uint32_t)__half_as_ushort(l2) | ((uint32_t)__half_as_ushort(l3) << 16);
}

// ---------------- compaction prepasses ----------------
__global__ __launch_bounds__(512)
void scan_a(const int* __restrict__ mask, float* __restrict__ out_nm)
{
    __shared__ int wsum[16];
    __shared__ int woff[16];
    int b = blockIdx.x, s = threadIdx.x;
    int v = mask[b * S_ + s] != 0;
    unsigned bal = __ballot_sync(0xffffffffu, v);
    int lane = s & 31, w = s >> 5;
    int wpre = __popc(bal & ((1u << lane) - 1u));
    if (lane == 31) wsum[w] = __popc(bal);
    // fused new_mask output
    if (s < 256)
        out_nm[b * P_ + s] = (float)(mask[b * S_ + 2 * s] | mask[b * S_ + 2 * s + 1]);
    __syncthreads();
    if (s == 0) {
        int acc = 0;
        #pragma unroll
        for (int i = 0; i < 16; i++) { woff[i] = acc; acc += wsum[i]; }
        g_cnt[b] = acc;
    }
    __syncthreads();
    if (v) g_lp[b * S_ + s] = woff[w] + wpre;
}

__global__ void scan_b()
{
    int acc = 0;
    for (int i = 0; i < B_; i++) { g_boff[i] = acc; acc += g_cnt[i]; }
    g_mc[0] = acc;
    int nt = (acc + 127) >> 7;
    g_ntiles[0] = nt;
    int pad = nt * 128;
    for (int i = acc; i < pad; i++) g_gidx[i] = 0;
}

__global__ __launch_bounds__(512)
void scatter_idx(const int* __restrict__ mask)
{
    int b = blockIdx.x, s = threadIdx.x, m = b * S_ + s;
    if (mask[m]) g_gidx[g_boff[b] + g_lp[m]] = m;
}

// ---------------- fused hidden split: pooled q rows + compacted k/v rows ----------------
// one block per pooled row pair; reads hidden once.
__global__ __launch_bounds__(192)
void split_hidden(const float* __restrict__ A, const int* __restrict__ mask)
{
    int pr = blockIdx.x;                       // 0..16383
    int b = pr >> 8;
    int m0 = b * S_ + ((pr & 255) << 1);
    int k4 = threadIdx.x * 4;

    int mk0 = mask[m0], mk1 = mask[m0 + 1];
    float4 a0 = *(const float4*)&A[(size_t)m0 * D_ + k4];
    float4 a1 = *(const float4*)&A[(size_t)(m0 + 1) * D_ + k4];

    float f0 = (float)mk0, f1 = (float)mk1;
    float inv = 1.0f / fmaxf(f0 + f1, 1.0f);
    float4 ap = make_float4((f0 * a0.x + f1 * a1.x) * inv,
                            (f0 * a0.y + f1 * a1.y) * inv,
                            (f0 * a0.z + f1 * a1.z) * inv,
                            (f0 * a0.w + f1 * a1.w) * inv);
    uint2 ph, pl; split4(ap, ph, pl);
    *(uint2*)&g_apool[(size_t)pr * KE_ + k4]      = ph;
    *(uint2*)&g_apool[(size_t)pr * KE_ + D_ + k4] = pl;

    int boff = g_boff[b];
    if (mk0) {
        int ci = boff + g_lp[m0];
        uint2 h, l; split4(a0, h, l);
        *(uint2*)&g_aextc[(size_t)ci * KE_ + k4]      = h;
        *(uint2*)&g_aextc[(size_t)ci * KE_ + D_ + k4] = l;
    }
    if (mk1) {
        int ci = boff + g_lp[m0 + 1];
        uint2 h, l; split4(a1, h, l);
        *(uint2*)&g_aextc[(size_t)ci * KE_ + k4]      = h;
        *(uint2*)&g_aextc[(size_t)ci * KE_ + D_ + k4] = l;
    }
}

// ---------------- Prepass W: transpose + split ----------------
__global__ __launch_bounds__(256)
void split_wT(const float* __restrict__ W)
{
    __shared__ float t[32][33];
    int n0 = blockIdx.x * 32, k0 = blockIdx.y * 32;
    int tx = threadIdx.x, ty = threadIdx.y;
    #pragma unroll
    for (int j = 0; j < 4; j++)
        t[ty + j * 8][tx] = W[(size_t)(k0 + ty + j * 8) * N3_ + n0 + tx];
    __syncthreads();
    #pragma unroll
    for (int j = 0; j < 4; j++) {
        int n = n0 + ty + j * 8;
        int k = k0 + tx;
        float v = t[tx][ty + j * 8];
        __half h = __float2half_rn(v);
        __half l = __float2half_rn(v - __half2float(h));
        g_bext[(size_t)n * KE_ + k]      = h;
        g_bext[(size_t)n * KE_ + D_ + k] = l;
    }
}

// ---------------- unified 3-stage GEMM (fp16, 2-term: Ah*Bh + Al*Bh) ----------------
#define NKC   24
#define ABYTES 16384
#define BUFB  32768
#define PITCH 132
#define SMEM_REQ (3*BUFB + 1024)

__global__ __launch_bounds__(256, 2)
void gemm_all(const float* __restrict__ Wb, const int* __restrict__ maskp,
              float* __restrict__ resid)
{
    extern __shared__ char dsm[];
    __shared__ __align__(16) float s_bias[128];
    __shared__ int s_gidx[128];

    char* smem_al = (char*)(((uintptr_t)dsm + 1023) & ~(uintptr_t)1023);
    const uint32_t sbase = smem_u32(smem_al);

    const int bid = blockIdx.x;
    const bool isq = bid < 768;
    int n0, m0;
    const char* agbase;
    if (isq) {
        n0 = (bid % 6) * 128;
        m0 = (bid / 6) * 128;
        agbase = (const char*)g_apool + (size_t)m0 * (KE_ * 2);
    } else {
        int r = bid - 768;
        int by = r / 12;
        if (by >= g_ntiles[0]) return;
        n0 = 768 + (r % 12) * 128;
        m0 = by * 128;
        agbase = (const char*)g_aextc + (size_t)m0 * (KE_ * 2);
    }
    const char* bgbase = (const char*)g_bext + (size_t)n0 * (KE_ * 2);

    const int tid = threadIdx.x;
    const int wid = tid >> 5, lane = tid & 31;
    const int wm = wid & 3, wn = wid >> 2;
    const int mc = g_mc[0];

    if (tid < 128) {
        s_bias[tid] = Wb[n0 + tid];
        if (!isq) s_gidx[tid] = g_gidx[m0 + tid];
    }

    uint32_t ld_off[4];
    int g_offv[4];
    #pragma unroll
    for (int p = 0; p < 4; p++) {
        int idx = p * 256 + tid;
        int row = idx >> 3, seg = (idx & 7) * 16;
        ld_off[p] = SWZ128(row * 128 + seg);
        g_offv[p] = row * (KE_ * 2) + seg;
    }

    auto issue = [&](int kt) {
        int a_idx = kt;                              // 0..11 = Ah, 12..23 = Al
        int b_idx = (kt >= 12) ? kt - 12 : kt;       // always Bh
        const char* ag = agbase + a_idx * 128;
        const char* bg = bgbase + b_idx * 128;
        int bsel = kt - (kt / 3) * 3;
        uint32_t base = sbase + bsel * BUFB;
        #pragma unroll
        for (int p = 0; p < 4; p++)
            cp_async16(base + ld_off[p], ag + g_offv[p]);
        #pragma unroll
        for (int p = 0; p < 4; p++)
            cp_async16(base + ABYTES + ld_off[p], bg + g_offv[p]);
        cp_commit();
    };

    float c[2][8][4];
    #pragma unroll
    for (int i = 0; i < 2; i++)
        #pragma unroll
        for (int j = 0; j < 8; j++)
            #pragma unroll
            for (int q = 0; q < 4; q++) c[i][j][q] = 0.0f;

    uint32_t a_off[2][4], b_off[4][4];
    #pragma unroll
    for (int mi = 0; mi < 2; mi++)
        #pragma unroll
        for (int ks = 0; ks < 4; ks++) {
            int r = wm * 32 + mi * 16 + (lane & 15);
            int cb = ks * 32 + (lane >> 4) * 16;
            a_off[mi][ks] = SWZ128(r * 128 + cb);
        }
    #pragma unroll
    for (int ni = 0; ni < 4; ni++)
        #pragma unroll
        for (int ks = 0; ks < 4; ks++) {
            int r = wn * 64 + ni * 16 + (lane & 7) + ((lane >> 4) << 3);
            int cb = ks * 32 + ((lane >> 3) & 1) * 16;
            b_off[ni][ks] = ABYTES + SWZ128(r * 128 + cb);
        }

    issue(0);
    issue(1);

    for (int kt = 0; kt < NKC; kt++) {
        cp_wait<1>();
        __syncthreads();

        int bsel = kt - (kt / 3) * 3;
        uint32_t bufb = sbase + bsel * BUFB;
        #pragma unroll
        for (int ks = 0; ks < 4; ks++) {
            uint32_t a0[4], a1[4];
            ldsm4(a0, bufb + a_off[0][ks]);
            ldsm4(a1, bufb + a_off[1][ks]);
            uint32_t bb[4][4];
            #pragma unroll
            for (int ni = 0; ni < 4; ni++)
                ldsm4(bb[ni], bufb + b_off[ni][ks]);
            #pragma unroll
            for (int ni = 0; ni < 4; ni++) {
                mma16816(c[0][2 * ni],     a0, bb[ni][0], bb[ni][1]);
                mma16816(c[0][2 * ni + 1], a0, bb[ni][2], bb[ni][3]);
                mma16816(c[1][2 * ni],     a1, bb[ni][0], bb[ni][1]);
                mma16816(c[1][2 * ni + 1], a1, bb[ni][2], bb[ni][3]);
            }
        }
        if (kt + 2 < NKC) issue(kt + 2);
    }
    cp_wait<0>();
    __syncthreads();

    // ---- stage C to smem ----
    float* Csm = (float*)smem_al;
    #pragma unroll
    for (int mi = 0; mi < 2; mi++)
        #pragma unroll
        for (int nj = 0; nj < 8; nj++) {
            int row = wm * 32 + mi * 16 + (lane >> 2);
            int col = wn * 64 + nj * 8 + (lane & 3) * 2;
            *(float2*)&Csm[row * PITCH + col]       = make_float2(c[mi][nj][0], c[mi][nj][1]);
            *(float2*)&Csm[(row + 8) * PITCH + col] = make_float2(c[mi][nj][2], c[mi][nj][3]);
        }
    __syncthreads();

    int row = tid >> 1, half = tid & 1;
    int cbase = half * 64;
    if (isq) {
        int p = m0 + row;
        int b = p >> 8, pl_ = p & 255;
        int mm = b * S_ + 2 * pl_;
        float cb = (maskp[mm] | maskp[mm + 1]) ? 1.0f : 0.0f;
        float* dst = resid + (size_t)p * D_ + n0 + cbase;
        #pragma unroll
        for (int i = 0; i < 16; i++) {
            float4 x = *(float4*)&Csm[row * PITCH + cbase + i * 4];
            float4 bi = *(float4*)&s_bias[cbase + i * 4];
            *(float4*)(dst + i * 4) = make_float4(x.x + bi.x * cb, x.y + bi.y * cb,
                                                  x.z + bi.z * cb, x.w + bi.w * cb);
        }
    } else if (m0 + row < mc) {
        int m = s_gidx[row];
        int b = m >> 9, s = m & (S_ - 1);
        int region = 1 + (n0 >= 2 * D_);
        int head = ((n0 - region * D_) >> 6) + half;
        __half* g = (region == 1) ? g_k : g_v;
        __half* dst = g + (((size_t)(b * H_ + head)) * S_ + s) * DH_;
        #pragma unroll
        for (int i = 0; i < 16; i++) {
            float4 x = *(float4*)&Csm[row * PITCH + cbase + i * 4];
            float4 bi = *(float4*)&s_bias[cbase + i * 4];
            uint2 o;
            o.x = cvt_f16x2(x.y + bi.y, x.x + bi.x);
            o.y = cvt_f16x2(x.w + bi.w, x.z + bi.z);
            *(uint2*)(dst + i * 4) = o;
        }
    }
}

// ---------------- attention: FA2 mma.sync, fp16 2-term, 3-stage cp.async ----------------
__global__ __launch_bounds__(128)
void attn_mma(const int* __restrict__ maskp, const float* __restrict__ resid,
              float* __restrict__ out)
{
    __shared__ __align__(16) uint8_t sKV[3][8192];   // per stage: K 4KB | V 4KB
    __shared__ float sball[512];

    const int tid = threadIdx.x;
    const int lane = tid & 31, w = tid >> 5;
    const int b = blockIdx.z, h = blockIdx.y;
    const int p0 = blockIdx.x * 128 + w * 32;

    const float slope = (h < 8) ? exp2f(-(float)(h + 1)) : exp2f(-0.5f - (float)(h - 8));
    const uint32_t sbase = smem_u32(sKV);

    // bias table for all 512 source positions
    #pragma unroll
    for (int i = 0; i < 4; i++) {
        int idx = tid * 4 + i;
        sball[idx] = maskp[b * S_ + idx] ? 0.0f : -10000.0f;
    }

    // Q fragments: fp16 hi + residual
    uint32_t qh[2][4][4], ql[2][4][4];
    {
        const float* qb = resid + (size_t)(b * P_) * D_ + h * 64;
        #pragma unroll
        for (int mi = 0; mi < 2; mi++)
            #pragma unroll
            for (int ks = 0; ks < 4; ks++) {
                int r0 = p0 + mi * 16 + (lane >> 2);
                int c0 = ks * 16 + (lane & 3) * 2;
                float2 v[4];
                v[0] = *(const float2*)(qb + (size_t)r0 * D_ + c0);
                v[1] = *(const float2*)(qb + (size_t)(r0 + 8) * D_ + c0);
                v[2] = *(const float2*)(qb + (size_t)r0 * D_ + c0 + 8);
                v[3] = *(const float2*)(qb + (size_t)(r0 + 8) * D_ + c0 + 8);
                #pragma unroll
                for (int j = 0; j < 4; j++) {
                    uint32_t hp = cvt_f16x2(v[j].y, v[j].x);
                    float2 hf = unpack_h2(hp);
                    qh[mi][ks][j] = hp;
                    ql[mi][ks][j] = cvt_f16x2(v[j].y - hf.y, v[j].x - hf.x);
                }
            }
    }

    // lane-dependent ldmatrix base offsets (tile index adds above swizzle bits)
    uint32_t kbo[4], vbo[4];
    {
        int rk = (lane & 7) + ((lane >> 4) << 3);
        int rv = ((lane >> 3) & 1) * 8 + (lane & 7);
        #pragma unroll
        for (int ks = 0; ks < 4; ks++)
            kbo[ks] = SWZ128(rk * 128 + ks * 32 + ((lane >> 3) & 1) * 16);
        #pragma unroll
        for (int d16 = 0; d16 < 4; d16++)
            vbo[d16] = SWZ128(rv * 128 + d16 * 32 + ((lane >> 4) & 1) * 16);
    }

    float o[2][8][4];
    #pragma unroll
    for (int mi = 0; mi < 2; mi++)
        #pragma unroll
        for (int j = 0; j < 8; j++)
            #pragma unroll
            for (int q = 0; q < 4; q++) o[mi][j][q] = 0.0f;
    float mrun[2][2] = {{-1e30f, -1e30f}, {-1e30f, -1e30f}};
    float lsum[2][2] = {{0.0f, 0.0f}, {0.0f, 0.0f}};

    const __half* kg = g_k + (size_t)(b * H_ + h) * S_ * DH_;
    const __half* vg = g_v + (size_t)(b * H_ + h) * S_ * DH_;

    const int ldrow = tid >> 2;        // 32 rows, 4 threads/row
    const int ldc   = (tid & 3) * 32;  // byte offset within 128B row

    auto issueKV = [&](int cc) {
        int stage = cc - (cc / 3) * 3;
        uint32_t base = sbase + stage * 8192;
        const char* ks = (const char*)(kg + (size_t)(cc * 32 + ldrow) * 64) + ldc;
        const char* vs = (const char*)(vg + (size_t)(cc * 32 + ldrow) * 64) + ldc;
        #pragma unroll
        for (int i = 0; i < 2; i++) {
            uint32_t off = SWZ128(ldrow * 128 + ldc + i * 16);
            cp_async16(base + off, ks + i * 16);
            cp_async16(base + 4096 + off, vs + i * 16);
        }
        cp_commit();
    };

    issueKV(0);
    issueKV(1);

    for (int cc = 0; cc < 16; cc++) {
        const int s0 = cc * 32;
        cp_wait<1>();
        __syncthreads();
        int stage = cc - (cc / 3) * 3;
        const uint32_t k_base = sbase + stage * 8192;
        const uint32_t v_base = k_base + 4096;

        float sc[2][4][4];
        #pragma unroll
        for (int mi = 0; mi < 2; mi++)
            #pragma unroll
            for (int j = 0; j < 4; j++)
                #pragma unroll
                for (int q = 0; q < 4; q++) sc[mi][j][q] = 0.0f;

        // QK: (qh + ql) * kh
        #pragma unroll
        for (int n16 = 0; n16 < 2; n16++) {
            #pragma unroll
            for (int ks = 0; ks < 4; ks++) {
                uint32_t bh4[4];
                ldsm4(bh4, k_base + n16 * 2048 + kbo[ks]);
                #pragma unroll
                for (int mi = 0; mi < 2; mi++) {
                    mma16816(sc[mi][2*n16],   qh[mi][ks], bh4[0], bh4[1]);
                    mma16816(sc[mi][2*n16],   ql[mi][ks], bh4[0], bh4[1]);
                    mma16816(sc[mi][2*n16+1], qh[mi][ks], bh4[2], bh4[3]);
                    mma16816(sc[mi][2*n16+1], ql[mi][ks], bh4[2], bh4[3]);
                }
            }
        }

        // bias + online softmax
        #pragma unroll
        for (int mi = 0; mi < 2; mi++) {
            float r0f = (float)(p0 + mi * 16 + (lane >> 2));
            float r1f = r0f + 8.0f;
            float mx0 = -1e30f, mx1 = -1e30f;
            #pragma unroll
            for (int n8 = 0; n8 < 4; n8++) {
                int cl = n8 * 8 + (lane & 3) * 2;
                float colf = (float)(s0 + cl);
                float sb0 = sball[s0 + cl], sb1 = sball[s0 + cl + 1];
                sc[mi][n8][0] = sc[mi][n8][0] * 0.125f + sb0 - slope * fabsf(colf - r0f);
                sc[mi][n8][1] = sc[mi][n8][1] * 0.125f + sb1 - slope * fabsf(colf + 1.0f - r0f);
                sc[mi][n8][2] = sc[mi][n8][2] * 0.125f + sb0 - slope * fabsf(colf - r1f);
                sc[mi][n8][3] = sc[mi][n8][3] * 0.125f + sb1 - slope * fabsf(colf + 1.0f - r1f);
                mx0 = fmaxf(mx0, fmaxf(sc[mi][n8][0], sc[mi][n8][1]));
                mx1 = fmaxf(mx1, fmaxf(sc[mi][n8][2], sc[mi][n8][3]));
            }
            mx0 = fmaxf(mx0, __shfl_xor_sync(0xffffffffu, mx0, 1));
            mx0 = fmaxf(mx0, __shfl_xor_sync(0xffffffffu, mx0, 2));
            mx1 = fmaxf(mx1, __shfl_xor_sync(0xffffffffu, mx1, 1));
            mx1 = fmaxf(mx1, __shfl_xor_sync(0xffffffffu, mx1, 2));
            float mn0 = fmaxf(mrun[mi][0], mx0);
            float mn1 = fmaxf(mrun[mi][1], mx1);
            float cr0 = __expf(mrun[mi][0] - mn0);
            float cr1 = __expf(mrun[mi][1] - mn1);
            mrun[mi][0] = mn0; mrun[mi][1] = mn1;
            float rs0 = 0.0f, rs1 = 0.0f;
            #pragma unroll
            for (int n8 = 0; n8 < 4; n8++) {
                sc[mi][n8][0] = __expf(sc[mi][n8][0] - mn0);
                sc[mi][n8][1] = __expf(sc[mi][n8][1] - mn0);
                sc[mi][n8][2] = __expf(sc[mi][n8][2] - mn1);
                sc[mi][n8][3] = __expf(sc[mi][n8][3] - mn1);
                rs0 += sc[mi][n8][0] + sc[mi][n8][1];
                rs1 += sc[mi][n8][2] + sc[mi][n8][3];
            }
            rs0 += __shfl_xor_sync(0xffffffffu, rs0, 1);
            rs0 += __shfl_xor_sync(0xffffffffu, rs0, 2);
            rs1 += __shfl_xor_sync(0xffffffffu, rs1, 1);
            rs1 += __shfl_xor_sync(0xffffffffu, rs1, 2);
            lsum[mi][0] = lsum[mi][0] * cr0 + rs0;
            lsum[mi][1] = lsum[mi][1] * cr1 + rs1;
            #pragma unroll
            for (int d8 = 0; d8 < 8; d8++) {
                o[mi][d8][0] *= cr0; o[mi][d8][1] *= cr0;
                o[mi][d8][2] *= cr1; o[mi][d8][3] *= cr1;
            }
        }

        // PV: (ph + pl) * vh
        #pragma unroll
        for (int ksP = 0; ksP < 2; ksP++) {
            uint32_t ph[2][4], pl[2][4];
            #pragma unroll
            for (int mi = 0; mi < 2; mi++) {
                float e0 = sc[mi][2*ksP][0], e1 = sc[mi][2*ksP][1];
                float e2 = sc[mi][2*ksP][2], e3 = sc[mi][2*ksP][3];
                float f0 = sc[mi][2*ksP+1][0], f1 = sc[mi][2*ksP+1][1];
                float f2 = sc[mi][2*ksP+1][2], f3 = sc[mi][2*ksP+1][3];
                ph[mi][0] = cvt_f16x2(e1, e0);
                ph[mi][1] = cvt_f16x2(e3, e2);
                ph[mi][2] = cvt_f16x2(f1, f0);
                ph[mi][3] = cvt_f16x2(f3, f2);
                float2 g0 = unpack_h2(ph[mi][0]);
                float2 g1 = unpack_h2(ph[mi][1]);
                float2 g2 = unpack_h2(ph[mi][2]);
                float2 g3 = unpack_h2(ph[mi][3]);
                pl[mi][0] = cvt_f16x2(e1 - g0.y, e0 - g0.x);
                pl[mi][1] = cvt_f16x2(e3 - g1.y, e2 - g1.x);
                pl[mi][2] = cvt_f16x2(f1 - g2.y, f0 - g2.x);
                pl[mi][3] = cvt_f16x2(f3 - g3.y, f2 - g3.x);
            }
            #pragma unroll
            for (int d16 = 0; d16 < 4; d16++) {
                uint32_t vh4[4];
                ldsm4t(vh4, v_base + ksP * 2048 + vbo[d16]);
                #pragma unroll
                for (int mi = 0; mi < 2; mi++) {
                    mma16816(o[mi][2*d16],   ph[mi], vh4[0], vh4[1]);
                    mma16816(o[mi][2*d16],   pl[mi], vh4[0], vh4[1]);
                    mma16816(o[mi][2*d16+1], ph[mi], vh4[2], vh4[3]);
                    mma16816(o[mi][2*d16+1], pl[mi], vh4[2], vh4[3]);
                }
            }
        }
        if (cc + 2 < 16) issueKV(cc + 2);
    }

    #pragma unroll
    for (int mi = 0; mi < 2; mi++) {
        int rp0 = p0 + mi * 16 + (lane >> 2);
        int rp1 = rp0 + 8;
        int nm0 = maskp[b * S_ + 2 * rp0] | maskp[b * S_ + 2 * rp0 + 1];
        int nm1 = maskp[b * S_ + 2 * rp1] | maskp[b * S_ + 2 * rp1 + 1];
        float s0v = nm0 ? (1.0f / lsum[mi][0]) : 0.0f;
        float s1v = nm1 ? (1.0f / lsum[mi][1]) : 0.0f;
        float* dst0 = out + (size_t)(b * P_ + rp0) * D_ + h * 64 + (lane & 3) * 2;
        float* dst1 = out + (size_t)(b * P_ + rp1) * D_ + h * 64 + (lane & 3) * 2;
        #pragma unroll
        for (int d8 = 0; d8 < 8; d8++) {
            *(float2*)(dst0 + d8 * 8) = make_float2(o[mi][d8][0] * s0v, o[mi][d8][1] * s0v);
            *(float2*)(dst1 + d8 * 8) = make_float2(o[mi][d8][2] * s1v, o[mi][d8][3] * s1v);
        }
    }
}

// ---------------- launch ----------------
extern "C" void kernel_launch(void* const* d_in, const int* in_sizes, int n_in,
                              void* d_out, int out_size)
{
    const float* hidden = (const float*)d_in[0];
    const int*   mask   = (const int*)d_in[1];
    const float* W      = (const float*)d_in[2];
    const float* Wb     = (const float*)d_in[3];
    float* out = (float*)d_out;

    float* resid = out + RQ_OFF;
    float* nmout = out + NM_OFF;

    (void)cudaFuncSetAttribute(gemm_all, cudaFuncAttributeMaxDynamicSharedMemorySize, SMEM_REQ);

    scan_a<<<B_, 512>>>(mask, nmout);
    scan_b<<<1, 1>>>();
    scatter_idx<<<B_, 512>>>(mask);
    split_hidden<<<B_ * P_, 192>>>(hidden, mask);
    split_wT<<<dim3(N3_/32, D_/32), dim3(32, 8)>>>(W);
    gemm_all<<<768 + 12*256, 256, SMEM_REQ>>>(Wb, mask, resid);
    attn_mma<<<dim3(2, H_, B_), 128>>>(mask, resid, out);
}

// round 11
// speedup vs baseline: 7.8275x; 1.1297x over previous
#include <cuda_runtime.h>
#include <cuda_fp16.h>
#include <cstdint>

// Problem constants
#define B_   64
#define S_   512
#define D_   768
#define H_   12
#define DH_  64
#define P_   256
#define N3_  2304
#define KE_  1536   // stored extended K (hi 768 | lo 768), fp16

#define ATTN_SZ   (B_*P_*D_)
#define NM_OFF    (ATTN_SZ)
#define RQ_OFF    (ATTN_SZ + B_*P_)

// Scratch. K/V stored COMPACTED per (b,h): slot < cnt[b]; slots >= cnt stay zero.
__device__ __half g_k[B_*H_*S_*DH_];
__device__ __half g_v[B_*H_*S_*DH_];
__device__ __half g_aextc[B_*S_*KE_];    // compacted unmasked rows, hi|lo
__device__ __half g_apool[B_*P_*KE_];    // pooled rows, hi|lo
__device__ __half g_bext[N3_*KE_];       // [2304][1536]  W^T hi|lo
// compaction bookkeeping
__device__ int g_cnt[B_];
__device__ int g_lp[B_*S_];
__device__ int g_boff[B_];
__device__ int g_mc[1];
__device__ int g_ntiles[1];
__device__ int g_gidx[B_*S_ + 128];

// ---------------- PTX helpers ----------------
__device__ __forceinline__ uint32_t smem_u32(const void* p) {
    uint32_t a;
    asm("{ .reg .u64 t; cvta.to.shared.u64 t, %1; cvt.u32.u64 %0, t; }" : "=r"(a) : "l"(p));
    return a;
}
#define SWZ128(o) ((o) ^ (((o) >> 3) & 0x70))

__device__ __forceinline__ void cp_async16(uint32_t dst, const void* src) {
    asm volatile("cp.async.cg.shared.global [%0], [%1], 16;" :: "r"(dst), "l"(src) : "memory");
}
__device__ __forceinline__ void cp_commit() {
    asm volatile("cp.async.commit_group;" ::: "memory");
}
template<int N>
__device__ __forceinline__ void cp_wait() {
    asm volatile("cp.async.wait_group %0;" :: "n"(N) : "memory");
}
__device__ __forceinline__ void ldsm4(uint32_t* r, uint32_t addr) {
    asm volatile("ldmatrix.sync.aligned.m8n8.x4.shared.b16 {%0,%1,%2,%3}, [%4];"
        : "=r"(r[0]), "=r"(r[1]), "=r"(r[2]), "=r"(r[3]) : "r"(addr));
}
__device__ __forceinline__ void ldsm4t(uint32_t* r, uint32_t addr) {
    asm volatile("ldmatrix.sync.aligned.m8n8.x4.trans.shared.b16 {%0,%1,%2,%3}, [%4];"
        : "=r"(r[0]), "=r"(r[1]), "=r"(r[2]), "=r"(r[3]) : "r"(addr));
}
__device__ __forceinline__ void mma16816(float* c, const uint32_t* a, uint32_t b0, uint32_t b1) {
    asm volatile("mma.sync.aligned.m16n8k16.row.col.f32.f16.f16.f32 "
        "{%0,%1,%2,%3}, {%4,%5,%6,%7}, {%8,%9}, {%0,%1,%2,%3};"
        : "+f"(c[0]), "+f"(c[1]), "+f"(c[2]), "+f"(c[3])
        : "r"(a[0]), "r"(a[1]), "r"(a[2]), "r"(a[3]), "r"(b0), "r"(b1));
}
__device__ __forceinline__ uint32_t cvt_f16x2(float hi, float lo) {
    uint32_t r;
    asm("cvt.rn.f16x2.f32 %0, %1, %2;" : "=r"(r) : "f"(hi), "f"(lo));
    return r;
}
__device__ __forceinline__ float2 unpack_h2(uint32_t u) {
    __half2 h = *reinterpret_cast<__half2*>(&u);
    return make_float2(__low2float(h), __high2float(h));
}
__device__ __forceinline__ void split4(float4 a, uint2& ph, uint2& pl) {
    __half h0 = __float2half_rn(a.x), h1 = __float2half_rn(a.y);
    __half h2 = __float2half_rn(a.z), h3 = __float2half_rn(a.w);
    __half l0 = __float2half_rn(a.x - __half2float(h0));
    __half l1 = __float2half_rn(a.y - __half2float(h1));
    __half l2 = __float2half_rn(a.z - __half2float(h2));
    __half l3 = __float2half_rn(a.w - __half2float(h3));
    ph.x = (uint32_t)__half_as_ushort(h0) | ((uint32_t)__half_as_ushort(h1) << 16);
    ph.y = (uint32_t)__half_as_ushort(h2) | ((uint32_t)__half_as_ushort(h3) << 16);
    pl.x = (uint32_t)__half_as_ushort(l0) | ((uint32_t)__half_as_ushort(l1) << 16);
    pl.y = (uint32_t)__half_as_ushort(l2) | ((uint32_t)__half_as_ushort(l3) << 16);
}

// ---------------- compaction prepasses ----------------
__global__ __launch_bounds__(512)
void scan_a(const int* __restrict__ mask, float* __restrict__ out_nm)
{
    __shared__ int wsum[16];
    __shared__ int woff[16];
    int b = blockIdx.x, s = threadIdx.x;
    int v = mask[b * S_ + s] != 0;
    unsigned bal = __ballot_sync(0xffffffffu, v);
    int lane = s & 31, w = s >> 5;
    int wpre = __popc(bal & ((1u << lane) - 1u));
    if (lane == 31) wsum[w] = __popc(bal);
    if (s < 256)
        out_nm[b * P_ + s] = (float)(mask[b * S_ + 2 * s] | mask[b * S_ + 2 * s + 1]);
    __syncthreads();
    if (s == 0) {
        int acc = 0;
        #pragma unroll
        for (int i = 0; i < 16; i++) { woff[i] = acc; acc += wsum[i]; }
        g_cnt[b] = acc;
    }
    __syncthreads();
    if (v) g_lp[b * S_ + s] = woff[w] + wpre;
}

__global__ void scan_b()
{
    int acc = 0;
    for (int i = 0; i < B_; i++) { g_boff[i] = acc; acc += g_cnt[i]; }
    g_mc[0] = acc;
    int nt = (acc + 127) >> 7;
    g_ntiles[0] = nt;
    int pad = nt * 128;
    for (int i = acc; i < pad; i++) g_gidx[i] = 0;
}

__global__ __launch_bounds__(512)
void scatter_idx(const int* __restrict__ mask)
{
    int b = blockIdx.x, s = threadIdx.x, m = b * S_ + s;
    if (mask[m]) g_gidx[g_boff[b] + g_lp[m]] = m;
}

// ---------------- fused hidden split ----------------
__global__ __launch_bounds__(192)
void split_hidden(const float* __restrict__ A, const int* __restrict__ mask)
{
    int pr = blockIdx.x;                       // 0..16383
    int b = pr >> 8;
    int m0 = b * S_ + ((pr & 255) << 1);
    int k4 = threadIdx.x * 4;

    int mk0 = mask[m0], mk1 = mask[m0 + 1];
    float4 a0 = *(const float4*)&A[(size_t)m0 * D_ + k4];
    float4 a1 = *(const float4*)&A[(size_t)(m0 + 1) * D_ + k4];

    float f0 = (float)mk0, f1 = (float)mk1;
    float inv = 1.0f / fmaxf(f0 + f1, 1.0f);
    float4 ap = make_float4((f0 * a0.x + f1 * a1.x) * inv,
                            (f0 * a0.y + f1 * a1.y) * inv,
                            (f0 * a0.z + f1 * a1.z) * inv,
                            (f0 * a0.w + f1 * a1.w) * inv);
    uint2 ph, pl; split4(ap, ph, pl);
    *(uint2*)&g_apool[(size_t)pr * KE_ + k4]      = ph;
    *(uint2*)&g_apool[(size_t)pr * KE_ + D_ + k4] = pl;

    int boff = g_boff[b];
    if (mk0) {
        int ci = boff + g_lp[m0];
        uint2 h, l; split4(a0, h, l);
        *(uint2*)&g_aextc[(size_t)ci * KE_ + k4]      = h;
        *(uint2*)&g_aextc[(size_t)ci * KE_ + D_ + k4] = l;
    }
    if (mk1) {
        int ci = boff + g_lp[m0 + 1];
        uint2 h, l; split4(a1, h, l);
        *(uint2*)&g_aextc[(size_t)ci * KE_ + k4]      = h;
        *(uint2*)&g_aextc[(size_t)ci * KE_ + D_ + k4] = l;
    }
}

// ---------------- Prepass W: transpose + split ----------------
__global__ __launch_bounds__(256)
void split_wT(const float* __restrict__ W)
{
    __shared__ float t[32][33];
    int n0 = blockIdx.x * 32, k0 = blockIdx.y * 32;
    int tx = threadIdx.x, ty = threadIdx.y;
    #pragma unroll
    for (int j = 0; j < 4; j++)
        t[ty + j * 8][tx] = W[(size_t)(k0 + ty + j * 8) * N3_ + n0 + tx];
    __syncthreads();
    #pragma unroll
    for (int j = 0; j < 4; j++) {
        int n = n0 + ty + j * 8;
        int k = k0 + tx;
        float v = t[tx][ty + j * 8];
        __half h = __float2half_rn(v);
        __half l = __float2half_rn(v - __half2float(h));
        g_bext[(size_t)n * KE_ + k]      = h;
        g_bext[(size_t)n * KE_ + D_ + k] = l;
    }
}

// ---------------- unified 3-stage GEMM (fp16, 2-term: Ah*Bh + Al*Bh) ----------------
#define NKC   24
#define ABYTES 16384
#define BUFB  32768
#define PITCH 132
#define SMEM_REQ (3*BUFB + 1024)

__global__ __launch_bounds__(256, 2)
void gemm_all(const float* __restrict__ Wb, const int* __restrict__ maskp,
              float* __restrict__ resid)
{
    extern __shared__ char dsm[];
    __shared__ __align__(16) float s_bias[128];
    __shared__ int s_gidx[128];
    __shared__ int s_slot[128];

    char* smem_al = (char*)(((uintptr_t)dsm + 1023) & ~(uintptr_t)1023);
    const uint32_t sbase = smem_u32(smem_al);

    const int bid = blockIdx.x;
    const bool isq = bid < 768;
    int n0, m0;
    const char* agbase;
    if (isq) {
        n0 = (bid % 6) * 128;
        m0 = (bid / 6) * 128;
        agbase = (const char*)g_apool + (size_t)m0 * (KE_ * 2);
    } else {
        int r = bid - 768;
        int by = r / 12;
        if (by >= g_ntiles[0]) return;
        n0 = 768 + (r % 12) * 128;
        m0 = by * 128;
        agbase = (const char*)g_aextc + (size_t)m0 * (KE_ * 2);
    }
    const char* bgbase = (const char*)g_bext + (size_t)n0 * (KE_ * 2);

    const int tid = threadIdx.x;
    const int wid = tid >> 5, lane = tid & 31;
    const int wm = wid & 3, wn = wid >> 2;
    const int mc = g_mc[0];

    if (tid < 128) {
        s_bias[tid] = Wb[n0 + tid];
        if (!isq) {
            int m = g_gidx[m0 + tid];
            s_gidx[tid] = m;
            s_slot[tid] = g_lp[m];
        }
    }

    uint32_t ld_off[4];
    int g_offv[4];
    #pragma unroll
    for (int p = 0; p < 4; p++) {
        int idx = p * 256 + tid;
        int row = idx >> 3, seg = (idx & 7) * 16;
        ld_off[p] = SWZ128(row * 128 + seg);
        g_offv[p] = row * (KE_ * 2) + seg;
    }

    auto issue = [&](int kt) {
        int a_idx = kt;                              // 0..11 = Ah, 12..23 = Al
        int b_idx = (kt >= 12) ? kt - 12 : kt;       // always Bh
        const char* ag = agbase + a_idx * 128;
        const char* bg = bgbase + b_idx * 128;
        int bsel = kt - (kt / 3) * 3;
        uint32_t base = sbase + bsel * BUFB;
        #pragma unroll
        for (int p = 0; p < 4; p++)
            cp_async16(base + ld_off[p], ag + g_offv[p]);
        #pragma unroll
        for (int p = 0; p < 4; p++)
            cp_async16(base + ABYTES + ld_off[p], bg + g_offv[p]);
        cp_commit();
    };

    float c[2][8][4];
    #pragma unroll
    for (int i = 0; i < 2; i++)
        #pragma unroll
        for (int j = 0; j < 8; j++)
            #pragma unroll
            for (int q = 0; q < 4; q++) c[i][j][q] = 0.0f;

    uint32_t a_off[2][4], b_off[4][4];
    #pragma unroll
    for (int mi = 0; mi < 2; mi++)
        #pragma unroll
        for (int ks = 0; ks < 4; ks++) {
            int r = wm * 32 + mi * 16 + (lane & 15);
            int cb = ks * 32 + (lane >> 4) * 16;
            a_off[mi][ks] = SWZ128(r * 128 + cb);
        }
    #pragma unroll
    for (int ni = 0; ni < 4; ni++)
        #pragma unroll
        for (int ks = 0; ks < 4; ks++) {
            int r = wn * 64 + ni * 16 + (lane & 7) + ((lane >> 4) << 3);
            int cb = ks * 32 + ((lane >> 3) & 1) * 16;
            b_off[ni][ks] = ABYTES + SWZ128(r * 128 + cb);
        }

    issue(0);
    issue(1);

    for (int kt = 0; kt < NKC; kt++) {
        if (kt + 2 < NKC) { cp_wait<1>(); } else { cp_wait<0>(); }
        __syncthreads();

        int bsel = kt - (kt / 3) * 3;
        uint32_t bufb = sbase + bsel * BUFB;
        #pragma unroll
        for (int ks = 0; ks < 4; ks++) {
            uint32_t a0[4], a1[4];
            ldsm4(a0, bufb + a_off[0][ks]);
            ldsm4(a1, bufb + a_off[1][ks]);
            uint32_t bb[4][4];
            #pragma unroll
            for (int ni = 0; ni < 4; ni++)
                ldsm4(bb[ni], bufb + b_off[ni][ks]);
            #pragma unroll
            for (int ni = 0; ni < 4; ni++) {
                mma16816(c[0][2 * ni],     a0, bb[ni][0], bb[ni][1]);
                mma16816(c[0][2 * ni + 1], a0, bb[ni][2], bb[ni][3]);
                mma16816(c[1][2 * ni],     a1, bb[ni][0], bb[ni][1]);
                mma16816(c[1][2 * ni + 1], a1, bb[ni][2], bb[ni][3]);
            }
        }
        if (kt + 2 < NKC) issue(kt + 2);
    }
    __syncthreads();

    // ---- stage C to smem ----
    float* Csm = (float*)smem_al;
    #pragma unroll
    for (int mi = 0; mi < 2; mi++)
        #pragma unroll
        for (int nj = 0; nj < 8; nj++) {
            int row = wm * 32 + mi * 16 + (lane >> 2);
            int col = wn * 64 + nj * 8 + (lane & 3) * 2;
            *(float2*)&Csm[row * PITCH + col]       = make_float2(c[mi][nj][0], c[mi][nj][1]);
            *(float2*)&Csm[(row + 8) * PITCH + col] = make_float2(c[mi][nj][2], c[mi][nj][3]);
        }
    __syncthreads();

    int row = tid >> 1, half = tid & 1;
    int cbase = half * 64;
    if (isq) {
        int p = m0 + row;
        int b = p >> 8, pl_ = p & 255;
        int mm = b * S_ + 2 * pl_;
        float cb = (maskp[mm] | maskp[mm + 1]) ? 1.0f : 0.0f;
        float* dst = resid + (size_t)p * D_ + n0 + cbase;
        #pragma unroll
        for (int i = 0; i < 16; i++) {
            float4 x = *(float4*)&Csm[row * PITCH + cbase + i * 4];
            float4 bi = *(float4*)&s_bias[cbase + i * 4];
            *(float4*)(dst + i * 4) = make_float4(x.x + bi.x * cb, x.y + bi.y * cb,
                                                  x.z + bi.z * cb, x.w + bi.w * cb);
        }
    } else if (m0 + row < mc) {
        int m = s_gidx[row];
        int b = m >> 9;
        int slot = s_slot[row];
        int region = 1 + (n0 >= 2 * D_);
        int head = ((n0 - region * D_) >> 6) + half;
        __half* g = (region == 1) ? g_k : g_v;
        __half* dst = g + (((size_t)(b * H_ + head)) * S_ + slot) * DH_;
        #pragma unroll
        for (int i = 0; i < 16; i++) {
            float4 x = *(float4*)&Csm[row * PITCH + cbase + i * 4];
            float4 bi = *(float4*)&s_bias[cbase + i * 4];
            uint2 o;
            o.x = cvt_f16x2(x.y + bi.y, x.x + bi.x);
            o.y = cvt_f16x2(x.w + bi.w, x.z + bi.z);
            *(uint2*)(dst + i * 4) = o;
        }
    }
}

// ---------------- attention: FA2 mma.sync over COMPACTED K/V ----------------
__global__ __launch_bounds__(128)
void attn_mma(const int* __restrict__ maskp, const float* __restrict__ resid,
              float* __restrict__ out)
{
    __shared__ __align__(16) uint8_t sKV[3][8192];   // per stage: K 4KB | V 4KB
    __shared__ float sfo[512];                       // orig s per compacted slot

    const int tid = threadIdx.x;
    const int lane = tid & 31, w = tid >> 5;
    const int b = blockIdx.z, h = blockIdx.y;
    const int p0 = blockIdx.x * 128 + w * 32;

    const float slope = (h < 8) ? exp2f(-(float)(h + 1)) : exp2f(-0.5f - (float)(h - 8));
    const uint32_t sbase = smem_u32(sKV);

    const int cnt = g_cnt[b];
    const int boff = g_boff[b];
    const int nch = (cnt + 31) >> 5;

    // orig-index table (sentinel pushes padded slots to exp->0)
    #pragma unroll
    for (int i = 0; i < 4; i++) {
        int idx = tid * 4 + i;
        sfo[idx] = (idx < cnt) ? (float)(g_gidx[boff + idx] - b * S_) : 1.0e6f;
    }

    uint32_t qh[2][4][4], ql[2][4][4];
    {
        const float* qb = resid + (size_t)(b * P_) * D_ + h * 64;
        #pragma unroll
        for (int mi = 0; mi < 2; mi++)
            #pragma unroll
            for (int ks = 0; ks < 4; ks++) {
                int r0 = p0 + mi * 16 + (lane >> 2);
                int c0 = ks * 16 + (lane & 3) * 2;
                float2 v[4];
                v[0] = *(const float2*)(qb + (size_t)r0 * D_ + c0);
                v[1] = *(const float2*)(qb + (size_t)(r0 + 8) * D_ + c0);
                v[2] = *(const float2*)(qb + (size_t)r0 * D_ + c0 + 8);
                v[3] = *(const float2*)(qb + (size_t)(r0 + 8) * D_ + c0 + 8);
                #pragma unroll
                for (int j = 0; j < 4; j++) {
                    uint32_t hp = cvt_f16x2(v[j].y, v[j].x);
                    float2 hf = unpack_h2(hp);
                    qh[mi][ks][j] = hp;
                    ql[mi][ks][j] = cvt_f16x2(v[j].y - hf.y, v[j].x - hf.x);
                }
            }
    }

    uint32_t kbo[4], vbo[4];
    {
        int rk = (lane & 7) + ((lane >> 4) << 3);
        int rv = ((lane >> 3) & 1) * 8 + (lane & 7);
        #pragma unroll
        for (int ks = 0; ks < 4; ks++)
            kbo[ks] = SWZ128(rk * 128 + ks * 32 + ((lane >> 3) & 1) * 16);
        #pragma unroll
        for (int d16 = 0; d16 < 4; d16++)
            vbo[d16] = SWZ128(rv * 128 + d16 * 32 + ((lane >> 4) & 1) * 16);
    }

    float o[2][8][4];
    #pragma unroll
    for (int mi = 0; mi < 2; mi++)
        #pragma unroll
        for (int j = 0; j < 8; j++)
            #pragma unroll
            for (int q = 0; q < 4; q++) o[mi][j][q] = 0.0f;
    float mrun[2][2] = {{-1e30f, -1e30f}, {-1e30f, -1e30f}};
    float lsum[2][2] = {{0.0f, 0.0f}, {0.0f, 0.0f}};

    const __half* kg = g_k + (size_t)(b * H_ + h) * S_ * DH_;
    const __half* vg = g_v + (size_t)(b * H_ + h) * S_ * DH_;

    const int ldrow = tid >> 2;
    const int ldc   = (tid & 3) * 32;

    auto issueKV = [&](int cc) {
        int stage = cc - (cc / 3) * 3;
        uint32_t base = sbase + stage * 8192;
        const char* ks = (const char*)(kg + (size_t)(cc * 32 + ldrow) * 64) + ldc;
        const char* vs = (const char*)(vg + (size_t)(cc * 32 + ldrow) * 64) + ldc;
        #pragma unroll
        for (int i = 0; i < 2; i++) {
            uint32_t off = SWZ128(ldrow * 128 + ldc + i * 16);
            cp_async16(base + off, ks + i * 16);
            cp_async16(base + 4096 + off, vs + i * 16);
        }
        cp_commit();
    };

    issueKV(0);
    if (nch > 1) issueKV(1);

    for (int cc = 0; cc < nch; cc++) {
        const int s0 = cc * 32;
        if (cc + 2 < nch) { cp_wait<1>(); } else { cp_wait<0>(); }
        __syncthreads();
        int stage = cc - (cc / 3) * 3;
        const uint32_t k_base = sbase + stage * 8192;
        const uint32_t v_base = k_base + 4096;

        float sc[2][4][4];
        #pragma unroll
        for (int mi = 0; mi < 2; mi++)
            #pragma unroll
            for (int j = 0; j < 4; j++)
                #pragma unroll
                for (int q = 0; q < 4; q++) sc[mi][j][q] = 0.0f;

        #pragma unroll
        for (int n16 = 0; n16 < 2; n16++) {
            #pragma unroll
            for (int ks = 0; ks < 4; ks++) {
                uint32_t bh4[4];
                ldsm4(bh4, k_base + n16 * 2048 + kbo[ks]);
                #pragma unroll
                for (int mi = 0; mi < 2; mi++) {
                    mma16816(sc[mi][2*n16],   qh[mi][ks], bh4[0], bh4[1]);
                    mma16816(sc[mi][2*n16],   ql[mi][ks], bh4[0], bh4[1]);
                    mma16816(sc[mi][2*n16+1], qh[mi][ks], bh4[2], bh4[3]);
                    mma16816(sc[mi][2*n16+1], ql[mi][ks], bh4[2], bh4[3]);
                }
            }
        }

        #pragma unroll
        for (int mi = 0; mi < 2; mi++) {
            float r0f = (float)(p0 + mi * 16 + (lane >> 2));
            float r1f = r0f + 8.0f;
            float mx0 = -1e30f, mx1 = -1e30f;
            #pragma unroll
            for (int n8 = 0; n8 < 4; n8++) {
                int cl = s0 + n8 * 8 + (lane & 3) * 2;
                float c0f = sfo[cl], c1f = sfo[cl + 1];
                sc[mi][n8][0] = sc[mi][n8][0] * 0.125f - slope * fabsf(c0f - r0f);
                sc[mi][n8][1] = sc[mi][n8][1] * 0.125f - slope * fabsf(c1f - r0f);
                sc[mi][n8][2] = sc[mi][n8][2] * 0.125f - slope * fabsf(c0f - r1f);
                sc[mi][n8][3] = sc[mi][n8][3] * 0.125f - slope * fabsf(c1f - r1f);
                mx0 = fmaxf(mx0, fmaxf(sc[mi][n8][0], sc[mi][n8][1]));
                mx1 = fmaxf(mx1, fmaxf(sc[mi][n8][2], sc[mi][n8][3]));
            }
            mx0 = fmaxf(mx0, __shfl_xor_sync(0xffffffffu, mx0, 1));
            mx0 = fmaxf(mx0, __shfl_xor_sync(0xffffffffu, mx0, 2));
            mx1 = fmaxf(mx1, __shfl_xor_sync(0xffffffffu, mx1, 1));
            mx1 = fmaxf(mx1, __shfl_xor_sync(0xffffffffu, mx1, 2));
            float mn0 = fmaxf(mrun[mi][0], mx0);
            float mn1 = fmaxf(mrun[mi][1], mx1);
            float cr0 = __expf(mrun[mi][0] - mn0);
            float cr1 = __expf(mrun[mi][1] - mn1);
            mrun[mi][0] = mn0; mrun[mi][1] = mn1;
            float rs0 = 0.0f, rs1 = 0.0f;
            #pragma unroll
            for (int n8 = 0; n8 < 4; n8++) {
                sc[mi][n8][0] = __expf(sc[mi][n8][0] - mn0);
                sc[mi][n8][1] = __expf(sc[mi][n8][1] - mn0);
                sc[mi][n8][2] = __expf(sc[mi][n8][2] - mn1);
                sc[mi][n8][3] = __expf(sc[mi][n8][3] - mn1);
                rs0 += sc[mi][n8][0] + sc[mi][n8][1];
                rs1 += sc[mi][n8][2] + sc[mi][n8][3];
            }
            rs0 += __shfl_xor_sync(0xffffffffu, rs0, 1);
            rs0 += __shfl_xor_sync(0xffffffffu, rs0, 2);
            rs1 += __shfl_xor_sync(0xffffffffu, rs1, 1);
            rs1 += __shfl_xor_sync(0xffffffffu, rs1, 2);
            lsum[mi][0] = lsum[mi][0] * cr0 + rs0;
            lsum[mi][1] = lsum[mi][1] * cr1 + rs1;
            #pragma unroll
            for (int d8 = 0; d8 < 8; d8++) {
                o[mi][d8][0] *= cr0; o[mi][d8][1] *= cr0;
                o[mi][d8][2] *= cr1; o[mi][d8][3] *= cr1;
            }
        }

        #pragma unroll
        for (int ksP = 0; ksP < 2; ksP++) {
            uint32_t ph[2][4], pl[2][4];
            #pragma unroll
            for (int mi = 0; mi < 2; mi++) {
                float e0 = sc[mi][2*ksP][0], e1 = sc[mi][2*ksP][1];
                float e2 = sc[mi][2*ksP][2], e3 = sc[mi][2*ksP][3];
                float f0 = sc[mi][2*ksP+1][0], f1 = sc[mi][2*ksP+1][1];
                float f2 = sc[mi][2*ksP+1][2], f3 = sc[mi][2*ksP+1][3];
                ph[mi][0] = cvt_f16x2(e1, e0);
                ph[mi][1] = cvt_f16x2(e3, e2);
                ph[mi][2] = cvt_f16x2(f1, f0);
                ph[mi][3] = cvt_f16x2(f3, f2);
                float2 g0 = unpack_h2(ph[mi][0]);
                float2 g1 = unpack_h2(ph[mi][1]);
                float2 g2 = unpack_h2(ph[mi][2]);
                float2 g3 = unpack_h2(ph[mi][3]);
                pl[mi][0] = cvt_f16x2(e1 - g0.y, e0 - g0.x);
                pl[mi][1] = cvt_f16x2(e3 - g1.y, e2 - g1.x);
                pl[mi][2] = cvt_f16x2(f1 - g2.y, f0 - g2.x);
                pl[mi][3] = cvt_f16x2(f3 - g3.y, f2 - g3.x);
            }
            #pragma unroll
            for (int d16 = 0; d16 < 4; d16++) {
                uint32_t vh4[4];
                ldsm4t(vh4, v_base + ksP * 2048 + vbo[d16]);
                #pragma unroll
                for (int mi = 0; mi < 2; mi++) {
                    mma16816(o[mi][2*d16],   ph[mi], vh4[0], vh4[1]);
                    mma16816(o[mi][2*d16],   pl[mi], vh4[0], vh4[1]);
                    mma16816(o[mi][2*d16+1], ph[mi], vh4[2], vh4[3]);
                    mma16816(o[mi][2*d16+1], pl[mi], vh4[2], vh4[3]);
                }
            }
        }
        if (cc + 2 < nch) issueKV(cc + 2);
    }

    #pragma unroll
    for (int mi = 0; mi < 2; mi++) {
        int rp0 = p0 + mi * 16 + (lane >> 2);
        int rp1 = rp0 + 8;
        int nm0 = maskp[b * S_ + 2 * rp0] | maskp[b * S_ + 2 * rp0 + 1];
        int nm1 = maskp[b * S_ + 2 * rp1] | maskp[b * S_ + 2 * rp1 + 1];
        float s0v = nm0 ? (1.0f / lsum[mi][0]) : 0.0f;
        float s1v = nm1 ? (1.0f / lsum[mi][1]) : 0.0f;
        float* dst0 = out + (size_t)(b * P_ + rp0) * D_ + h * 64 + (lane & 3) * 2;
        float* dst1 = out + (size_t)(b * P_ + rp1) * D_ + h * 64 + (lane & 3) * 2;
        #pragma unroll
        for (int d8 = 0; d8 < 8; d8++) {
            *(float2*)(dst0 + d8 * 8) = make_float2(o[mi][d8][0] * s0v, o[mi][d8][1] * s0v);
            *(float2*)(dst1 + d8 * 8) = make_float2(o[mi][d8][2] * s1v, o[mi][d8][3] * s1v);
        }
    }
}

// ---------------- launch ----------------
extern "C" void kernel_launch(void* const* d_in, const int* in_sizes, int n_in,
                              void* d_out, int out_size)
{
    const float* hidden = (const float*)d_in[0];
    const int*   mask   = (const int*)d_in[1];
    const float* W      = (const float*)d_in[2];
    const float* Wb     = (const float*)d_in[3];
    float* out = (float*)d_out;

    float* resid = out + RQ_OFF;
    float* nmout = out + NM_OFF;

    (void)cudaFuncSetAttribute(gemm_all, cudaFuncAttributeMaxDynamicSharedMemorySize, SMEM_REQ);

    scan_a<<<B_, 512>>>(mask, nmout);
    scan_b<<<1, 1>>>();
    scatter_idx<<<B_, 512>>>(mask);
    split_hidden<<<B_ * P_, 192>>>(hidden, mask);
    split_wT<<<dim3(N3_/32, D_/32), dim3(32, 8)>>>(W);
    gemm_all<<<768 + 12*256, 256, SMEM_REQ>>>(Wb, mask, resid);
    attn_mma<<<dim3(2, H_, B_), 128>>>(mask, resid, out);
}

// round 12
// speedup vs baseline: 8.4727x; 1.0824x over previous
#include <cuda_runtime.h>
#include <cuda_fp16.h>
#include <cstdint>

// Problem constants
#define B_   64
#define S_   512
#define D_   768
#define H_   12
#define DH_  64
#define P_   256
#define N3_  2304
#define KE_  1536   // stored extended K (hi 768 | lo 768), fp16

#define ATTN_SZ   (B_*P_*D_)
#define NM_OFF    (ATTN_SZ)
#define RQ_OFF    (ATTN_SZ + B_*P_)

// Scratch. K/V stored COMPACTED per (b,h): slot < cnt[b]; slots >= cnt stay zero.
__device__ __half g_k[B_*H_*S_*DH_];
__device__ __half g_v[B_*H_*S_*DH_];
__device__ __half g_aextc[B_*S_*KE_];    // compacted unmasked rows, hi|lo
__device__ __half g_apool[B_*P_*KE_];    // pooled rows, hi|lo
__device__ __half g_bext[N3_*KE_];       // [2304][1536]  W^T hi|lo
// compaction bookkeeping
__device__ int g_cnt[B_];
__device__ int g_lp[B_*S_];
__device__ int g_boff[B_];
__device__ int g_mc[1];
__device__ int g_ntiles[1];
__device__ int g_gidx[B_*S_ + 128];

// ---------------- PTX helpers ----------------
__device__ __forceinline__ uint32_t smem_u32(const void* p) {
    uint32_t a;
    asm("{ .reg .u64 t; cvta.to.shared.u64 t, %1; cvt.u32.u64 %0, t; }" : "=r"(a) : "l"(p));
    return a;
}
#define SWZ128(o) ((o) ^ (((o) >> 3) & 0x70))

__device__ __forceinline__ void cp_async16(uint32_t dst, const void* src) {
    asm volatile("cp.async.cg.shared.global [%0], [%1], 16;" :: "r"(dst), "l"(src) : "memory");
}
__device__ __forceinline__ void cp_commit() {
    asm volatile("cp.async.commit_group;" ::: "memory");
}
template<int N>
__device__ __forceinline__ void cp_wait() {
    asm volatile("cp.async.wait_group %0;" :: "n"(N) : "memory");
}
__device__ __forceinline__ void ldsm4(uint32_t* r, uint32_t addr) {
    asm volatile("ldmatrix.sync.aligned.m8n8.x4.shared.b16 {%0,%1,%2,%3}, [%4];"
        : "=r"(r[0]), "=r"(r[1]), "=r"(r[2]), "=r"(r[3]) : "r"(addr));
}
__device__ __forceinline__ void ldsm4t(uint32_t* r, uint32_t addr) {
    asm volatile("ldmatrix.sync.aligned.m8n8.x4.trans.shared.b16 {%0,%1,%2,%3}, [%4];"
        : "=r"(r[0]), "=r"(r[1]), "=r"(r[2]), "=r"(r[3]) : "r"(addr));
}
__device__ __forceinline__ void mma16816(float* c, const uint32_t* a, uint32_t b0, uint32_t b1) {
    asm volatile("mma.sync.aligned.m16n8k16.row.col.f32.f16.f16.f32 "
        "{%0,%1,%2,%3}, {%4,%5,%6,%7}, {%8,%9}, {%0,%1,%2,%3};"
        : "+f"(c[0]), "+f"(c[1]), "+f"(c[2]), "+f"(c[3])
        : "r"(a[0]), "r"(a[1]), "r"(a[2]), "r"(a[3]), "r"(b0), "r"(b1));
}
__device__ __forceinline__ uint32_t cvt_f16x2(float hi, float lo) {
    uint32_t r;
    asm("cvt.rn.f16x2.f32 %0, %1, %2;" : "=r"(r) : "f"(hi), "f"(lo));
    return r;
}
__device__ __forceinline__ float2 unpack_h2(uint32_t u) {
    __half2 h = *reinterpret_cast<__half2*>(&u);
    return make_float2(__low2float(h), __high2float(h));
}
__device__ __forceinline__ void split4(float4 a, uint2& ph, uint2& pl) {
    __half h0 = __float2half_rn(a.x), h1 = __float2half_rn(a.y);
    __half h2 = __float2half_rn(a.z), h3 = __float2half_rn(a.w);
    __half l0 = __float2half_rn(a.x - __half2float(h0));
    __half l1 = __float2half_rn(a.y - __half2float(h1));
    __half l2 = __float2half_rn(a.z - __half2float(h2));
    __half l3 = __float2half_rn(a.w - __half2float(h3));
    ph.x = (uint32_t)__half_as_ushort(h0) | ((uint32_t)__half_as_ushort(h1) << 16);
    ph.y = (uint32_t)__half_as_ushort(h2) | ((uint32_t)__half_as_ushort(h3) << 16);
    pl.x = (uint32_t)__half_as_ushort(l0) | ((uint32_t)__half_as_ushort(l1) << 16);
    pl.y = (uint32_t)__half_as_ushort(l2) | ((uint32_t)__half_as_ushort(l3) << 16);
}

// ---------------- compaction prepasses ----------------
__global__ __launch_bounds__(512)
void scan_a(const int* __restrict__ mask, float* __restrict__ out_nm)
{
    __shared__ int wsum[16];
    __shared__ int woff[16];
    int b = blockIdx.x, s = threadIdx.x;
    int v = mask[b * S_ + s] != 0;
    unsigned bal = __ballot_sync(0xffffffffu, v);
    int lane = s & 31, w = s >> 5;
    int wpre = __popc(bal & ((1u << lane) - 1u));
    if (lane == 31) wsum[w] = __popc(bal);
    if (s < 256)
        out_nm[b * P_ + s] = (float)(mask[b * S_ + 2 * s] | mask[b * S_ + 2 * s + 1]);
    __syncthreads();
    if (s == 0) {
        int acc = 0;
        #pragma unroll
        for (int i = 0; i < 16; i++) { woff[i] = acc; acc += wsum[i]; }
        g_cnt[b] = acc;
    }
    __syncthreads();
    if (v) g_lp[b * S_ + s] = woff[w] + wpre;
}

__global__ void scan_b()
{
    int acc = 0;
    for (int i = 0; i < B_; i++) { g_boff[i] = acc; acc += g_cnt[i]; }
    g_mc[0] = acc;
    int nt = (acc + 127) >> 7;
    g_ntiles[0] = nt;
    int pad = nt * 128;
    for (int i = acc; i < pad; i++) g_gidx[i] = 0;
}

__global__ __launch_bounds__(512)
void scatter_idx(const int* __restrict__ mask)
{
    int b = blockIdx.x, s = threadIdx.x, m = b * S_ + s;
    if (mask[m]) g_gidx[g_boff[b] + g_lp[m]] = m;
}

// ---------------- fused hidden split ----------------
__global__ __launch_bounds__(192)
void split_hidden(const float* __restrict__ A, const int* __restrict__ mask)
{
    int pr = blockIdx.x;                       // 0..16383
    int b = pr >> 8;
    int m0 = b * S_ + ((pr & 255) << 1);
    int k4 = threadIdx.x * 4;

    int mk0 = mask[m0], mk1 = mask[m0 + 1];
    float4 a0 = *(const float4*)&A[(size_t)m0 * D_ + k4];
    float4 a1 = *(const float4*)&A[(size_t)(m0 + 1) * D_ + k4];

    float f0 = (float)mk0, f1 = (float)mk1;
    float inv = 1.0f / fmaxf(f0 + f1, 1.0f);
    float4 ap = make_float4((f0 * a0.x + f1 * a1.x) * inv,
                            (f0 * a0.y + f1 * a1.y) * inv,
                            (f0 * a0.z + f1 * a1.z) * inv,
                            (f0 * a0.w + f1 * a1.w) * inv);
    uint2 ph, pl; split4(ap, ph, pl);
    *(uint2*)&g_apool[(size_t)pr * KE_ + k4]      = ph;
    *(uint2*)&g_apool[(size_t)pr * KE_ + D_ + k4] = pl;

    int boff = g_boff[b];
    if (mk0) {
        int ci = boff + g_lp[m0];
        uint2 h, l; split4(a0, h, l);
        *(uint2*)&g_aextc[(size_t)ci * KE_ + k4]      = h;
        *(uint2*)&g_aextc[(size_t)ci * KE_ + D_ + k4] = l;
    }
    if (mk1) {
        int ci = boff + g_lp[m0 + 1];
        uint2 h, l; split4(a1, h, l);
        *(uint2*)&g_aextc[(size_t)ci * KE_ + k4]      = h;
        *(uint2*)&g_aextc[(size_t)ci * KE_ + D_ + k4] = l;
    }
}

// ---------------- Prepass W: transpose + split ----------------
__global__ __launch_bounds__(256)
void split_wT(const float* __restrict__ W)
{
    __shared__ float t[32][33];
    int n0 = blockIdx.x * 32, k0 = blockIdx.y * 32;
    int tx = threadIdx.x, ty = threadIdx.y;
    #pragma unroll
    for (int j = 0; j < 4; j++)
        t[ty + j * 8][tx] = W[(size_t)(k0 + ty + j * 8) * N3_ + n0 + tx];
    __syncthreads();
    #pragma unroll
    for (int j = 0; j < 4; j++) {
        int n = n0 + ty + j * 8;
        int k = k0 + tx;
        float v = t[tx][ty + j * 8];
        __half h = __float2half_rn(v);
        __half l = __float2half_rn(v - __half2float(h));
        g_bext[(size_t)n * KE_ + k]      = h;
        g_bext[(size_t)n * KE_ + D_ + k] = l;
    }
}

// ---------------- unified GEMM: 12 pair-iters, stage [Ah|Al|Bh], 64x64 warp tiles ----------------
// C = (Ah + Al) * Bh.  4 warps, 128 threads, 2-stage double buffer, 2 CTA/SM.
#define NP    12
#define TILEB 16384
#define STB   (3*TILEB)          // 48KB per stage
#define PITCH 132
#define SMEM_REQ (2*STB + 1024)

__global__ __launch_bounds__(128, 2)
void gemm_all(const float* __restrict__ Wb, const int* __restrict__ maskp,
              float* __restrict__ resid)
{
    extern __shared__ char dsm[];
    __shared__ __align__(16) float s_bias[128];
    __shared__ int s_gidx[128];
    __shared__ int s_slot[128];

    char* smem_al = (char*)(((uintptr_t)dsm + 1023) & ~(uintptr_t)1023);
    const uint32_t sbase = smem_u32(smem_al);

    const int bid = blockIdx.x;
    const bool isq = bid < 768;
    int n0, m0;
    const char* agbase;
    if (isq) {
        n0 = (bid % 6) * 128;
        m0 = (bid / 6) * 128;
        agbase = (const char*)g_apool + (size_t)m0 * (KE_ * 2);
    } else {
        int r = bid - 768;
        int by = r / 12;
        if (by >= g_ntiles[0]) return;
        n0 = 768 + (r % 12) * 128;
        m0 = by * 128;
        agbase = (const char*)g_aextc + (size_t)m0 * (KE_ * 2);
    }
    const char* bgbase = (const char*)g_bext + (size_t)n0 * (KE_ * 2);

    const int tid = threadIdx.x;
    const int wid = tid >> 5, lane = tid & 31;
    const int wm = wid & 1, wn = wid >> 1;     // warp tile 64(m) x 64(n)
    const int mc = g_mc[0];

    s_bias[tid] = Wb[n0 + tid];
    if (!isq) {
        int m = g_gidx[m0 + tid];
        s_gidx[tid] = m;
        s_slot[tid] = g_lp[m];
    }

    // cp.async coords: 8 per thread per 16KB tile
    uint32_t ld_off[8];
    int g_offv[8];
    #pragma unroll
    for (int p = 0; p < 8; p++) {
        int idx = p * 128 + tid;
        int row = idx >> 3, seg = (idx & 7) * 16;
        ld_off[p] = SWZ128(row * 128 + seg);
        g_offv[p] = row * (KE_ * 2) + seg;
    }

    auto issue = [&](int j) {                 // pair j: Ah(j), Al(j), Bh(j)
        const char* ah = agbase + j * 128;            // hi chunk j
        const char* al = agbase + 1536 + j * 128;     // lo chunk j (+768 cols * 2B)
        const char* bh = bgbase + j * 128;
        uint32_t base = sbase + (j & 1) * STB;
        #pragma unroll
        for (int p = 0; p < 8; p++)
            cp_async16(base + ld_off[p], ah + g_offv[p]);
        #pragma unroll
        for (int p = 0; p < 8; p++)
            cp_async16(base + TILEB + ld_off[p], al + g_offv[p]);
        #pragma unroll
        for (int p = 0; p < 8; p++)
            cp_async16(base + 2 * TILEB + ld_off[p], bh + g_offv[p]);
        cp_commit();
    };

    float c[4][8][4];
    #pragma unroll
    for (int i = 0; i < 4; i++)
        #pragma unroll
        for (int j = 0; j < 8; j++)
            #pragma unroll
            for (int q = 0; q < 4; q++) c[i][j][q] = 0.0f;

    uint32_t a_off[4][4], b_off[4][4];
    #pragma unroll
    for (int mi = 0; mi < 4; mi++)
        #pragma unroll
        for (int ks = 0; ks < 4; ks++) {
            int r = wm * 64 + mi * 16 + (lane & 15);
            int cb = ks * 32 + (lane >> 4) * 16;
            a_off[mi][ks] = SWZ128(r * 128 + cb);
        }
    #pragma unroll
    for (int ni = 0; ni < 4; ni++)
        #pragma unroll
        for (int ks = 0; ks < 4; ks++) {
            int r = wn * 64 + ni * 16 + (lane & 7) + ((lane >> 4) << 3);
            int cb = ks * 32 + ((lane >> 3) & 1) * 16;
            b_off[ni][ks] = 2 * TILEB + SWZ128(r * 128 + cb);
        }

    issue(0);

    for (int j = 0; j < NP; j++) {
        if (j + 1 < NP) { issue(j + 1); cp_wait<1>(); }
        else cp_wait<0>();
        __syncthreads();

        uint32_t buf = sbase + (j & 1) * STB;
        #pragma unroll
        for (int ks = 0; ks < 4; ks++) {
            uint32_t bb[4][4];
            #pragma unroll
            for (int ni = 0; ni < 4; ni++)
                ldsm4(bb[ni], buf + b_off[ni][ks]);
            uint32_t av[4][4];
            // term 1: Ah
            #pragma unroll
            for (int mi = 0; mi < 4; mi++)
                ldsm4(av[mi], buf + a_off[mi][ks]);
            #pragma unroll
            for (int ni = 0; ni < 4; ni++)
                #pragma unroll
                for (int mi = 0; mi < 4; mi++) {
                    mma16816(c[mi][2 * ni],     av[mi], bb[ni][0], bb[ni][1]);
                    mma16816(c[mi][2 * ni + 1], av[mi], bb[ni][2], bb[ni][3]);
                }
            // term 2: Al (reuse B regs)
            #pragma unroll
            for (int mi = 0; mi < 4; mi++)
                ldsm4(av[mi], buf + TILEB + a_off[mi][ks]);
            #pragma unroll
            for (int ni = 0; ni < 4; ni++)
                #pragma unroll
                for (int mi = 0; mi < 4; mi++) {
                    mma16816(c[mi][2 * ni],     av[mi], bb[ni][0], bb[ni][1]);
                    mma16816(c[mi][2 * ni + 1], av[mi], bb[ni][2], bb[ni][3]);
                }
        }
        __syncthreads();   // WAR: all warps done with buf before next issue overwrites it
    }

    // ---- stage C to smem ----
    float* Csm = (float*)smem_al;
    #pragma unroll
    for (int mi = 0; mi < 4; mi++)
        #pragma unroll
        for (int nj = 0; nj < 8; nj++) {
            int row = wm * 64 + mi * 16 + (lane >> 2);
            int col = wn * 64 + nj * 8 + (lane & 3) * 2;
            *(float2*)&Csm[row * PITCH + col]       = make_float2(c[mi][nj][0], c[mi][nj][1]);
            *(float2*)&Csm[(row + 8) * PITCH + col] = make_float2(c[mi][nj][2], c[mi][nj][3]);
        }
    __syncthreads();

    const int row = tid;
    if (isq) {
        int p = m0 + row;
        int b = p >> 8, pl_ = p & 255;
        int mm = b * S_ + 2 * pl_;
        float cb = (maskp[mm] | maskp[mm + 1]) ? 1.0f : 0.0f;
        float* dst = resid + (size_t)p * D_ + n0;
        #pragma unroll
        for (int i = 0; i < 32; i++) {
            float4 x = *(float4*)&Csm[row * PITCH + i * 4];
            float4 bi = *(float4*)&s_bias[i * 4];
            *(float4*)(dst + i * 4) = make_float4(x.x + bi.x * cb, x.y + bi.y * cb,
                                                  x.z + bi.z * cb, x.w + bi.w * cb);
        }
    } else if (m0 + row < mc) {
        int m = s_gidx[row];
        int b = m >> 9;
        int slot = s_slot[row];
        int region = 1 + (n0 >= 2 * D_);
        int head0 = (n0 - region * D_) >> 6;
        __half* g = (region == 1) ? g_k : g_v;
        #pragma unroll
        for (int half = 0; half < 2; half++) {
            int cbase = half * 64;
            __half* dst = g + (((size_t)(b * H_ + head0 + half)) * S_ + slot) * DH_;
            #pragma unroll
            for (int i = 0; i < 16; i++) {
                float4 x = *(float4*)&Csm[row * PITCH + cbase + i * 4];
                float4 bi = *(float4*)&s_bias[cbase + i * 4];
                uint2 o;
                o.x = cvt_f16x2(x.y + bi.y, x.x + bi.x);
                o.y = cvt_f16x2(x.w + bi.w, x.z + bi.z);
                *(uint2*)(dst + i * 4) = o;
            }
        }
    }
}

// ---------------- attention: FA2 mma.sync over COMPACTED K/V ----------------
__global__ __launch_bounds__(128)
void attn_mma(const int* __restrict__ maskp, const float* __restrict__ resid,
              float* __restrict__ out)
{
    __shared__ __align__(16) uint8_t sKV[3][8192];   // per stage: K 4KB | V 4KB
    __shared__ float sfo[512];                       // orig s per compacted slot

    const int tid = threadIdx.x;
    const int lane = tid & 31, w = tid >> 5;
    const int b = blockIdx.z, h = blockIdx.y;
    const int p0 = blockIdx.x * 128 + w * 32;

    const float slope = (h < 8) ? exp2f(-(float)(h + 1)) : exp2f(-0.5f - (float)(h - 8));
    const uint32_t sbase = smem_u32(sKV);

    const int cnt = g_cnt[b];
    const int boff = g_boff[b];
    const int nch = (cnt + 31) >> 5;

    #pragma unroll
    for (int i = 0; i < 4; i++) {
        int idx = tid * 4 + i;
        sfo[idx] = (idx < cnt) ? (float)(g_gidx[boff + idx] - b * S_) : 1.0e6f;
    }

    uint32_t qh[2][4][4], ql[2][4][4];
    {
        const float* qb = resid + (size_t)(b * P_) * D_ + h * 64;
        #pragma unroll
        for (int mi = 0; mi < 2; mi++)
            #pragma unroll
            for (int ks = 0; ks < 4; ks++) {
                int r0 = p0 + mi * 16 + (lane >> 2);
                int c0 = ks * 16 + (lane & 3) * 2;
                float2 v[4];
                v[0] = *(const float2*)(qb + (size_t)r0 * D_ + c0);
                v[1] = *(const float2*)(qb + (size_t)(r0 + 8) * D_ + c0);
                v[2] = *(const float2*)(qb + (size_t)r0 * D_ + c0 + 8);
                v[3] = *(const float2*)(qb + (size_t)(r0 + 8) * D_ + c0 + 8);
                #pragma unroll
                for (int j = 0; j < 4; j++) {
                    uint32_t hp = cvt_f16x2(v[j].y, v[j].x);
                    float2 hf = unpack_h2(hp);
                    qh[mi][ks][j] = hp;
                    ql[mi][ks][j] = cvt_f16x2(v[j].y - hf.y, v[j].x - hf.x);
                }
            }
    }

    uint32_t kbo[4], vbo[4];
    {
        int rk = (lane & 7) + ((lane >> 4) << 3);
        int rv = ((lane >> 3) & 1) * 8 + (lane & 7);
        #pragma unroll
        for (int ks = 0; ks < 4; ks++)
            kbo[ks] = SWZ128(rk * 128 + ks * 32 + ((lane >> 3) & 1) * 16);
        #pragma unroll
        for (int d16 = 0; d16 < 4; d16++)
            vbo[d16] = SWZ128(rv * 128 + d16 * 32 + ((lane >> 4) & 1) * 16);
    }

    float o[2][8][4];
    #pragma unroll
    for (int mi = 0; mi < 2; mi++)
        #pragma unroll
        for (int j = 0; j < 8; j++)
            #pragma unroll
            for (int q = 0; q < 4; q++) o[mi][j][q] = 0.0f;
    float mrun[2][2] = {{-1e30f, -1e30f}, {-1e30f, -1e30f}};
    float lsum[2][2] = {{0.0f, 0.0f}, {0.0f, 0.0f}};

    const __half* kg = g_k + (size_t)(b * H_ + h) * S_ * DH_;
    const __half* vg = g_v + (size_t)(b * H_ + h) * S_ * DH_;

    const int ldrow = tid >> 2;
    const int ldc   = (tid & 3) * 32;

    auto issueKV = [&](int cc) {
        int stage = cc - (cc / 3) * 3;
        uint32_t base = sbase + stage * 8192;
        const char* ks = (const char*)(kg + (size_t)(cc * 32 + ldrow) * 64) + ldc;
        const char* vs = (const char*)(vg + (size_t)(cc * 32 + ldrow) * 64) + ldc;
        #pragma unroll
        for (int i = 0; i < 2; i++) {
            uint32_t off = SWZ128(ldrow * 128 + ldc + i * 16);
            cp_async16(base + off, ks + i * 16);
            cp_async16(base + 4096 + off, vs + i * 16);
        }
        cp_commit();
    };

    issueKV(0);
    if (nch > 1) issueKV(1);

    for (int cc = 0; cc < nch; cc++) {
        const int s0 = cc * 32;
        if (cc + 2 < nch) { cp_wait<1>(); } else { cp_wait<0>(); }
        __syncthreads();
        int stage = cc - (cc / 3) * 3;
        const uint32_t k_base = sbase + stage * 8192;
        const uint32_t v_base = k_base + 4096;

        float sc[2][4][4];
        #pragma unroll
        for (int mi = 0; mi < 2; mi++)
            #pragma unroll
            for (int j = 0; j < 4; j++)
                #pragma unroll
                for (int q = 0; q < 4; q++) sc[mi][j][q] = 0.0f;

        #pragma unroll
        for (int n16 = 0; n16 < 2; n16++) {
            #pragma unroll
            for (int ks = 0; ks < 4; ks++) {
                uint32_t bh4[4];
                ldsm4(bh4, k_base + n16 * 2048 + kbo[ks]);
                #pragma unroll
                for (int mi = 0; mi < 2; mi++) {
                    mma16816(sc[mi][2*n16],   qh[mi][ks], bh4[0], bh4[1]);
                    mma16816(sc[mi][2*n16],   ql[mi][ks], bh4[0], bh4[1]);
                    mma16816(sc[mi][2*n16+1], qh[mi][ks], bh4[2], bh4[3]);
                    mma16816(sc[mi][2*n16+1], ql[mi][ks], bh4[2], bh4[3]);
                }
            }
        }

        #pragma unroll
        for (int mi = 0; mi < 2; mi++) {
            float r0f = (float)(p0 + mi * 16 + (lane >> 2));
            float r1f = r0f + 8.0f;
            float mx0 = -1e30f, mx1 = -1e30f;
            #pragma unroll
            for (int n8 = 0; n8 < 4; n8++) {
                int cl = s0 + n8 * 8 + (lane & 3) * 2;
                float c0f = sfo[cl], c1f = sfo[cl + 1];
                sc[mi][n8][0] = sc[mi][n8][0] * 0.125f - slope * fabsf(c0f - r0f);
                sc[mi][n8][1] = sc[mi][n8][1] * 0.125f - slope * fabsf(c1f - r0f);
                sc[mi][n8][2] = sc[mi][n8][2] * 0.125f - slope * fabsf(c0f - r1f);
                sc[mi][n8][3] = sc[mi][n8][3] * 0.125f - slope * fabsf(c1f - r1f);
                mx0 = fmaxf(mx0, fmaxf(sc[mi][n8][0], sc[mi][n8][1]));
                mx1 = fmaxf(mx1, fmaxf(sc[mi][n8][2], sc[mi][n8][3]));
            }
            mx0 = fmaxf(mx0, __shfl_xor_sync(0xffffffffu, mx0, 1));
            mx0 = fmaxf(mx0, __shfl_xor_sync(0xffffffffu, mx0, 2));
            mx1 = fmaxf(mx1, __shfl_xor_sync(0xffffffffu, mx1, 1));
            mx1 = fmaxf(mx1, __shfl_xor_sync(0xffffffffu, mx1, 2));
            float mn0 = fmaxf(mrun[mi][0], mx0);
            float mn1 = fmaxf(mrun[mi][1], mx1);
            float cr0 = __expf(mrun[mi][0] - mn0);
            float cr1 = __expf(mrun[mi][1] - mn1);
            mrun[mi][0] = mn0; mrun[mi][1] = mn1;
            float rs0 = 0.0f, rs1 = 0.0f;
            #pragma unroll
            for (int n8 = 0; n8 < 4; n8++) {
                sc[mi][n8][0] = __expf(sc[mi][n8][0] - mn0);
                sc[mi][n8][1] = __expf(sc[mi][n8][1] - mn0);
                sc[mi][n8][2] = __expf(sc[mi][n8][2] - mn1);
                sc[mi][n8][3] = __expf(sc[mi][n8][3] - mn1);
                rs0 += sc[mi][n8][0] + sc[mi][n8][1];
                rs1 += sc[mi][n8][2] + sc[mi][n8][3];
            }
            rs0 += __shfl_xor_sync(0xffffffffu, rs0, 1);
            rs0 += __shfl_xor_sync(0xffffffffu, rs0, 2);
            rs1 += __shfl_xor_sync(0xffffffffu, rs1, 1);
            rs1 += __shfl_xor_sync(0xffffffffu, rs1, 2);
            lsum[mi][0] = lsum[mi][0] * cr0 + rs0;
            lsum[mi][1] = lsum[mi][1] * cr1 + rs1;
            #pragma unroll
            for (int d8 = 0; d8 < 8; d8++) {
                o[mi][d8][0] *= cr0; o[mi][d8][1] *= cr0;
                o[mi][d8][2] *= cr1; o[mi][d8][3] *= cr1;
            }
        }

        #pragma unroll
        for (int ksP = 0; ksP < 2; ksP++) {
            uint32_t ph[2][4], pl[2][4];
            #pragma unroll
            for (int mi = 0; mi < 2; mi++) {
                float e0 = sc[mi][2*ksP][0], e1 = sc[mi][2*ksP][1];
                float e2 = sc[mi][2*ksP][2], e3 = sc[mi][2*ksP][3];
                float f0 = sc[mi][2*ksP+1][0], f1 = sc[mi][2*ksP+1][1];
                float f2 = sc[mi][2*ksP+1][2], f3 = sc[mi][2*ksP+1][3];
                ph[mi][0] = cvt_f16x2(e1, e0);
                ph[mi][1] = cvt_f16x2(e3, e2);
                ph[mi][2] = cvt_f16x2(f1, f0);
                ph[mi][3] = cvt_f16x2(f3, f2);
                float2 g0 = unpack_h2(ph[mi][0]);
                float2 g1 = unpack_h2(ph[mi][1]);
                float2 g2 = unpack_h2(ph[mi][2]);
                float2 g3 = unpack_h2(ph[mi][3]);
                pl[mi][0] = cvt_f16x2(e1 - g0.y, e0 - g0.x);
                pl[mi][1] = cvt_f16x2(e3 - g1.y, e2 - g1.x);
                pl[mi][2] = cvt_f16x2(f1 - g2.y, f0 - g2.x);
                pl[mi][3] = cvt_f16x2(f3 - g3.y, f2 - g3.x);
            }
            #pragma unroll
            for (int d16 = 0; d16 < 4; d16++) {
                uint32_t vh4[4];
                ldsm4t(vh4, v_base + ksP * 2048 + vbo[d16]);
                #pragma unroll
                for (int mi = 0; mi < 2; mi++) {
                    mma16816(o[mi][2*d16],   ph[mi], vh4[0], vh4[1]);
                    mma16816(o[mi][2*d16],   pl[mi], vh4[0], vh4[1]);
                    mma16816(o[mi][2*d16+1], ph[mi], vh4[2], vh4[3]);
                    mma16816(o[mi][2*d16+1], pl[mi], vh4[2], vh4[3]);
                }
            }
        }
        if (cc + 2 < nch) issueKV(cc + 2);
    }

    #pragma unroll
    for (int mi = 0; mi < 2; mi++) {
        int rp0 = p0 + mi * 16 + (lane >> 2);
        int rp1 = rp0 + 8;
        int nm0 = maskp[b * S_ + 2 * rp0] | maskp[b * S_ + 2 * rp0 + 1];
        int nm1 = maskp[b * S_ + 2 * rp1] | maskp[b * S_ + 2 * rp1 + 1];
        float s0v = nm0 ? (1.0f / lsum[mi][0]) : 0.0f;
        float s1v = nm1 ? (1.0f / lsum[mi][1]) : 0.0f;
        float* dst0 = out + (size_t)(b * P_ + rp0) * D_ + h * 64 + (lane & 3) * 2;
        float* dst1 = out + (size_t)(b * P_ + rp1) * D_ + h * 64 + (lane & 3) * 2;
        #pragma unroll
        for (int d8 = 0; d8 < 8; d8++) {
            *(float2*)(dst0 + d8 * 8) = make_float2(o[mi][d8][0] * s0v, o[mi][d8][1] * s0v);
            *(float2*)(dst1 + d8 * 8) = make_float2(o[mi][d8][2] * s1v, o[mi][d8][3] * s1v);
        }
    }
}

// ---------------- launch ----------------
extern "C" void kernel_launch(void* const* d_in, const int* in_sizes, int n_in,
                              void* d_out, int out_size)
{
    const float* hidden = (const float*)d_in[0];
    const int*   mask   = (const int*)d_in[1];
    const float* W      = (const float*)d_in[2];
    const float* Wb     = (const float*)d_in[3];
    float* out = (float*)d_out;

    float* resid = out + RQ_OFF;
    float* nmout = out + NM_OFF;

    (void)cudaFuncSetAttribute(gemm_all, cudaFuncAttributeMaxDynamicSharedMemorySize, SMEM_REQ);

    scan_a<<<B_, 512>>>(mask, nmout);
    scan_b<<<1, 1>>>();
    scatter_idx<<<B_, 512>>>(mask);
    split_hidden<<<B_ * P_, 192>>>(hidden, mask);
    split_wT<<<dim3(N3_/32, D_/32), dim3(32, 8)>>>(W);
    gemm_all<<<768 + 12*256, 128, SMEM_REQ>>>(Wb, mask, resid);
    attn_mma<<<dim3(2, H_, B_), 128>>>(mask, resid, out);
}